// round 4
// baseline (speedup 1.0000x reference)
#include <cuda_runtime.h>
#include <math.h>
#include <stdint.h>

#define B_    8
#define N_    1024
#define DIM_  768
#define H_    12
#define DH_   64
#define CTX_  992
#define BH_   96
#define ROWS_ 8192

// ---------------- scratch ----------------------------------------------------
__device__ float g_Qh  [BH_ * N_ * DH_];   // roped+scaled Q, head-major
__device__ float g_KVh [BH_ * N_ * DH_];   // roped KV, head-major
__device__ float g_LKVh[BH_ * N_ * DH_];   // LN(roped KV), head-major
__device__ float g_Attn[ROWS_ * DIM_];     // merged attention output

// ---------------- tf32 mma helpers ------------------------------------------
__device__ __forceinline__ uint32_t f2t(float x) {
    uint32_t r; asm("cvt.rna.tf32.f32 %0, %1;" : "=r"(r) : "f"(x)); return r;
}
__device__ __forceinline__ void mma8(float4& c, const uint32_t* a, const uint32_t* b) {
    asm volatile(
        "mma.sync.aligned.m16n8k8.row.col.f32.tf32.tf32.f32 "
        "{%0,%1,%2,%3}, {%4,%5,%6,%7}, {%8,%9}, {%0,%1,%2,%3};\n"
        : "+f"(c.x), "+f"(c.y), "+f"(c.z), "+f"(c.w)
        : "r"(a[0]), "r"(a[1]), "r"(a[2]), "r"(a[3]), "r"(b[0]), "r"(b[1]));
}

// ---------------- projection GEMM + fused RoPE(/LN) epilogue -----------------
// C[128,64] tile = x[128,768] @ W[768, head*64..+64]. grid (64, 12), 256 thr.
template<int IS_KV>
__global__ __launch_bounds__(256) void proj_kernel(const float* __restrict__ A,
                                                   const float* __restrict__ W,
                                                   const float* __restrict__ lng,
                                                   const float* __restrict__ lnb) {
    __shared__ union {
        struct { uint32_t As[128][33]; uint32_t Bs[32][65]; } in;
        float Csh[128][65];
    } sm;

    const int m0   = blockIdx.x * 128;
    const int head = blockIdx.y;
    const int n0   = head * 64;
    const int tid  = threadIdx.x;
    const int lane = tid & 31, wid = tid >> 5;
    const int wm   = (wid & 3) * 32;     // 4 warps along M
    const int wn   = (wid >> 2) * 32;    // 2 warps along N
    const int g    = lane >> 2, t = lane & 3;

    float4 acc[2][4];
    #pragma unroll
    for (int i = 0; i < 2; i++)
        #pragma unroll
        for (int j = 0; j < 4; j++) acc[i][j] = make_float4(0.f, 0.f, 0.f, 0.f);

    for (int k0 = 0; k0 < DIM_; k0 += 32) {
        __syncthreads();
        #pragma unroll
        for (int i = 0; i < 4; i++) {                    // A: 128x32
            int idx = tid + i * 256;
            int r = idx >> 3, c4 = (idx & 7) * 4;
            float4 v = *(const float4*)(A + (size_t)(m0 + r) * DIM_ + k0 + c4);
            sm.in.As[r][c4 + 0] = f2t(v.x);
            sm.in.As[r][c4 + 1] = f2t(v.y);
            sm.in.As[r][c4 + 2] = f2t(v.z);
            sm.in.As[r][c4 + 3] = f2t(v.w);
        }
        #pragma unroll
        for (int i = 0; i < 2; i++) {                    // B: 32x64
            int idx = tid + i * 256;
            int r = idx >> 4, c4 = (idx & 15) * 4;
            float4 v = *(const float4*)(W + (size_t)(k0 + r) * DIM_ + n0 + c4);
            sm.in.Bs[r][c4 + 0] = f2t(v.x);
            sm.in.Bs[r][c4 + 1] = f2t(v.y);
            sm.in.Bs[r][c4 + 2] = f2t(v.z);
            sm.in.Bs[r][c4 + 3] = f2t(v.w);
        }
        __syncthreads();

        #pragma unroll
        for (int kk = 0; kk < 4; kk++) {
            uint32_t a[2][4], b[4][2];
            #pragma unroll
            for (int mt = 0; mt < 2; mt++) {
                int r = wm + mt * 16;
                a[mt][0] = sm.in.As[r + g    ][kk * 8 + t];
                a[mt][1] = sm.in.As[r + g + 8][kk * 8 + t];
                a[mt][2] = sm.in.As[r + g    ][kk * 8 + t + 4];
                a[mt][3] = sm.in.As[r + g + 8][kk * 8 + t + 4];
            }
            #pragma unroll
            for (int j = 0; j < 4; j++) {
                b[j][0] = sm.in.Bs[kk * 8 + t    ][wn + j * 8 + g];
                b[j][1] = sm.in.Bs[kk * 8 + t + 4][wn + j * 8 + g];
            }
            #pragma unroll
            for (int mt = 0; mt < 2; mt++)
                #pragma unroll
                for (int j = 0; j < 4; j++) mma8(acc[mt][j], a[mt], b[j]);
        }
    }
    __syncthreads();

    // stage C tile
    #pragma unroll
    for (int mt = 0; mt < 2; mt++)
        #pragma unroll
        for (int j = 0; j < 4; j++) {
            int r = wm + mt * 16 + g, c = wn + j * 8 + 2 * t;
            sm.Csh[r    ][c] = acc[mt][j].x; sm.Csh[r    ][c + 1] = acc[mt][j].y;
            sm.Csh[r + 8][c] = acc[mt][j].z; sm.Csh[r + 8][c + 1] = acc[mt][j].w;
        }
    __syncthreads();

    // rope epilogue (pairs (d, d+32), d<32)
    #pragma unroll
    for (int i = 0; i < 16; i++) {
        int idx = tid + i * 256;                 // 0..4095
        int r = idx >> 5, d = idx & 31;
        float t1 = sm.Csh[r][d], t2 = sm.Csh[r][d + 32];
        int row = m0 + r;
        int bb = row >> 10, n = row & 1023;
        float inv = expf(-(float)d * 0.28782313662425575f);
        float fr = (float)n * inv;
        float sn, cs; sincosf(fr, &sn, &cs);
        float r1 = t1 * cs - t2 * sn;
        float r2 = t2 * cs + t1 * sn;
        size_t o = ((size_t)(bb * H_ + head) * N_ + n) * DH_;
        if (!IS_KV) {
            g_Qh[o + d]      = r1 * 0.125f;
            g_Qh[o + d + 32] = r2 * 0.125f;
        } else {
            g_KVh[o + d]      = r1;
            g_KVh[o + d + 32] = r2;
        }
    }

    if (IS_KV) {
        // write roped values back for the LN pass
        __syncthreads();
        #pragma unroll
        for (int i = 0; i < 16; i++) {
            int idx = tid + i * 256;
            int r = idx >> 5, d = idx & 31;
            int row = m0 + r;
            int bb = row >> 10, n = row & 1023;
            size_t o = ((size_t)(bb * H_ + head) * N_ + n) * DH_;
            sm.Csh[r][d]      = g_KVh[o + d];
            sm.Csh[r][d + 32] = g_KVh[o + d + 32];
        }
        __syncthreads();
        // warp per row: LN over 64 dims
        for (int rr = 0; rr < 16; rr++) {
            int r = wid * 16 + rr;
            float v1 = sm.Csh[r][lane], v2 = sm.Csh[r][lane + 32];
            float s = v1 + v2;
            #pragma unroll
            for (int off = 16; off; off >>= 1) s += __shfl_xor_sync(0xffffffffu, s, off);
            float mean = s * (1.0f / 64.0f);
            float d1 = v1 - mean, d2 = v2 - mean;
            float vv = d1 * d1 + d2 * d2;
            #pragma unroll
            for (int off = 16; off; off >>= 1) vv += __shfl_xor_sync(0xffffffffu, vv, off);
            float istd = rsqrtf(vv * (1.0f / 64.0f) + 1e-5f);
            int row = m0 + r;
            int bb = row >> 10, n = row & 1023;
            size_t o = ((size_t)(bb * H_ + head) * N_ + n) * DH_;
            g_LKVh[o + lane]      = d1 * istd * lng[lane]      + lnb[lane];
            g_LKVh[o + lane + 32] = d2 * istd * lng[lane + 32] + lnb[lane + 32];
        }
    }
}

// ---------------- fused attention (tf32 mma) ---------------------------------
// grid (96, 8), block 256 (8 warps), dynamic smem.
// layout (u32 units): QP[128][65] @0 (Q stage, then per-warp P), Ksh[64][65]
// @8320, VshT[64][65] @12480. total 16640 u32 = 66560 B.
#define QP(r, c)  dsm[(r) * 65 + (c)]
#define KS(r, c)  dsm[8320 + (r) * 65 + (c)]
#define VT(d, k)  dsm[12480 + (d) * 65 + (k)]

__global__ __launch_bounds__(256, 2) void attn_kernel() {
    extern __shared__ uint32_t dsm[];
    const int bh = blockIdx.x;
    const int qt = blockIdx.y;
    const int m0 = qt * 128;
    const int tid = threadIdx.x;
    const int lane = tid & 31, wid = tid >> 5;
    const int g = lane >> 2, t = lane & 3;
    const int wr = wid * 16;                  // warp's 16 query rows

    // stage Q (tf32)
    const float* qsrc = g_Qh + ((size_t)bh * N_ + m0) * DH_;
    #pragma unroll
    for (int i = 0; i < 8; i++) {
        int idx = tid + i * 256;              // 0..2047 float4s
        int r = idx >> 4, c4 = (idx & 15) * 4;
        float4 v = *(const float4*)(qsrc + (size_t)r * DH_ + c4);
        QP(r, c4 + 0) = f2t(v.x); QP(r, c4 + 1) = f2t(v.y);
        QP(r, c4 + 2) = f2t(v.z); QP(r, c4 + 3) = f2t(v.w);
    }
    __syncthreads();

    uint32_t qa[8][4];
    #pragma unroll
    for (int kk = 0; kk < 8; kk++) {
        qa[kk][0] = QP(wr + g,     kk * 8 + t);
        qa[kk][1] = QP(wr + g + 8, kk * 8 + t);
        qa[kk][2] = QP(wr + g,     kk * 8 + t + 4);
        qa[kk][3] = QP(wr + g + 8, kk * 8 + t + 4);
    }
    __syncthreads();          // everyone's Q frags loaded before QP is reused as P

    float4 o[8];
    #pragma unroll
    for (int j = 0; j < 8; j++) o[j] = make_float4(0.f, 0.f, 0.f, 0.f);
    float l0 = 0.f, l1 = 0.f;
    const int r0g = m0 + wr + g;              // global query row of c.x/c.y
    const bool lat0 = (r0g     >= CTX_);
    const bool lat1 = (r0g + 8 >= CTX_);

    for (int kt = 0; kt < 16; kt++) {
        const float* kb = g_KVh  + ((size_t)bh * N_ + kt * 64) * DH_;
        const float* vb = g_LKVh + ((size_t)bh * N_ + kt * 64) * DH_;
        #pragma unroll
        for (int i = 0; i < 4; i++) {
            int idx = tid + i * 256;          // 0..1023 float4s
            int r = idx >> 4, c4 = (idx & 15) * 4;
            float4 kv = *(const float4*)(kb + (size_t)r * DH_ + c4);
            KS(r, c4 + 0) = f2t(kv.x); KS(r, c4 + 1) = f2t(kv.y);
            KS(r, c4 + 2) = f2t(kv.z); KS(r, c4 + 3) = f2t(kv.w);
            float4 vv = *(const float4*)(vb + (size_t)r * DH_ + c4);
            VT(c4 + 0, r) = f2t(vv.x); VT(c4 + 1, r) = f2t(vv.y);
            VT(c4 + 2, r) = f2t(vv.z); VT(c4 + 3, r) = f2t(vv.w);
        }
        __syncthreads();

        // S = Q K^T for this 64-key tile, then exp -> P (warp-private rows)
        #pragma unroll
        for (int j = 0; j < 8; j++) {
            float4 s = make_float4(0.f, 0.f, 0.f, 0.f);
            #pragma unroll
            for (int kk = 0; kk < 8; kk++) {
                uint32_t b[2];
                b[0] = KS(j * 8 + g, kk * 8 + t);
                b[1] = KS(j * 8 + g, kk * 8 + t + 4);
                mma8(s, qa[kk], b);
            }
            float px = __expf(s.x), py = __expf(s.y);
            float pz = __expf(s.z), pw = __expf(s.w);
            if (kt == 15) {
                int kc = j * 8 + 2 * t;       // local key col (even)
                if (kc >= 32) {               // keys >= CTX_
                    if (!lat0) { px = 0.f; py = 0.f; }
                    if (!lat1) { pz = 0.f; pw = 0.f; }
                }
            }
            l0 += px + py; l1 += pz + pw;
            int c = j * 8 + 2 * t;
            QP(wr + g,     c) = f2t(px); QP(wr + g,     c + 1) = f2t(py);
            QP(wr + g + 8, c) = f2t(pz); QP(wr + g + 8, c + 1) = f2t(pw);
        }
        __syncwarp();

        // O += P V
        #pragma unroll
        for (int kk = 0; kk < 8; kk++) {
            uint32_t ap[4];
            ap[0] = QP(wr + g,     kk * 8 + t);
            ap[1] = QP(wr + g + 8, kk * 8 + t);
            ap[2] = QP(wr + g,     kk * 8 + t + 4);
            ap[3] = QP(wr + g + 8, kk * 8 + t + 4);
            #pragma unroll
            for (int j = 0; j < 8; j++) {
                uint32_t b[2];
                b[0] = VT(j * 8 + g, kk * 8 + t);
                b[1] = VT(j * 8 + g, kk * 8 + t + 4);
                mma8(o[j], ap, b);
            }
        }
        __syncthreads();
    }

    // rowsum reduce across the 4 lanes of each group
    l0 += __shfl_xor_sync(0xffffffffu, l0, 1);
    l0 += __shfl_xor_sync(0xffffffffu, l0, 2);
    l1 += __shfl_xor_sync(0xffffffffu, l1, 1);
    l1 += __shfl_xor_sync(0xffffffffu, l1, 2);
    float i0 = 1.0f / l0, i1 = 1.0f / l1;

    const int bb = bh / H_, h = bh % H_;
    #pragma unroll
    for (int j = 0; j < 8; j++) {
        int col = h * 64 + j * 8 + 2 * t;
        float* p0 = g_Attn + (size_t)(bb * N_ + r0g)     * DIM_ + col;
        float* p1 = g_Attn + (size_t)(bb * N_ + r0g + 8) * DIM_ + col;
        p0[0] = o[j].x * i0; p0[1] = o[j].y * i0;
        p1[0] = o[j].z * i1; p1[1] = o[j].w * i1;
    }
}

// ---------------- output projection (row-dependent W) ------------------------
// M tile 32 (992 = 31*32 -> homogeneous), N tile 128. grid (256, 6), 256 thr.
__global__ __launch_bounds__(256) void out_kernel(const float* __restrict__ Wc,
                                                  const float* __restrict__ bc,
                                                  const float* __restrict__ Wl,
                                                  const float* __restrict__ bl,
                                                  float* __restrict__ out) {
    __shared__ uint32_t As[32][33];
    __shared__ uint32_t Bs[32][129];

    const int m0 = blockIdx.x * 32;
    const int n0 = blockIdx.y * 128;
    const bool ctx = ((m0 & 1023) < CTX_);
    const float* W    = ctx ? Wc : Wl;
    const float* bias = ctx ? bc : bl;

    const int tid = threadIdx.x;
    const int lane = tid & 31, wid = tid >> 5;
    const int wm = (wid & 1) * 16;
    const int wn = (wid >> 1) * 32;
    const int g = lane >> 2, t = lane & 3;

    float4 acc[4];
    #pragma unroll
    for (int j = 0; j < 4; j++) acc[j] = make_float4(0.f, 0.f, 0.f, 0.f);

    for (int k0 = 0; k0 < DIM_; k0 += 32) {
        __syncthreads();
        {                                      // A: 32x32, 1 float4/thread
            int r = tid >> 3, c4 = (tid & 7) * 4;
            float4 v = *(const float4*)(g_Attn + (size_t)(m0 + r) * DIM_ + k0 + c4);
            As[r][c4 + 0] = f2t(v.x); As[r][c4 + 1] = f2t(v.y);
            As[r][c4 + 2] = f2t(v.z); As[r][c4 + 3] = f2t(v.w);
        }
        #pragma unroll
        for (int i = 0; i < 4; i++) {          // B: 32x128
            int idx = tid + i * 256;
            int r = idx >> 5, c4 = (idx & 31) * 4;
            float4 v = *(const float4*)(W + (size_t)(k0 + r) * DIM_ + n0 + c4);
            Bs[r][c4 + 0] = f2t(v.x); Bs[r][c4 + 1] = f2t(v.y);
            Bs[r][c4 + 2] = f2t(v.z); Bs[r][c4 + 3] = f2t(v.w);
        }
        __syncthreads();

        #pragma unroll
        for (int kk = 0; kk < 4; kk++) {
            uint32_t a[4];
            a[0] = As[wm + g    ][kk * 8 + t];
            a[1] = As[wm + g + 8][kk * 8 + t];
            a[2] = As[wm + g    ][kk * 8 + t + 4];
            a[3] = As[wm + g + 8][kk * 8 + t + 4];
            #pragma unroll
            for (int j = 0; j < 4; j++) {
                uint32_t b[2];
                b[0] = Bs[kk * 8 + t    ][wn + j * 8 + g];
                b[1] = Bs[kk * 8 + t + 4][wn + j * 8 + g];
                mma8(acc[j], a, b);
            }
        }
    }

    #pragma unroll
    for (int j = 0; j < 4; j++) {
        int col = n0 + wn + j * 8 + 2 * t;
        float bx = bias[col], by = bias[col + 1];
        int r0 = m0 + wm + g;
        out[(size_t)r0 * DIM_ + col]           = acc[j].x + bx;
        out[(size_t)r0 * DIM_ + col + 1]       = acc[j].y + by;
        out[(size_t)(r0 + 8) * DIM_ + col]     = acc[j].z + bx;
        out[(size_t)(r0 + 8) * DIM_ + col + 1] = acc[j].w + by;
    }
}

// ---------------- launch -----------------------------------------------------
extern "C" void kernel_launch(void* const* d_in, const int* in_sizes, int n_in,
                              void* d_out, int out_size) {
    const float* x      = (const float*)d_in[0];
    const float* Wq     = (const float*)d_in[1];
    const float* Wkv    = (const float*)d_in[2];
    const float* Wo_ctx = (const float*)d_in[3];
    const float* bo_ctx = (const float*)d_in[4];
    const float* Wo_lat = (const float*)d_in[5];
    const float* bo_lat = (const float*)d_in[6];
    const float* ln_g   = (const float*)d_in[7];
    const float* ln_b   = (const float*)d_in[8];
    float* out = (float*)d_out;

    cudaFuncSetAttribute(attn_kernel,
                         cudaFuncAttributeMaxDynamicSharedMemorySize, 66560);

    proj_kernel<0><<<dim3(64, 12), 256>>>(x, Wq, nullptr, nullptr);
    proj_kernel<1><<<dim3(64, 12), 256>>>(x, Wkv, ln_g, ln_b);
    attn_kernel<<<dim3(96, 8), 256, 66560>>>();
    out_kernel<<<dim3(256, 6), 256>>>(Wo_ctx, bo_ctx, Wo_lat, bo_lat, out);
}

// round 5
// speedup vs baseline: 2.4404x; 2.4404x over previous
#include <cuda_runtime.h>
#include <math.h>
#include <stdint.h>

#define B_    8
#define N_    1024
#define DIM_  768
#define H_    12
#define DH_   64
#define CTX_  992
#define BH_   96
#define ROWS_ 8192
#define GCTX_ 7936   // 8*992 grouped ctx rows

// ---------------- scratch ----------------------------------------------------
__device__ float g_Qh  [BH_ * N_ * DH_];
__device__ float g_KVh [BH_ * N_ * DH_];
__device__ float g_LKVh[BH_ * N_ * DH_];
__device__ float g_LKVT[BH_ * DH_ * N_];    // per-head transposed LN(KV): [d][key]
__device__ float g_Attn[ROWS_ * DIM_];      // grouped rows: ctx first, latent tail
__device__ float g_WqT [DIM_ * DIM_];
__device__ float g_WkvT[DIM_ * DIM_];
__device__ float g_WocT[DIM_ * DIM_];
__device__ float g_WolT[DIM_ * DIM_];

// ---------------- helpers ----------------------------------------------------
__device__ __forceinline__ uint32_t f2t(float x) {
    uint32_t r; asm("cvt.rna.tf32.f32 %0, %1;" : "=r"(r) : "f"(x)); return r;
}
__device__ __forceinline__ void mma8(float4& c, const uint32_t* a, uint32_t b0, uint32_t b1) {
    asm volatile(
        "mma.sync.aligned.m16n8k8.row.col.f32.tf32.tf32.f32 "
        "{%0,%1,%2,%3}, {%4,%5,%6,%7}, {%8,%9}, {%0,%1,%2,%3};\n"
        : "+f"(c.x), "+f"(c.y), "+f"(c.z), "+f"(c.w)
        : "r"(a[0]), "r"(a[1]), "r"(a[2]), "r"(a[3]), "r"(b0), "r"(b1));
}
__device__ __forceinline__ void ldsm4(uint32_t& r0, uint32_t& r1, uint32_t& r2,
                                      uint32_t& r3, uint32_t addr) {
    asm volatile("ldmatrix.sync.aligned.m8n8.x4.shared.b16 {%0,%1,%2,%3}, [%4];"
                 : "=r"(r0), "=r"(r1), "=r"(r2), "=r"(r3) : "r"(addr));
}
// per-lane ldmatrix byte offset for row-stride S (in u32)
__device__ __forceinline__ uint32_t lane_off(int lane, int S) {
    int lr = ((lane >> 3) & 1) * 8 + (lane & 7);
    int lc = (lane >> 4) * 4;
    return (uint32_t)(lr * S + lc) * 4u;
}

// ---------------- transpose: dst[C][R] = src[R][C], batched on z -------------
__global__ __launch_bounds__(256) void transpose_kernel(const float* __restrict__ srcp,
                                                        int which, int R, int C) {
    __shared__ float tile[32][33];
    const float* src;
    float* dst;
    switch (which) {
        case 0: src = srcp;   dst = g_WqT;  break;
        case 1: src = srcp;   dst = g_WkvT; break;
        case 2: src = srcp;   dst = g_WocT; break;
        case 3: src = srcp;   dst = g_WolT; break;
        default: src = g_LKVh; dst = g_LKVT; break;
    }
    size_t zo = (size_t)blockIdx.z * R * C;
    src += zo; dst += zo;
    int c0 = blockIdx.x * 32, r0 = blockIdx.y * 32;
    int tx = threadIdx.x & 31, ty = threadIdx.x >> 5;
    #pragma unroll
    for (int i = 0; i < 4; i++)
        tile[ty + i * 8][tx] = src[(size_t)(r0 + ty + i * 8) * C + c0 + tx];
    __syncthreads();
    #pragma unroll
    for (int i = 0; i < 4; i++)
        dst[(size_t)(c0 + ty + i * 8) * R + r0 + tx] = tile[tx][ty + i * 8];
}

// ---------------- projection + in-register RoPE(/LN) epilogue ----------------
// block 128x64 (one head), 8 warps x 16 rows, warp covers all 64 cols.
template<int IS_KV>
__global__ __launch_bounds__(256) void proj_kernel(const float* __restrict__ A,
                                                   const float* __restrict__ lng,
                                                   const float* __restrict__ lnb) {
    __shared__ uint32_t As[128 * 36];
    __shared__ uint32_t Bs[64 * 36];
    const float* WT = IS_KV ? g_WkvT : g_WqT;

    const int m0 = blockIdx.x * 128;
    const int head = blockIdx.y;
    const int n0 = head * 64;
    const int tid = threadIdx.x;
    const int lane = tid & 31, wid = tid >> 5;
    const int g = lane >> 2, t = lane & 3;
    const uint32_t sA = (uint32_t)__cvta_generic_to_shared(As) + lane_off(lane, 36);
    const uint32_t sB = (uint32_t)__cvta_generic_to_shared(Bs) + lane_off(lane, 36);

    float4 acc[8];
    #pragma unroll
    for (int j = 0; j < 8; j++) acc[j] = make_float4(0.f, 0.f, 0.f, 0.f);

    for (int k0 = 0; k0 < DIM_; k0 += 32) {
        __syncthreads();
        #pragma unroll
        for (int i = 0; i < 4; i++) {            // A: 128 x 32
            int idx = tid + i * 256;
            int r = idx >> 3, c4 = (idx & 7) * 4;
            float4 v = *(const float4*)(A + (size_t)(m0 + r) * DIM_ + k0 + c4);
            *(uint4*)&As[r * 36 + c4] = make_uint4(f2t(v.x), f2t(v.y), f2t(v.z), f2t(v.w));
        }
        #pragma unroll
        for (int i = 0; i < 2; i++) {            // B^T: 64 n x 32 k
            int idx = tid + i * 256;
            int r = idx >> 3, c4 = (idx & 7) * 4;
            float4 v = *(const float4*)(WT + (size_t)(n0 + r) * DIM_ + k0 + c4);
            *(uint4*)&Bs[r * 36 + c4] = make_uint4(f2t(v.x), f2t(v.y), f2t(v.z), f2t(v.w));
        }
        __syncthreads();

        #pragma unroll
        for (int kk = 0; kk < 4; kk++) {
            uint32_t a[4];
            ldsm4(a[0], a[1], a[2], a[3], sA + (uint32_t)((wid * 16) * 36 + kk * 8) * 4);
            #pragma unroll
            for (int jp = 0; jp < 4; jp++) {
                uint32_t b0, b1, b2, b3;
                ldsm4(b0, b1, b2, b3, sB + (uint32_t)((jp * 16) * 36 + kk * 8) * 4);
                mma8(acc[2 * jp],     a, b0, b2);
                mma8(acc[2 * jp + 1], a, b1, b3);
            }
        }
    }

    // in-register RoPE (+LN): pair (d, d+32) = acc[jl] / acc[jl+4], same lane.
    const int rA = m0 + wid * 16 + g;           // rows rA (x,y) and rA+8 (z,w)
    const int bb = rA >> 10;
    const int nA = rA & 1023;
    float lo[4][4], hi[4][4];
    #pragma unroll
    for (int jl = 0; jl < 4; jl++)
        #pragma unroll
        for (int c = 0; c < 4; c++) {
            float v1 = ((const float*)&acc[jl])[c];
            float v2 = ((const float*)&acc[jl + 4])[c];
            int d = jl * 8 + 2 * t + (c & 1);
            int n = nA + (c >> 1) * 8;
            float inv = exp2f(-(float)d * 0.41524101186092034f);
            float sn, cs;
            sincosf((float)n * inv, &sn, &cs);
            lo[jl][c] = v1 * cs - v2 * sn;
            hi[jl][c] = v2 * cs + v1 * sn;
        }

    size_t oA = ((size_t)(bb * H_ + head) * N_ + nA) * DH_ + 2 * t;
    size_t oB = oA + 8 * DH_;
    if (!IS_KV) {
        #pragma unroll
        for (int jl = 0; jl < 4; jl++) {
            *(float2*)(g_Qh + oA + jl * 8)      = make_float2(lo[jl][0] * 0.125f, lo[jl][1] * 0.125f);
            *(float2*)(g_Qh + oA + jl * 8 + 32) = make_float2(hi[jl][0] * 0.125f, hi[jl][1] * 0.125f);
            *(float2*)(g_Qh + oB + jl * 8)      = make_float2(lo[jl][2] * 0.125f, lo[jl][3] * 0.125f);
            *(float2*)(g_Qh + oB + jl * 8 + 32) = make_float2(hi[jl][2] * 0.125f, hi[jl][3] * 0.125f);
        }
    } else {
        #pragma unroll
        for (int jl = 0; jl < 4; jl++) {
            *(float2*)(g_KVh + oA + jl * 8)      = make_float2(lo[jl][0], lo[jl][1]);
            *(float2*)(g_KVh + oA + jl * 8 + 32) = make_float2(hi[jl][0], hi[jl][1]);
            *(float2*)(g_KVh + oB + jl * 8)      = make_float2(lo[jl][2], lo[jl][3]);
            *(float2*)(g_KVh + oB + jl * 8 + 32) = make_float2(hi[jl][2], hi[jl][3]);
        }
        float sumA = 0.f, sumB = 0.f;
        #pragma unroll
        for (int jl = 0; jl < 4; jl++) {
            sumA += lo[jl][0] + lo[jl][1] + hi[jl][0] + hi[jl][1];
            sumB += lo[jl][2] + lo[jl][3] + hi[jl][2] + hi[jl][3];
        }
        sumA += __shfl_xor_sync(0xffffffffu, sumA, 1);
        sumA += __shfl_xor_sync(0xffffffffu, sumA, 2);
        sumB += __shfl_xor_sync(0xffffffffu, sumB, 1);
        sumB += __shfl_xor_sync(0xffffffffu, sumB, 2);
        float mA = sumA * (1.f / 64.f), mB = sumB * (1.f / 64.f);
        float vA = 0.f, vB = 0.f;
        #pragma unroll
        for (int jl = 0; jl < 4; jl++)
            #pragma unroll
            for (int c = 0; c < 2; c++) {
                float d1 = lo[jl][c] - mA, d2 = hi[jl][c] - mA;
                vA += d1 * d1 + d2 * d2;
                float d3 = lo[jl][c + 2] - mB, d4 = hi[jl][c + 2] - mB;
                vB += d3 * d3 + d4 * d4;
            }
        vA += __shfl_xor_sync(0xffffffffu, vA, 1);
        vA += __shfl_xor_sync(0xffffffffu, vA, 2);
        vB += __shfl_xor_sync(0xffffffffu, vB, 1);
        vB += __shfl_xor_sync(0xffffffffu, vB, 2);
        float iA = rsqrtf(vA * (1.f / 64.f) + 1e-5f);
        float iB = rsqrtf(vB * (1.f / 64.f) + 1e-5f);
        #pragma unroll
        for (int jl = 0; jl < 4; jl++) {
            int d = jl * 8 + 2 * t;
            float g0 = lng[d], g1 = lng[d + 1], b0 = lnb[d], b1 = lnb[d + 1];
            float g2 = lng[d + 32], g3 = lng[d + 33], b2 = lnb[d + 32], b3 = lnb[d + 33];
            *(float2*)(g_LKVh + oA + jl * 8) = make_float2(
                (lo[jl][0] - mA) * iA * g0 + b0, (lo[jl][1] - mA) * iA * g1 + b1);
            *(float2*)(g_LKVh + oA + jl * 8 + 32) = make_float2(
                (hi[jl][0] - mA) * iA * g2 + b2, (hi[jl][1] - mA) * iA * g3 + b3);
            *(float2*)(g_LKVh + oB + jl * 8) = make_float2(
                (lo[jl][2] - mB) * iB * g0 + b0, (lo[jl][3] - mB) * iB * g1 + b1);
            *(float2*)(g_LKVh + oB + jl * 8 + 32) = make_float2(
                (hi[jl][2] - mB) * iB * g2 + b2, (hi[jl][3] - mB) * iB * g3 + b3);
        }
    }
}

// ---------------- fused attention (ldmatrix everywhere) ----------------------
// grid (96,8), 256 threads. dyn smem u32: QP[128][68]@0, KS[64][68]@8704,
// VT[64][68]@13056 -> 17408 u32 = 69632 B. Q region reused for P.
__global__ __launch_bounds__(256, 2) void attn_kernel() {
    extern __shared__ uint32_t dsm[];
    const int bh = blockIdx.x, qt = blockIdx.y;
    const int m0 = qt * 128;
    const int tid = threadIdx.x;
    const int lane = tid & 31, wid = tid >> 5;
    const int g = lane >> 2, t = lane & 3;
    const int wr = wid * 16;
    const uint32_t sbase = (uint32_t)__cvta_generic_to_shared(dsm);
    const uint32_t lo68 = lane_off(lane, 68);
    const uint32_t lbQ = sbase + lo68;
    const uint32_t lbK = sbase + 8704u * 4 + lo68;
    const uint32_t lbV = sbase + 13056u * 4 + lo68;

    const float* qsrc = g_Qh + ((size_t)bh * N_ + m0) * DH_;
    #pragma unroll
    for (int i = 0; i < 8; i++) {
        int idx = tid + i * 256;
        int r = idx >> 4, c4 = (idx & 15) * 4;
        float4 v = *(const float4*)(qsrc + (size_t)r * DH_ + c4);
        *(uint4*)&dsm[r * 68 + c4] = make_uint4(f2t(v.x), f2t(v.y), f2t(v.z), f2t(v.w));
    }
    __syncthreads();
    uint32_t qa[8][4];
    #pragma unroll
    for (int kk = 0; kk < 8; kk++)
        ldsm4(qa[kk][0], qa[kk][1], qa[kk][2], qa[kk][3],
              lbQ + (uint32_t)(wr * 68 + kk * 8) * 4);

    float4 o[8];
    #pragma unroll
    for (int j = 0; j < 8; j++) o[j] = make_float4(0.f, 0.f, 0.f, 0.f);
    float l0 = 0.f, l1 = 0.f;
    const int r0g = m0 + wr + g;
    const bool lat0 = (r0g >= CTX_);
    const bool lat1 = (r0g + 8 >= CTX_);

    for (int kt = 0; kt < 16; kt++) {
        const float* kb = g_KVh + ((size_t)bh * N_ + kt * 64) * DH_;
        const float* vt = g_LKVT + (size_t)bh * DH_ * N_ + kt * 64;
        __syncthreads();
        #pragma unroll
        for (int i = 0; i < 4; i++) {
            int idx = tid + i * 256;
            int r = idx >> 4, c4 = (idx & 15) * 4;
            float4 kv = *(const float4*)(kb + (size_t)r * DH_ + c4);
            *(uint4*)&dsm[8704 + r * 68 + c4] =
                make_uint4(f2t(kv.x), f2t(kv.y), f2t(kv.z), f2t(kv.w));
            float4 vv = *(const float4*)(vt + (size_t)r * N_ + c4);
            *(uint4*)&dsm[13056 + r * 68 + c4] =
                make_uint4(f2t(vv.x), f2t(vv.y), f2t(vv.z), f2t(vv.w));
        }
        __syncthreads();

        float4 s[8];
        #pragma unroll
        for (int j = 0; j < 8; j++) s[j] = make_float4(0.f, 0.f, 0.f, 0.f);
        #pragma unroll
        for (int kk = 0; kk < 8; kk++) {
            #pragma unroll
            for (int jp = 0; jp < 4; jp++) {
                uint32_t b0, b1, b2, b3;
                ldsm4(b0, b1, b2, b3, lbK + (uint32_t)((jp * 16) * 68 + kk * 8) * 4);
                mma8(s[2 * jp],     qa[kk], b0, b2);
                mma8(s[2 * jp + 1], qa[kk], b1, b3);
            }
        }
        #pragma unroll
        for (int j = 0; j < 8; j++) {
            float px = __expf(s[j].x), py = __expf(s[j].y);
            float pz = __expf(s[j].z), pw = __expf(s[j].w);
            if (kt == 15 && (j * 8 + 2 * t) >= 32) {
                if (!lat0) { px = 0.f; py = 0.f; }
                if (!lat1) { pz = 0.f; pw = 0.f; }
            }
            l0 += px + py; l1 += pz + pw;
            *(uint2*)&dsm[(wr + g) * 68 + j * 8 + 2 * t]     = make_uint2(f2t(px), f2t(py));
            *(uint2*)&dsm[(wr + g + 8) * 68 + j * 8 + 2 * t] = make_uint2(f2t(pz), f2t(pw));
        }
        __syncwarp();
        #pragma unroll
        for (int kk = 0; kk < 8; kk++) {
            uint32_t pa[4];
            ldsm4(pa[0], pa[1], pa[2], pa[3], lbQ + (uint32_t)(wr * 68 + kk * 8) * 4);
            #pragma unroll
            for (int jp = 0; jp < 4; jp++) {
                uint32_t b0, b1, b2, b3;
                ldsm4(b0, b1, b2, b3, lbV + (uint32_t)((jp * 16) * 68 + kk * 8) * 4);
                mma8(o[2 * jp],     pa, b0, b2);
                mma8(o[2 * jp + 1], pa, b1, b3);
            }
        }
    }

    l0 += __shfl_xor_sync(0xffffffffu, l0, 1);
    l0 += __shfl_xor_sync(0xffffffffu, l0, 2);
    l1 += __shfl_xor_sync(0xffffffffu, l1, 1);
    l1 += __shfl_xor_sync(0xffffffffu, l1, 2);
    float i0 = 1.0f / l0, i1 = 1.0f / l1;

    const int bb = bh / H_, h = bh % H_;
    int gr0 = (r0g < CTX_) ? bb * CTX_ + r0g : GCTX_ + bb * 32 + (r0g - CTX_);
    int r1g = r0g + 8;
    int gr1 = (r1g < CTX_) ? bb * CTX_ + r1g : GCTX_ + bb * 32 + (r1g - CTX_);
    #pragma unroll
    for (int j = 0; j < 8; j++) {
        int col = h * 64 + j * 8 + 2 * t;
        *(float2*)(g_Attn + (size_t)gr0 * DIM_ + col) = make_float2(o[j].x * i0, o[j].y * i0);
        *(float2*)(g_Attn + (size_t)gr1 * DIM_ + col) = make_float2(o[j].z * i1, o[j].w * i1);
    }
}

// ---------------- output projection: 128x128 tiles, grouped rows -------------
__global__ __launch_bounds__(256) void out_kernel(const float* __restrict__ bc,
                                                  const float* __restrict__ bl,
                                                  float* __restrict__ out) {
    __shared__ uint32_t As[128 * 36];
    __shared__ uint32_t Bs[128 * 36];
    const int m0 = blockIdx.x * 128;
    const int n0 = blockIdx.y * 128;
    const bool ctx = (m0 < GCTX_);           // 7936 = 62*128 -> homogeneous tiles
    const float* WT   = ctx ? g_WocT : g_WolT;
    const float* bias = ctx ? bc : bl;

    const int tid = threadIdx.x;
    const int lane = tid & 31, wid = tid >> 5;
    const int wm = (wid & 3) * 32;
    const int wn = (wid >> 2) * 64;
    const int g = lane >> 2, t = lane & 3;
    const uint32_t sA = (uint32_t)__cvta_generic_to_shared(As) + lane_off(lane, 36);
    const uint32_t sB = (uint32_t)__cvta_generic_to_shared(Bs) + lane_off(lane, 36);

    float4 acc[2][8];
    #pragma unroll
    for (int i = 0; i < 2; i++)
        #pragma unroll
        for (int j = 0; j < 8; j++) acc[i][j] = make_float4(0.f, 0.f, 0.f, 0.f);

    for (int k0 = 0; k0 < DIM_; k0 += 32) {
        __syncthreads();
        #pragma unroll
        for (int i = 0; i < 4; i++) {
            int idx = tid + i * 256;
            int r = idx >> 3, c4 = (idx & 7) * 4;
            float4 v = *(const float4*)(g_Attn + (size_t)(m0 + r) * DIM_ + k0 + c4);
            *(uint4*)&As[r * 36 + c4] = make_uint4(f2t(v.x), f2t(v.y), f2t(v.z), f2t(v.w));
            float4 w = *(const float4*)(WT + (size_t)(n0 + r) * DIM_ + k0 + c4);
            *(uint4*)&Bs[r * 36 + c4] = make_uint4(f2t(w.x), f2t(w.y), f2t(w.z), f2t(w.w));
        }
        __syncthreads();

        #pragma unroll
        for (int kk = 0; kk < 4; kk++) {
            uint32_t a0[4], a1[4];
            ldsm4(a0[0], a0[1], a0[2], a0[3], sA + (uint32_t)(wm * 36 + kk * 8) * 4);
            ldsm4(a1[0], a1[1], a1[2], a1[3], sA + (uint32_t)((wm + 16) * 36 + kk * 8) * 4);
            #pragma unroll
            for (int jp = 0; jp < 4; jp++) {
                uint32_t b0, b1, b2, b3;
                ldsm4(b0, b1, b2, b3, sB + (uint32_t)((wn + jp * 16) * 36 + kk * 8) * 4);
                mma8(acc[0][2 * jp],     a0, b0, b2);
                mma8(acc[0][2 * jp + 1], a0, b1, b3);
                mma8(acc[1][2 * jp],     a1, b0, b2);
                mma8(acc[1][2 * jp + 1], a1, b1, b3);
            }
        }
    }

    #pragma unroll
    for (int mt = 0; mt < 2; mt++) {
        int rA = m0 + wm + mt * 16 + g;
        #pragma unroll
        for (int half = 0; half < 2; half++) {
            int r = rA + half * 8;
            int b, n;
            if (r < GCTX_) { b = r / CTX_; n = r - b * CTX_; }
            else { int q = r - GCTX_; b = q >> 5; n = CTX_ + (q & 31); }
            float* orow = out + (size_t)(b * N_ + n) * DIM_;
            #pragma unroll
            for (int jf = 0; jf < 8; jf++) {
                int col = n0 + wn + jf * 8 + 2 * t;
                float vx = half ? acc[mt][jf].z : acc[mt][jf].x;
                float vy = half ? acc[mt][jf].w : acc[mt][jf].y;
                *(float2*)(orow + col) = make_float2(vx + bias[col], vy + bias[col + 1]);
            }
        }
    }
}

// ---------------- launch -----------------------------------------------------
extern "C" void kernel_launch(void* const* d_in, const int* in_sizes, int n_in,
                              void* d_out, int out_size) {
    const float* x      = (const float*)d_in[0];
    const float* Wq     = (const float*)d_in[1];
    const float* Wkv    = (const float*)d_in[2];
    const float* Wo_ctx = (const float*)d_in[3];
    const float* bo_ctx = (const float*)d_in[4];
    const float* Wo_lat = (const float*)d_in[5];
    const float* bo_lat = (const float*)d_in[6];
    const float* ln_g   = (const float*)d_in[7];
    const float* ln_b   = (const float*)d_in[8];
    float* out = (float*)d_out;

    cudaFuncSetAttribute(attn_kernel,
                         cudaFuncAttributeMaxDynamicSharedMemorySize, 69632);

    dim3 tw(24, 24, 1);
    transpose_kernel<<<tw, 256>>>(Wq, 0, DIM_, DIM_);
    transpose_kernel<<<tw, 256>>>(Wkv, 1, DIM_, DIM_);
    transpose_kernel<<<tw, 256>>>(Wo_ctx, 2, DIM_, DIM_);
    transpose_kernel<<<tw, 256>>>(Wo_lat, 3, DIM_, DIM_);

    proj_kernel<0><<<dim3(64, 12), 256>>>(x, nullptr, nullptr);
    proj_kernel<1><<<dim3(64, 12), 256>>>(x, ln_g, ln_b);

    transpose_kernel<<<dim3(2, 32, 96), 256>>>(nullptr, 4, N_, DH_);

    attn_kernel<<<dim3(96, 8), 256, 69632>>>();
    out_kernel<<<dim3(64, 6), 256>>>(bo_ctx, bo_lat, out);
}

// round 7
// speedup vs baseline: 4.0994x; 1.6798x over previous
#include <cuda_runtime.h>
#include <cuda_fp16.h>
#include <math.h>
#include <stdint.h>

#define B_    8
#define N_    1024
#define DIM_  768
#define H_    12
#define DH_   64
#define CTX_  992
#define BH_   96
#define ROWS_ 8192
#define GCTX_ 7936   // 8*992 grouped ctx rows

// ---------------- scratch (all fp16) -----------------------------------------
__device__ __half g_Qh  [BH_ * N_ * DH_];
__device__ __half g_KVh [BH_ * N_ * DH_];
__device__ __half g_LKVh[BH_ * N_ * DH_];
__device__ __half g_Attn[ROWS_ * DIM_];     // grouped rows: ctx first, latent tail
__device__ __half g_WqT [DIM_ * DIM_];
__device__ __half g_WkvT[DIM_ * DIM_];
__device__ __half g_WocT[DIM_ * DIM_];
__device__ __half g_WolT[DIM_ * DIM_];

// ---------------- helpers ----------------------------------------------------
__device__ __forceinline__ uint32_t f2h2(float a, float b) {
    __half2 h = __floats2half2_rn(a, b);
    return *reinterpret_cast<uint32_t*>(&h);
}
__device__ __forceinline__ void mma16(float4& c, const uint32_t* a, uint32_t b0, uint32_t b1) {
    asm volatile(
        "mma.sync.aligned.m16n8k16.row.col.f32.f16.f16.f32 "
        "{%0,%1,%2,%3}, {%4,%5,%6,%7}, {%8,%9}, {%0,%1,%2,%3};\n"
        : "+f"(c.x), "+f"(c.y), "+f"(c.z), "+f"(c.w)
        : "r"(a[0]), "r"(a[1]), "r"(a[2]), "r"(a[3]), "r"(b0), "r"(b1));
}
__device__ __forceinline__ void ldsm4(uint32_t& r0, uint32_t& r1, uint32_t& r2,
                                      uint32_t& r3, uint32_t addr) {
    asm volatile("ldmatrix.sync.aligned.m8n8.x4.shared.b16 {%0,%1,%2,%3}, [%4];"
                 : "=r"(r0), "=r"(r1), "=r"(r2), "=r"(r3) : "r"(addr));
}
__device__ __forceinline__ void ldsm4t(uint32_t& r0, uint32_t& r1, uint32_t& r2,
                                       uint32_t& r3, uint32_t addr) {
    asm volatile("ldmatrix.sync.aligned.m8n8.x4.trans.shared.b16 {%0,%1,%2,%3}, [%4];"
                 : "=r"(r0), "=r"(r1), "=r"(r2), "=r"(r3) : "r"(addr));
}
// per-lane ldmatrix byte offsets; S = row stride in u32 (half2 units)
__device__ __forceinline__ uint32_t lane_off16(int lane, int S) {
    int lr = (lane & 7) + ((lane >> 3) & 1) * 8;
    return (uint32_t)(lr * S * 4 + (lane >> 4) * 16);
}
__device__ __forceinline__ uint32_t lane_off16t(int lane, int S) {   // for V .trans
    int lr = (lane & 7) + ((lane >> 4) & 1) * 8;
    return (uint32_t)(lr * S * 4 + ((lane >> 3) & 1) * 16);
}

// ---------------- weight transpose: half dst[C][R] = f32 src[R][C] -----------
__global__ __launch_bounds__(256) void transpose_w(const float* __restrict__ src,
                                                   int which) {
    __shared__ float tile[32][33];
    __half* dst;
    switch (which) {
        case 0: dst = g_WqT;  break;
        case 1: dst = g_WkvT; break;
        case 2: dst = g_WocT; break;
        default: dst = g_WolT; break;
    }
    int c0 = blockIdx.x * 32, r0 = blockIdx.y * 32;
    int tx = threadIdx.x & 31, ty = threadIdx.x >> 5;
    #pragma unroll
    for (int i = 0; i < 4; i++)
        tile[ty + i * 8][tx] = src[(size_t)(r0 + ty + i * 8) * DIM_ + c0 + tx];
    __syncthreads();
    #pragma unroll
    for (int i = 0; i < 4; i++)
        dst[(size_t)(c0 + ty + i * 8) * DIM_ + r0 + tx] = __float2half(tile[tx][ty + i * 8]);
}

// ---------------- projection + in-register RoPE(/LN) epilogue ----------------
// block 128x64 (one head), 8 warps x 16 rows, K-tile 64.
template<int IS_KV>
__global__ __launch_bounds__(256) void proj_kernel(const float* __restrict__ A,
                                                   const float* __restrict__ lng,
                                                   const float* __restrict__ lnb) {
    __shared__ uint32_t As[128 * 36];
    __shared__ uint32_t Bs[64 * 36];
    const __half* WT = IS_KV ? g_WkvT : g_WqT;

    const int m0 = blockIdx.x * 128;
    const int head = blockIdx.y;
    const int n0 = head * 64;
    const int tid = threadIdx.x;
    const int lane = tid & 31, wid = tid >> 5;
    const int g = lane >> 2, t = lane & 3;
    const uint32_t sA = (uint32_t)__cvta_generic_to_shared(As) + lane_off16(lane, 36);
    const uint32_t sB = (uint32_t)__cvta_generic_to_shared(Bs) + lane_off16(lane, 36);

    float4 acc[8];
    #pragma unroll
    for (int j = 0; j < 8; j++) acc[j] = make_float4(0.f, 0.f, 0.f, 0.f);

    for (int k0 = 0; k0 < DIM_; k0 += 64) {
        __syncthreads();
        #pragma unroll
        for (int i = 0; i < 4; i++) {             // A: 128 x 64 halves (cvt f32)
            int idx = tid + i * 256;
            int r = idx >> 3, c8 = (idx & 7) * 8;
            const float* ap = A + (size_t)(m0 + r) * DIM_ + k0 + c8;
            float4 v0 = *(const float4*)ap;
            float4 v1 = *(const float4*)(ap + 4);
            *(uint4*)&As[r * 36 + (idx & 7) * 4] = make_uint4(
                f2h2(v0.x, v0.y), f2h2(v0.z, v0.w), f2h2(v1.x, v1.y), f2h2(v1.z, v1.w));
        }
        #pragma unroll
        for (int i = 0; i < 2; i++) {             // B^T: 64 n x 64 k halves
            int idx = tid + i * 256;
            int r = idx >> 3, c = idx & 7;
            uint4 v = *(const uint4*)(WT + (size_t)(n0 + r) * DIM_ + k0 + c * 8);
            *(uint4*)&Bs[r * 36 + c * 4] = v;
        }
        __syncthreads();

        #pragma unroll
        for (int kk = 0; kk < 4; kk++) {
            uint32_t a[4];
            ldsm4(a[0], a[1], a[2], a[3], sA + (uint32_t)((wid * 16) * 36 * 4 + kk * 32));
            #pragma unroll
            for (int jp = 0; jp < 4; jp++) {
                uint32_t b0, b1, b2, b3;
                ldsm4(b0, b1, b2, b3, sB + (uint32_t)((jp * 16) * 36 * 4 + kk * 32));
                mma16(acc[2 * jp],     a, b0, b2);
                mma16(acc[2 * jp + 1], a, b1, b3);
            }
        }
    }

    // in-register RoPE (+LN): pair (d, d+32) = acc[jl] / acc[jl+4], same lane.
    const int rA = m0 + wid * 16 + g;            // rows rA (x,y) and rA+8 (z,w)
    const int bb = rA >> 10;
    const int nA = rA & 1023;
    float lo[4][4], hi[4][4];
    #pragma unroll
    for (int jl = 0; jl < 4; jl++)
        #pragma unroll
        for (int c = 0; c < 4; c++) {
            float v1 = ((const float*)&acc[jl])[c];
            float v2 = ((const float*)&acc[jl + 4])[c];
            int d = jl * 8 + 2 * t + (c & 1);
            int n = nA + (c >> 1) * 8;
            float inv = exp2f(-(float)d * 0.41524101186092034f);
            float sn, cs;
            sincosf((float)n * inv, &sn, &cs);
            lo[jl][c] = v1 * cs - v2 * sn;
            hi[jl][c] = v2 * cs + v1 * sn;
        }

    size_t oA = ((size_t)(bb * H_ + head) * N_ + nA) * DH_ + 2 * t;
    size_t oB = oA + 8 * DH_;
    if (!IS_KV) {
        #pragma unroll
        for (int jl = 0; jl < 4; jl++) {
            *(uint32_t*)(g_Qh + oA + jl * 8)      = f2h2(lo[jl][0] * 0.125f, lo[jl][1] * 0.125f);
            *(uint32_t*)(g_Qh + oA + jl * 8 + 32) = f2h2(hi[jl][0] * 0.125f, hi[jl][1] * 0.125f);
            *(uint32_t*)(g_Qh + oB + jl * 8)      = f2h2(lo[jl][2] * 0.125f, lo[jl][3] * 0.125f);
            *(uint32_t*)(g_Qh + oB + jl * 8 + 32) = f2h2(hi[jl][2] * 0.125f, hi[jl][3] * 0.125f);
        }
    } else {
        #pragma unroll
        for (int jl = 0; jl < 4; jl++) {
            *(uint32_t*)(g_KVh + oA + jl * 8)      = f2h2(lo[jl][0], lo[jl][1]);
            *(uint32_t*)(g_KVh + oA + jl * 8 + 32) = f2h2(hi[jl][0], hi[jl][1]);
            *(uint32_t*)(g_KVh + oB + jl * 8)      = f2h2(lo[jl][2], lo[jl][3]);
            *(uint32_t*)(g_KVh + oB + jl * 8 + 32) = f2h2(hi[jl][2], hi[jl][3]);
        }
        float sumA = 0.f, sumB = 0.f;
        #pragma unroll
        for (int jl = 0; jl < 4; jl++) {
            sumA += lo[jl][0] + lo[jl][1] + hi[jl][0] + hi[jl][1];
            sumB += lo[jl][2] + lo[jl][3] + hi[jl][2] + hi[jl][3];
        }
        sumA += __shfl_xor_sync(0xffffffffu, sumA, 1);
        sumA += __shfl_xor_sync(0xffffffffu, sumA, 2);
        sumB += __shfl_xor_sync(0xffffffffu, sumB, 1);
        sumB += __shfl_xor_sync(0xffffffffu, sumB, 2);
        float mA = sumA * (1.f / 64.f), mB = sumB * (1.f / 64.f);
        float vA = 0.f, vB = 0.f;
        #pragma unroll
        for (int jl = 0; jl < 4; jl++)
            #pragma unroll
            for (int c = 0; c < 2; c++) {
                float d1 = lo[jl][c] - mA, d2 = hi[jl][c] - mA;
                vA += d1 * d1 + d2 * d2;
                float d3 = lo[jl][c + 2] - mB, d4 = hi[jl][c + 2] - mB;
                vB += d3 * d3 + d4 * d4;
            }
        vA += __shfl_xor_sync(0xffffffffu, vA, 1);
        vA += __shfl_xor_sync(0xffffffffu, vA, 2);
        vB += __shfl_xor_sync(0xffffffffu, vB, 1);
        vB += __shfl_xor_sync(0xffffffffu, vB, 2);
        float iA = rsqrtf(vA * (1.f / 64.f) + 1e-5f);
        float iB = rsqrtf(vB * (1.f / 64.f) + 1e-5f);
        #pragma unroll
        for (int jl = 0; jl < 4; jl++) {
            int d = jl * 8 + 2 * t;
            float g0 = lng[d], g1 = lng[d + 1], b0 = lnb[d], b1 = lnb[d + 1];
            float g2 = lng[d + 32], g3 = lng[d + 33], b2 = lnb[d + 32], b3 = lnb[d + 33];
            *(uint32_t*)(g_LKVh + oA + jl * 8) = f2h2(
                (lo[jl][0] - mA) * iA * g0 + b0, (lo[jl][1] - mA) * iA * g1 + b1);
            *(uint32_t*)(g_LKVh + oA + jl * 8 + 32) = f2h2(
                (hi[jl][0] - mA) * iA * g2 + b2, (hi[jl][1] - mA) * iA * g3 + b3);
            *(uint32_t*)(g_LKVh + oB + jl * 8) = f2h2(
                (lo[jl][2] - mB) * iB * g0 + b0, (lo[jl][3] - mB) * iB * g1 + b1);
            *(uint32_t*)(g_LKVh + oB + jl * 8 + 32) = f2h2(
                (hi[jl][2] - mB) * iB * g2 + b2, (hi[jl][3] - mB) * iB * g3 + b3);
        }
    }
}

// ---------------- fused attention (fp16 mma, V via ldmatrix.trans) -----------
// grid (96,8), 256 threads. smem u32: QP[128*36]@0, K[64*36]@4608, V[64*36]@6912.
__global__ __launch_bounds__(256, 2) void attn_kernel() {
    __shared__ uint32_t dsm[9216];
    const int bh = blockIdx.x, qt = blockIdx.y;
    const int m0 = qt * 128;
    const int tid = threadIdx.x;
    const int lane = tid & 31, wid = tid >> 5;
    const int g = lane >> 2, t = lane & 3;
    const int wr = wid * 16;
    const uint32_t sbase = (uint32_t)__cvta_generic_to_shared(dsm);
    const uint32_t lbQ = sbase + lane_off16(lane, 36);
    const uint32_t lbK = sbase + 4608u * 4 + lane_off16(lane, 36);
    const uint32_t lbV = sbase + 6912u * 4 + lane_off16t(lane, 36);

    const __half* qsrc = g_Qh + ((size_t)bh * N_ + m0) * DH_;
    #pragma unroll
    for (int i = 0; i < 4; i++) {
        int idx = tid + i * 256;
        int r = idx >> 3, c = idx & 7;
        uint4 v = *(const uint4*)(qsrc + (size_t)r * DH_ + c * 8);
        *(uint4*)&dsm[r * 36 + c * 4] = v;
    }
    __syncthreads();
    uint32_t qa[4][4];
    #pragma unroll
    for (int kk = 0; kk < 4; kk++)
        ldsm4(qa[kk][0], qa[kk][1], qa[kk][2], qa[kk][3],
              lbQ + (uint32_t)(wr * 36 * 4 + kk * 32));

    float4 o[8];
    #pragma unroll
    for (int j = 0; j < 8; j++) o[j] = make_float4(0.f, 0.f, 0.f, 0.f);
    float l0 = 0.f, l1 = 0.f;
    const int r0g = m0 + wr + g;
    const bool lat0 = (r0g >= CTX_);
    const bool lat1 = (r0g + 8 >= CTX_);

    for (int kt = 0; kt < 16; kt++) {
        const __half* kb = g_KVh  + ((size_t)bh * N_ + kt * 64) * DH_;
        const __half* vb = g_LKVh + ((size_t)bh * N_ + kt * 64) * DH_;
        __syncthreads();
        #pragma unroll
        for (int i = 0; i < 2; i++) {
            int idx = tid + i * 256;
            int r = idx >> 3, c = idx & 7;
            uint4 kv = *(const uint4*)(kb + (size_t)r * DH_ + c * 8);
            *(uint4*)&dsm[4608 + r * 36 + c * 4] = kv;
            uint4 vv = *(const uint4*)(vb + (size_t)r * DH_ + c * 8);
            *(uint4*)&dsm[6912 + r * 36 + c * 4] = vv;
        }
        __syncthreads();

        float4 s[8];
        #pragma unroll
        for (int j = 0; j < 8; j++) s[j] = make_float4(0.f, 0.f, 0.f, 0.f);
        #pragma unroll
        for (int kk = 0; kk < 4; kk++) {
            #pragma unroll
            for (int jp = 0; jp < 4; jp++) {
                uint32_t b0, b1, b2, b3;
                ldsm4(b0, b1, b2, b3, lbK + (uint32_t)((jp * 16) * 36 * 4 + kk * 32));
                mma16(s[2 * jp],     qa[kk], b0, b2);
                mma16(s[2 * jp + 1], qa[kk], b1, b3);
            }
        }
        #pragma unroll
        for (int j = 0; j < 8; j++) {
            float px = __expf(s[j].x), py = __expf(s[j].y);
            float pz = __expf(s[j].z), pw = __expf(s[j].w);
            if (kt == 15 && j >= 4) {            // local key cols >= 32 -> key >= CTX_
                if (!lat0) { px = 0.f; py = 0.f; }
                if (!lat1) { pz = 0.f; pw = 0.f; }
            }
            l0 += px + py; l1 += pz + pw;
            dsm[(wr + g) * 36 + j * 4 + t]     = f2h2(px, py);
            dsm[(wr + g + 8) * 36 + j * 4 + t] = f2h2(pz, pw);
        }
        __syncwarp();
        #pragma unroll
        for (int kk = 0; kk < 4; kk++) {
            uint32_t pa[4];
            ldsm4(pa[0], pa[1], pa[2], pa[3], lbQ + (uint32_t)(wr * 36 * 4 + kk * 32));
            #pragma unroll
            for (int jp = 0; jp < 4; jp++) {
                uint32_t b0, b1, b2, b3;
                ldsm4t(b0, b1, b2, b3,
                       lbV + (uint32_t)((kk * 16) * 36 * 4 + (jp * 16) * 2));
                mma16(o[2 * jp],     pa, b0, b2);
                mma16(o[2 * jp + 1], pa, b1, b3);
            }
        }
    }

    l0 += __shfl_xor_sync(0xffffffffu, l0, 1);
    l0 += __shfl_xor_sync(0xffffffffu, l0, 2);
    l1 += __shfl_xor_sync(0xffffffffu, l1, 1);
    l1 += __shfl_xor_sync(0xffffffffu, l1, 2);
    float i0 = 1.0f / l0, i1 = 1.0f / l1;

    const int bb = bh / H_, h = bh % H_;
    int gr0 = (r0g < CTX_) ? bb * CTX_ + r0g : GCTX_ + bb * 32 + (r0g - CTX_);
    int r1g = r0g + 8;
    int gr1 = (r1g < CTX_) ? bb * CTX_ + r1g : GCTX_ + bb * 32 + (r1g - CTX_);
    #pragma unroll
    for (int j = 0; j < 8; j++) {
        int col = h * 64 + j * 8 + 2 * t;
        *(uint32_t*)(g_Attn + (size_t)gr0 * DIM_ + col) = f2h2(o[j].x * i0, o[j].y * i0);
        *(uint32_t*)(g_Attn + (size_t)gr1 * DIM_ + col) = f2h2(o[j].z * i1, o[j].w * i1);
    }
}

// ---------------- output projection: 128x128 tiles, grouped rows -------------
__global__ __launch_bounds__(256) void out_kernel(const float* __restrict__ bc,
                                                  const float* __restrict__ bl,
                                                  float* __restrict__ out) {
    __shared__ uint32_t As[128 * 36];
    __shared__ uint32_t Bs[128 * 36];
    const int m0 = blockIdx.x * 128;
    const int n0 = blockIdx.y * 128;
    const bool ctx = (m0 < GCTX_);            // 7936 = 62*128 -> homogeneous tiles
    const __half* WT  = ctx ? g_WocT : g_WolT;
    const float* bias = ctx ? bc : bl;

    const int tid = threadIdx.x;
    const int lane = tid & 31, wid = tid >> 5;
    const int wm = (wid & 3) * 32;
    const int wn = (wid >> 2) * 64;
    const int g = lane >> 2, t = lane & 3;
    const uint32_t sA = (uint32_t)__cvta_generic_to_shared(As) + lane_off16(lane, 36);
    const uint32_t sB = (uint32_t)__cvta_generic_to_shared(Bs) + lane_off16(lane, 36);

    float4 acc[2][8];
    #pragma unroll
    for (int i = 0; i < 2; i++)
        #pragma unroll
        for (int j = 0; j < 8; j++) acc[i][j] = make_float4(0.f, 0.f, 0.f, 0.f);

    for (int k0 = 0; k0 < DIM_; k0 += 64) {
        __syncthreads();
        #pragma unroll
        for (int i = 0; i < 4; i++) {
            int idx = tid + i * 256;
            int r = idx >> 3, c = idx & 7;
            uint4 v = *(const uint4*)(g_Attn + (size_t)(m0 + r) * DIM_ + k0 + c * 8);
            *(uint4*)&As[r * 36 + c * 4] = v;
            uint4 w = *(const uint4*)(WT + (size_t)(n0 + r) * DIM_ + k0 + c * 8);
            *(uint4*)&Bs[r * 36 + c * 4] = w;
        }
        __syncthreads();

        #pragma unroll
        for (int kk = 0; kk < 4; kk++) {
            uint32_t a0[4], a1[4];
            ldsm4(a0[0], a0[1], a0[2], a0[3], sA + (uint32_t)(wm * 36 * 4 + kk * 32));
            ldsm4(a1[0], a1[1], a1[2], a1[3], sA + (uint32_t)((wm + 16) * 36 * 4 + kk * 32));
            #pragma unroll
            for (int jp = 0; jp < 4; jp++) {
                uint32_t b0, b1, b2, b3;
                ldsm4(b0, b1, b2, b3, sB + (uint32_t)((wn + jp * 16) * 36 * 4 + kk * 32));
                mma16(acc[0][2 * jp],     a0, b0, b2);
                mma16(acc[0][2 * jp + 1], a0, b1, b3);
                mma16(acc[1][2 * jp],     a1, b0, b2);
                mma16(acc[1][2 * jp + 1], a1, b1, b3);
            }
        }
    }

    #pragma unroll
    for (int mt = 0; mt < 2; mt++) {
        int rA = m0 + wm + mt * 16 + g;
        #pragma unroll
        for (int half = 0; half < 2; half++) {
            int r = rA + half * 8;
            int b, n;
            if (r < GCTX_) { b = r / CTX_; n = r - b * CTX_; }
            else { int q = r - GCTX_; b = q >> 5; n = CTX_ + (q & 31); }
            float* orow = out + (size_t)(b * N_ + n) * DIM_;
            #pragma unroll
            for (int jf = 0; jf < 8; jf++) {
                int col = n0 + wn + jf * 8 + 2 * t;
                float vx = half ? acc[mt][jf].z : acc[mt][jf].x;
                float vy = half ? acc[mt][jf].w : acc[mt][jf].y;
                *(float2*)(orow + col) = make_float2(vx + bias[col], vy + bias[col + 1]);
            }
        }
    }
}

// ---------------- launch -----------------------------------------------------
extern "C" void kernel_launch(void* const* d_in, const int* in_sizes, int n_in,
                              void* d_out, int out_size) {
    const float* x      = (const float*)d_in[0];
    const float* Wq     = (const float*)d_in[1];
    const float* Wkv    = (const float*)d_in[2];
    const float* Wo_ctx = (const float*)d_in[3];
    const float* bo_ctx = (const float*)d_in[4];
    const float* Wo_lat = (const float*)d_in[5];
    const float* bo_lat = (const float*)d_in[6];
    const float* ln_g   = (const float*)d_in[7];
    const float* ln_b   = (const float*)d_in[8];
    float* out = (float*)d_out;

    dim3 tw(24, 24, 1);
    transpose_w<<<tw, 256>>>(Wq, 0);
    transpose_w<<<tw, 256>>>(Wkv, 1);
    transpose_w<<<tw, 256>>>(Wo_ctx, 2);
    transpose_w<<<tw, 256>>>(Wo_lat, 3);

    proj_kernel<0><<<dim3(64, 12), 256>>>(x, nullptr, nullptr);
    proj_kernel<1><<<dim3(64, 12), 256>>>(x, ln_g, ln_b);

    attn_kernel<<<dim3(96, 8), 256>>>();
    out_kernel<<<dim3(64, 6), 256>>>(bo_ctx, bo_lat, out);
}

// round 8
// speedup vs baseline: 5.3057x; 1.2942x over previous
#include <cuda_runtime.h>
#include <cuda_fp16.h>
#include <math.h>
#include <stdint.h>

#define B_    8
#define N_    1024
#define DIM_  768
#define H_    12
#define DH_   64
#define CTX_  992
#define BH_   96
#define ROWS_ 8192
#define GCTX_ 7936   // 8*992 grouped ctx rows

// ---------------- scratch (all fp16, 16B aligned) ----------------------------
__device__ __align__(16) __half g_Xh  [ROWS_ * DIM_];
__device__ __align__(16) __half g_Qh  [BH_ * N_ * DH_];
__device__ __align__(16) __half g_KVh [BH_ * N_ * DH_];
__device__ __align__(16) __half g_LKVh[BH_ * N_ * DH_];
__device__ __align__(16) __half g_Attn[ROWS_ * DIM_];   // grouped rows
__device__ __align__(16) __half g_WqT [DIM_ * DIM_];
__device__ __align__(16) __half g_WkvT[DIM_ * DIM_];
__device__ __align__(16) __half g_WocT[DIM_ * DIM_];
__device__ __align__(16) __half g_WolT[DIM_ * DIM_];

// ---------------- helpers ----------------------------------------------------
__device__ __forceinline__ uint32_t f2h2(float a, float b) {
    __half2 h = __floats2half2_rn(a, b);
    return *reinterpret_cast<uint32_t*>(&h);
}
__device__ __forceinline__ void mma16(float4& c, const uint32_t* a, uint32_t b0, uint32_t b1) {
    asm volatile(
        "mma.sync.aligned.m16n8k16.row.col.f32.f16.f16.f32 "
        "{%0,%1,%2,%3}, {%4,%5,%6,%7}, {%8,%9}, {%0,%1,%2,%3};\n"
        : "+f"(c.x), "+f"(c.y), "+f"(c.z), "+f"(c.w)
        : "r"(a[0]), "r"(a[1]), "r"(a[2]), "r"(a[3]), "r"(b0), "r"(b1));
}
__device__ __forceinline__ void ldsm4(uint32_t& r0, uint32_t& r1, uint32_t& r2,
                                      uint32_t& r3, uint32_t addr) {
    asm volatile("ldmatrix.sync.aligned.m8n8.x4.shared.b16 {%0,%1,%2,%3}, [%4];"
                 : "=r"(r0), "=r"(r1), "=r"(r2), "=r"(r3) : "r"(addr));
}
__device__ __forceinline__ void ldsm4t(uint32_t& r0, uint32_t& r1, uint32_t& r2,
                                       uint32_t& r3, uint32_t addr) {
    asm volatile("ldmatrix.sync.aligned.m8n8.x4.trans.shared.b16 {%0,%1,%2,%3}, [%4];"
                 : "=r"(r0), "=r"(r1), "=r"(r2), "=r"(r3) : "r"(addr));
}
__device__ __forceinline__ uint32_t lane_off16(int lane, int S) {
    int lr = (lane & 7) + ((lane >> 3) & 1) * 8;
    return (uint32_t)(lr * S * 4 + (lane >> 4) * 16);
}
__device__ __forceinline__ uint32_t lane_off16t(int lane, int S) {
    int lr = (lane & 7) + ((lane >> 4) & 1) * 8;
    return (uint32_t)(lr * S * 4 + ((lane >> 3) & 1) * 16);
}
__device__ __forceinline__ void cpa16(uint32_t dst, const void* src) {
    asm volatile("cp.async.ca.shared.global [%0], [%1], 16;" :: "r"(dst), "l"(src));
}
__device__ __forceinline__ void cp_commit() {
    asm volatile("cp.async.commit_group;");
}
template<int N>
__device__ __forceinline__ void cp_wait() {
    asm volatile("cp.async.wait_group %0;" :: "n"(N));
}

// ---------------- x -> fp16 ---------------------------------------------------
__global__ __launch_bounds__(256) void cvt_x(const float* __restrict__ x) {
    int idx = blockIdx.x * 256 + threadIdx.x;           // 8 floats per thread
    const float4* p = (const float4*)x + (size_t)idx * 2;
    float4 a = p[0], b = p[1];
    *(uint4*)(g_Xh + (size_t)idx * 8) =
        make_uint4(f2h2(a.x, a.y), f2h2(a.z, a.w), f2h2(b.x, b.y), f2h2(b.z, b.w));
}

// ---------------- fused weight transpose (grid.z selects matrix) -------------
__global__ __launch_bounds__(256) void transpose_w(const float* __restrict__ s0,
                                                   const float* __restrict__ s1,
                                                   const float* __restrict__ s2,
                                                   const float* __restrict__ s3) {
    __shared__ float tile[32][33];
    const float* src;
    __half* dst;
    switch (blockIdx.z) {
        case 0: src = s0; dst = g_WqT;  break;
        case 1: src = s1; dst = g_WkvT; break;
        case 2: src = s2; dst = g_WocT; break;
        default: src = s3; dst = g_WolT; break;
    }
    int c0 = blockIdx.x * 32, r0 = blockIdx.y * 32;
    int tx = threadIdx.x & 31, ty = threadIdx.x >> 5;
    #pragma unroll
    for (int i = 0; i < 4; i++)
        tile[ty + i * 8][tx] = src[(size_t)(r0 + ty + i * 8) * DIM_ + c0 + tx];
    __syncthreads();
    #pragma unroll
    for (int i = 0; i < 4; i++)
        dst[(size_t)(c0 + ty + i * 8) * DIM_ + r0 + tx] = __float2half(tile[tx][ty + i * 8]);
}

// ---------------- fused Q+KV projection, cp.async double-buffered ------------
// block 128 rows x one 64-wide head; 8 warps x 16 rows.
// dyn smem u32: A[2]@0/4608, BQ[2]@9216/11520, BK[2]@13824/16128 -> 18432 u32.
__global__ __launch_bounds__(256) void proj_kernel(const float* __restrict__ lng,
                                                   const float* __restrict__ lnb) {
    extern __shared__ uint32_t dsm[];
    const int m0 = blockIdx.x * 128;
    const int head = blockIdx.y;
    const int n0 = head * 64;
    const int tid = threadIdx.x;
    const int lane = tid & 31, wid = tid >> 5;
    const int g = lane >> 2, t = lane & 3;
    const uint32_t sbase = (uint32_t)__cvta_generic_to_shared(dsm);

    auto stage = [&](int bi, int k0) {
        uint32_t aoff = sbase + (uint32_t)(bi * 4608) * 4;
        #pragma unroll
        for (int i = 0; i < 4; i++) {
            int idx = tid + i * 256;
            int r = idx >> 3, c = idx & 7;
            cpa16(aoff + (uint32_t)(r * 36 + c * 4) * 4,
                  g_Xh + (size_t)(m0 + r) * DIM_ + k0 + c * 8);
        }
        uint32_t bqo = sbase + (uint32_t)(9216 + bi * 2304) * 4;
        uint32_t bko = sbase + (uint32_t)(13824 + bi * 2304) * 4;
        #pragma unroll
        for (int i = 0; i < 2; i++) {
            int idx = tid + i * 256;
            int r = idx >> 3, c = idx & 7;
            cpa16(bqo + (uint32_t)(r * 36 + c * 4) * 4,
                  g_WqT + (size_t)(n0 + r) * DIM_ + k0 + c * 8);
            cpa16(bko + (uint32_t)(r * 36 + c * 4) * 4,
                  g_WkvT + (size_t)(n0 + r) * DIM_ + k0 + c * 8);
        }
    };

    float4 accQ[8], accKV[8];
    #pragma unroll
    for (int j = 0; j < 8; j++) {
        accQ[j] = make_float4(0.f, 0.f, 0.f, 0.f);
        accKV[j] = make_float4(0.f, 0.f, 0.f, 0.f);
    }

    stage(0, 0);
    cp_commit();

    for (int kt = 0; kt < 12; kt++) {
        int bi = kt & 1;
        if (kt < 11) { stage(bi ^ 1, (kt + 1) * 64); cp_commit(); cp_wait<1>(); }
        else cp_wait<0>();
        __syncthreads();

        uint32_t lA = sbase + (uint32_t)(bi * 4608) * 4 + lane_off16(lane, 36);
        uint32_t lQ = sbase + (uint32_t)(9216 + bi * 2304) * 4 + lane_off16(lane, 36);
        uint32_t lK = sbase + (uint32_t)(13824 + bi * 2304) * 4 + lane_off16(lane, 36);
        #pragma unroll
        for (int kk = 0; kk < 4; kk++) {
            uint32_t a[4];
            ldsm4(a[0], a[1], a[2], a[3], lA + (uint32_t)((wid * 16) * 36 * 4 + kk * 32));
            #pragma unroll
            for (int jp = 0; jp < 4; jp++) {
                uint32_t b0, b1, b2, b3;
                ldsm4(b0, b1, b2, b3, lQ + (uint32_t)((jp * 16) * 36 * 4 + kk * 32));
                mma16(accQ[2 * jp],     a, b0, b2);
                mma16(accQ[2 * jp + 1], a, b1, b3);
                ldsm4(b0, b1, b2, b3, lK + (uint32_t)((jp * 16) * 36 * 4 + kk * 32));
                mma16(accKV[2 * jp],     a, b0, b2);
                mma16(accKV[2 * jp + 1], a, b1, b3);
            }
        }
        __syncthreads();
    }

    const int rA = m0 + wid * 16 + g;
    const int bb = rA >> 10;
    const int nA = rA & 1023;
    size_t oA = ((size_t)(bb * H_ + head) * N_ + nA) * DH_ + 2 * t;
    size_t oB = oA + 8 * DH_;
    float invf[4], snc[4][2][2];   // [jl][c-half?]... compute inline instead
    // ---- Q epilogue ----
    {
        float lo[4][4], hi[4][4];
        #pragma unroll
        for (int jl = 0; jl < 4; jl++)
            #pragma unroll
            for (int c = 0; c < 4; c++) {
                float v1 = ((const float*)&accQ[jl])[c];
                float v2 = ((const float*)&accQ[jl + 4])[c];
                int d = jl * 8 + 2 * t + (c & 1);
                int n = nA + (c >> 1) * 8;
                float inv = exp2f(-(float)d * 0.41524101186092034f);
                float sn, cs;
                sincosf((float)n * inv, &sn, &cs);
                lo[jl][c] = v1 * cs - v2 * sn;
                hi[jl][c] = v2 * cs + v1 * sn;
            }
        #pragma unroll
        for (int jl = 0; jl < 4; jl++) {
            *(uint32_t*)(g_Qh + oA + jl * 8)      = f2h2(lo[jl][0] * 0.125f, lo[jl][1] * 0.125f);
            *(uint32_t*)(g_Qh + oA + jl * 8 + 32) = f2h2(hi[jl][0] * 0.125f, hi[jl][1] * 0.125f);
            *(uint32_t*)(g_Qh + oB + jl * 8)      = f2h2(lo[jl][2] * 0.125f, lo[jl][3] * 0.125f);
            *(uint32_t*)(g_Qh + oB + jl * 8 + 32) = f2h2(hi[jl][2] * 0.125f, hi[jl][3] * 0.125f);
        }
    }
    // ---- KV epilogue (RoPE + LN) ----
    {
        float lo[4][4], hi[4][4];
        #pragma unroll
        for (int jl = 0; jl < 4; jl++)
            #pragma unroll
            for (int c = 0; c < 4; c++) {
                float v1 = ((const float*)&accKV[jl])[c];
                float v2 = ((const float*)&accKV[jl + 4])[c];
                int d = jl * 8 + 2 * t + (c & 1);
                int n = nA + (c >> 1) * 8;
                float inv = exp2f(-(float)d * 0.41524101186092034f);
                float sn, cs;
                sincosf((float)n * inv, &sn, &cs);
                lo[jl][c] = v1 * cs - v2 * sn;
                hi[jl][c] = v2 * cs + v1 * sn;
            }
        #pragma unroll
        for (int jl = 0; jl < 4; jl++) {
            *(uint32_t*)(g_KVh + oA + jl * 8)      = f2h2(lo[jl][0], lo[jl][1]);
            *(uint32_t*)(g_KVh + oA + jl * 8 + 32) = f2h2(hi[jl][0], hi[jl][1]);
            *(uint32_t*)(g_KVh + oB + jl * 8)      = f2h2(lo[jl][2], lo[jl][3]);
            *(uint32_t*)(g_KVh + oB + jl * 8 + 32) = f2h2(hi[jl][2], hi[jl][3]);
        }
        float sumA = 0.f, sumB = 0.f;
        #pragma unroll
        for (int jl = 0; jl < 4; jl++) {
            sumA += lo[jl][0] + lo[jl][1] + hi[jl][0] + hi[jl][1];
            sumB += lo[jl][2] + lo[jl][3] + hi[jl][2] + hi[jl][3];
        }
        sumA += __shfl_xor_sync(0xffffffffu, sumA, 1);
        sumA += __shfl_xor_sync(0xffffffffu, sumA, 2);
        sumB += __shfl_xor_sync(0xffffffffu, sumB, 1);
        sumB += __shfl_xor_sync(0xffffffffu, sumB, 2);
        float mA = sumA * (1.f / 64.f), mB = sumB * (1.f / 64.f);
        float vA = 0.f, vB = 0.f;
        #pragma unroll
        for (int jl = 0; jl < 4; jl++)
            #pragma unroll
            for (int c = 0; c < 2; c++) {
                float d1 = lo[jl][c] - mA, d2 = hi[jl][c] - mA;
                vA += d1 * d1 + d2 * d2;
                float d3 = lo[jl][c + 2] - mB, d4 = hi[jl][c + 2] - mB;
                vB += d3 * d3 + d4 * d4;
            }
        vA += __shfl_xor_sync(0xffffffffu, vA, 1);
        vA += __shfl_xor_sync(0xffffffffu, vA, 2);
        vB += __shfl_xor_sync(0xffffffffu, vB, 1);
        vB += __shfl_xor_sync(0xffffffffu, vB, 2);
        float iA = rsqrtf(vA * (1.f / 64.f) + 1e-5f);
        float iB = rsqrtf(vB * (1.f / 64.f) + 1e-5f);
        #pragma unroll
        for (int jl = 0; jl < 4; jl++) {
            int d = jl * 8 + 2 * t;
            float g0 = lng[d], g1 = lng[d + 1], b0 = lnb[d], b1 = lnb[d + 1];
            float g2 = lng[d + 32], g3 = lng[d + 33], b2 = lnb[d + 32], b3 = lnb[d + 33];
            *(uint32_t*)(g_LKVh + oA + jl * 8) = f2h2(
                (lo[jl][0] - mA) * iA * g0 + b0, (lo[jl][1] - mA) * iA * g1 + b1);
            *(uint32_t*)(g_LKVh + oA + jl * 8 + 32) = f2h2(
                (hi[jl][0] - mA) * iA * g2 + b2, (hi[jl][1] - mA) * iA * g3 + b3);
            *(uint32_t*)(g_LKVh + oB + jl * 8) = f2h2(
                (lo[jl][2] - mB) * iB * g0 + b0, (lo[jl][3] - mB) * iB * g1 + b1);
            *(uint32_t*)(g_LKVh + oB + jl * 8 + 32) = f2h2(
                (hi[jl][2] - mB) * iB * g2 + b2, (hi[jl][3] - mB) * iB * g3 + b3);
        }
    }
}

// ---------------- fused attention, cp.async double-buffered KV ---------------
// dyn smem u32: Q@0 (4608, reused as P), K[2]@4608/6912, V[2]@9216/11520 = 13824.
__global__ __launch_bounds__(256, 2) void attn_kernel() {
    extern __shared__ uint32_t dsm[];
    const int bh = blockIdx.x, qt = blockIdx.y;
    const int m0 = qt * 128;
    const int tid = threadIdx.x;
    const int lane = tid & 31, wid = tid >> 5;
    const int g = lane >> 2, t = lane & 3;
    const int wr = wid * 16;
    const uint32_t sbase = (uint32_t)__cvta_generic_to_shared(dsm);
    const uint32_t lbQ = sbase + lane_off16(lane, 36);

    auto stageKV = [&](int bi, int kt) {
        const __half* kb = g_KVh  + ((size_t)bh * N_ + kt * 64) * DH_;
        const __half* vb = g_LKVh + ((size_t)bh * N_ + kt * 64) * DH_;
        uint32_t ko = sbase + (uint32_t)(4608 + bi * 2304) * 4;
        uint32_t vo = sbase + (uint32_t)(9216 + bi * 2304) * 4;
        #pragma unroll
        for (int i = 0; i < 2; i++) {
            int idx = tid + i * 256;
            int r = idx >> 3, c = idx & 7;
            cpa16(ko + (uint32_t)(r * 36 + c * 4) * 4, kb + (size_t)r * DH_ + c * 8);
            cpa16(vo + (uint32_t)(r * 36 + c * 4) * 4, vb + (size_t)r * DH_ + c * 8);
        }
    };

    // stage Q + tile 0
    const __half* qsrc = g_Qh + ((size_t)bh * N_ + m0) * DH_;
    #pragma unroll
    for (int i = 0; i < 4; i++) {
        int idx = tid + i * 256;
        int r = idx >> 3, c = idx & 7;
        cpa16(sbase + (uint32_t)(r * 36 + c * 4) * 4, qsrc + (size_t)r * DH_ + c * 8);
    }
    stageKV(0, 0);
    cp_commit();
    cp_wait<0>();
    __syncthreads();

    uint32_t qa[4][4];
    #pragma unroll
    for (int kk = 0; kk < 4; kk++)
        ldsm4(qa[kk][0], qa[kk][1], qa[kk][2], qa[kk][3],
              lbQ + (uint32_t)(wr * 36 * 4 + kk * 32));
    __syncthreads();

    float4 o[8];
    #pragma unroll
    for (int j = 0; j < 8; j++) o[j] = make_float4(0.f, 0.f, 0.f, 0.f);
    float l0 = 0.f, l1 = 0.f;
    const int r0g = m0 + wr + g;
    const bool lat0 = (r0g >= CTX_);
    const bool lat1 = (r0g + 8 >= CTX_);

    for (int kt = 0; kt < 16; kt++) {
        int bi = kt & 1;
        if (kt < 15) { stageKV(bi ^ 1, kt + 1); cp_commit(); cp_wait<1>(); }
        else cp_wait<0>();
        __syncthreads();

        uint32_t lbK = sbase + (uint32_t)(4608 + bi * 2304) * 4 + lane_off16(lane, 36);
        uint32_t lbV = sbase + (uint32_t)(9216 + bi * 2304) * 4 + lane_off16t(lane, 36);

        float4 s[8];
        #pragma unroll
        for (int j = 0; j < 8; j++) s[j] = make_float4(0.f, 0.f, 0.f, 0.f);
        #pragma unroll
        for (int kk = 0; kk < 4; kk++) {
            #pragma unroll
            for (int jp = 0; jp < 4; jp++) {
                uint32_t b0, b1, b2, b3;
                ldsm4(b0, b1, b2, b3, lbK + (uint32_t)((jp * 16) * 36 * 4 + kk * 32));
                mma16(s[2 * jp],     qa[kk], b0, b2);
                mma16(s[2 * jp + 1], qa[kk], b1, b3);
            }
        }
        #pragma unroll
        for (int j = 0; j < 8; j++) {
            float px = __expf(s[j].x), py = __expf(s[j].y);
            float pz = __expf(s[j].z), pw = __expf(s[j].w);
            if (kt == 15 && j >= 4) {
                if (!lat0) { px = 0.f; py = 0.f; }
                if (!lat1) { pz = 0.f; pw = 0.f; }
            }
            l0 += px + py; l1 += pz + pw;
            dsm[(wr + g) * 36 + j * 4 + t]     = f2h2(px, py);
            dsm[(wr + g + 8) * 36 + j * 4 + t] = f2h2(pz, pw);
        }
        __syncwarp();
        #pragma unroll
        for (int kk = 0; kk < 4; kk++) {
            uint32_t pa[4];
            ldsm4(pa[0], pa[1], pa[2], pa[3], lbQ + (uint32_t)(wr * 36 * 4 + kk * 32));
            #pragma unroll
            for (int jp = 0; jp < 4; jp++) {
                uint32_t b0, b1, b2, b3;
                ldsm4t(b0, b1, b2, b3,
                       lbV + (uint32_t)((kk * 16) * 36 * 4 + (jp * 16) * 2));
                mma16(o[2 * jp],     pa, b0, b2);
                mma16(o[2 * jp + 1], pa, b1, b3);
            }
        }
        __syncthreads();
    }

    l0 += __shfl_xor_sync(0xffffffffu, l0, 1);
    l0 += __shfl_xor_sync(0xffffffffu, l0, 2);
    l1 += __shfl_xor_sync(0xffffffffu, l1, 1);
    l1 += __shfl_xor_sync(0xffffffffu, l1, 2);
    float i0 = 1.0f / l0, i1 = 1.0f / l1;

    const int bb = bh / H_, h = bh % H_;
    int gr0 = (r0g < CTX_) ? bb * CTX_ + r0g : GCTX_ + bb * 32 + (r0g - CTX_);
    int r1g = r0g + 8;
    int gr1 = (r1g < CTX_) ? bb * CTX_ + r1g : GCTX_ + bb * 32 + (r1g - CTX_);
    #pragma unroll
    for (int j = 0; j < 8; j++) {
        int col = h * 64 + j * 8 + 2 * t;
        *(uint32_t*)(g_Attn + (size_t)gr0 * DIM_ + col) = f2h2(o[j].x * i0, o[j].y * i0);
        *(uint32_t*)(g_Attn + (size_t)gr1 * DIM_ + col) = f2h2(o[j].z * i1, o[j].w * i1);
    }
}

// ---------------- output projection, cp.async double-buffered ----------------
// dyn smem u32: A[2]@0/4608, B[2]@9216/13824 -> 18432 u32 = 73728 B.
__global__ __launch_bounds__(256) void out_kernel(const float* __restrict__ bc,
                                                  const float* __restrict__ bl,
                                                  float* __restrict__ out) {
    extern __shared__ uint32_t dsm[];
    const int m0 = blockIdx.x * 128;
    const int n0 = blockIdx.y * 128;
    const bool ctx = (m0 < GCTX_);
    const __half* WT  = ctx ? g_WocT : g_WolT;
    const float* bias = ctx ? bc : bl;

    const int tid = threadIdx.x;
    const int lane = tid & 31, wid = tid >> 5;
    const int wm = (wid & 3) * 32;
    const int wn = (wid >> 2) * 64;
    const int g = lane >> 2, t = lane & 3;
    const uint32_t sbase = (uint32_t)__cvta_generic_to_shared(dsm);

    auto stage = [&](int bi, int k0) {
        uint32_t ao = sbase + (uint32_t)(bi * 4608) * 4;
        uint32_t bo = sbase + (uint32_t)(9216 + bi * 4608) * 4;
        #pragma unroll
        for (int i = 0; i < 4; i++) {
            int idx = tid + i * 256;
            int r = idx >> 3, c = idx & 7;
            cpa16(ao + (uint32_t)(r * 36 + c * 4) * 4,
                  g_Attn + (size_t)(m0 + r) * DIM_ + k0 + c * 8);
            cpa16(bo + (uint32_t)(r * 36 + c * 4) * 4,
                  WT + (size_t)(n0 + r) * DIM_ + k0 + c * 8);
        }
    };

    float4 acc[2][8];
    #pragma unroll
    for (int i = 0; i < 2; i++)
        #pragma unroll
        for (int j = 0; j < 8; j++) acc[i][j] = make_float4(0.f, 0.f, 0.f, 0.f);

    stage(0, 0);
    cp_commit();

    for (int kt = 0; kt < 12; kt++) {
        int bi = kt & 1;
        if (kt < 11) { stage(bi ^ 1, (kt + 1) * 64); cp_commit(); cp_wait<1>(); }
        else cp_wait<0>();
        __syncthreads();

        uint32_t sA = sbase + (uint32_t)(bi * 4608) * 4 + lane_off16(lane, 36);
        uint32_t sB = sbase + (uint32_t)(9216 + bi * 4608) * 4 + lane_off16(lane, 36);
        #pragma unroll
        for (int kk = 0; kk < 4; kk++) {
            uint32_t a0[4], a1[4];
            ldsm4(a0[0], a0[1], a0[2], a0[3], sA + (uint32_t)(wm * 36 * 4 + kk * 32));
            ldsm4(a1[0], a1[1], a1[2], a1[3], sA + (uint32_t)((wm + 16) * 36 * 4 + kk * 32));
            #pragma unroll
            for (int jp = 0; jp < 4; jp++) {
                uint32_t b0, b1, b2, b3;
                ldsm4(b0, b1, b2, b3, sB + (uint32_t)((wn + jp * 16) * 36 * 4 + kk * 32));
                mma16(acc[0][2 * jp],     a0, b0, b2);
                mma16(acc[0][2 * jp + 1], a0, b1, b3);
                mma16(acc[1][2 * jp],     a1, b0, b2);
                mma16(acc[1][2 * jp + 1], a1, b1, b3);
            }
        }
        __syncthreads();
    }

    #pragma unroll
    for (int mt = 0; mt < 2; mt++) {
        int rA = m0 + wm + mt * 16 + g;
        #pragma unroll
        for (int half = 0; half < 2; half++) {
            int r = rA + half * 8;
            int b, n;
            if (r < GCTX_) { b = r / CTX_; n = r - b * CTX_; }
            else { int q = r - GCTX_; b = q >> 5; n = CTX_ + (q & 31); }
            float* orow = out + (size_t)(b * N_ + n) * DIM_;
            #pragma unroll
            for (int jf = 0; jf < 8; jf++) {
                int col = n0 + wn + jf * 8 + 2 * t;
                float vx = half ? acc[mt][jf].z : acc[mt][jf].x;
                float vy = half ? acc[mt][jf].w : acc[mt][jf].y;
                *(float2*)(orow + col) = make_float2(vx + bias[col], vy + bias[col + 1]);
            }
        }
    }
}

// ---------------- launch -----------------------------------------------------
extern "C" void kernel_launch(void* const* d_in, const int* in_sizes, int n_in,
                              void* d_out, int out_size) {
    const float* x      = (const float*)d_in[0];
    const float* Wq     = (const float*)d_in[1];
    const float* Wkv    = (const float*)d_in[2];
    const float* Wo_ctx = (const float*)d_in[3];
    const float* bo_ctx = (const float*)d_in[4];
    const float* Wo_lat = (const float*)d_in[5];
    const float* bo_lat = (const float*)d_in[6];
    const float* ln_g   = (const float*)d_in[7];
    const float* ln_b   = (const float*)d_in[8];
    float* out = (float*)d_out;

    cudaFuncSetAttribute(proj_kernel, cudaFuncAttributeMaxDynamicSharedMemorySize, 73728);
    cudaFuncSetAttribute(attn_kernel, cudaFuncAttributeMaxDynamicSharedMemorySize, 55296);
    cudaFuncSetAttribute(out_kernel,  cudaFuncAttributeMaxDynamicSharedMemorySize, 73728);

    cvt_x<<<ROWS_ * DIM_ / (256 * 8), 256>>>(x);
    transpose_w<<<dim3(24, 24, 4), 256>>>(Wq, Wkv, Wo_ctx, Wo_lat);

    proj_kernel<<<dim3(64, 12), 256, 73728>>>(ln_g, ln_b);
    attn_kernel<<<dim3(96, 8), 256, 55296>>>();
    out_kernel<<<dim3(64, 6), 256, 73728>>>(bo_ctx, bo_lat, out);
}

// round 9
// speedup vs baseline: 5.4351x; 1.0244x over previous
#include <cuda_runtime.h>
#include <cuda_fp16.h>
#include <math.h>
#include <stdint.h>

#define B_    8
#define N_    1024
#define DIM_  768
#define H_    12
#define DH_   64
#define CTX_  992
#define BH_   96
#define ROWS_ 8192
#define GCTX_ 7936   // 8*992 grouped ctx rows

// ---------------- scratch (all fp16, 16B aligned) ----------------------------
__device__ __align__(16) __half g_Xh  [ROWS_ * DIM_];
__device__ __align__(16) __half g_Qh  [BH_ * N_ * DH_];
__device__ __align__(16) __half g_KVh [BH_ * N_ * DH_];
__device__ __align__(16) __half g_LKVh[BH_ * N_ * DH_];
__device__ __align__(16) __half g_Attn[ROWS_ * DIM_];   // grouped rows
__device__ __align__(16) __half g_WqT [DIM_ * DIM_];
__device__ __align__(16) __half g_WkvT[DIM_ * DIM_];
__device__ __align__(16) __half g_WocT[DIM_ * DIM_];
__device__ __align__(16) __half g_WolT[DIM_ * DIM_];

// ---------------- helpers ----------------------------------------------------
__device__ __forceinline__ uint32_t f2h2(float a, float b) {
    __half2 h = __floats2half2_rn(a, b);
    return *reinterpret_cast<uint32_t*>(&h);
}
__device__ __forceinline__ void mma16(float4& c, const uint32_t* a, uint32_t b0, uint32_t b1) {
    asm volatile(
        "mma.sync.aligned.m16n8k16.row.col.f32.f16.f16.f32 "
        "{%0,%1,%2,%3}, {%4,%5,%6,%7}, {%8,%9}, {%0,%1,%2,%3};\n"
        : "+f"(c.x), "+f"(c.y), "+f"(c.z), "+f"(c.w)
        : "r"(a[0]), "r"(a[1]), "r"(a[2]), "r"(a[3]), "r"(b0), "r"(b1));
}
__device__ __forceinline__ void ldsm4(uint32_t& r0, uint32_t& r1, uint32_t& r2,
                                      uint32_t& r3, uint32_t addr) {
    asm volatile("ldmatrix.sync.aligned.m8n8.x4.shared.b16 {%0,%1,%2,%3}, [%4];"
                 : "=r"(r0), "=r"(r1), "=r"(r2), "=r"(r3) : "r"(addr));
}
__device__ __forceinline__ void ldsm4t(uint32_t& r0, uint32_t& r1, uint32_t& r2,
                                       uint32_t& r3, uint32_t addr) {
    asm volatile("ldmatrix.sync.aligned.m8n8.x4.trans.shared.b16 {%0,%1,%2,%3}, [%4];"
                 : "=r"(r0), "=r"(r1), "=r"(r2), "=r"(r3) : "r"(addr));
}
__device__ __forceinline__ uint32_t lane_off16(int lane, int S) {
    int lr = (lane & 7) + ((lane >> 3) & 1) * 8;
    return (uint32_t)(lr * S * 4 + (lane >> 4) * 16);
}
__device__ __forceinline__ uint32_t lane_off16t(int lane, int S) {
    int lr = (lane & 7) + ((lane >> 4) & 1) * 8;
    return (uint32_t)(lr * S * 4 + ((lane >> 3) & 1) * 16);
}
__device__ __forceinline__ void cpa16(uint32_t dst, const void* src) {
    asm volatile("cp.async.ca.shared.global [%0], [%1], 16;" :: "r"(dst), "l"(src));
}
__device__ __forceinline__ void cp_commit() {
    asm volatile("cp.async.commit_group;");
}
template<int N>
__device__ __forceinline__ void cp_wait() {
    asm volatile("cp.async.wait_group %0;" :: "n"(N));
}

// ---------------- x -> fp16 ---------------------------------------------------
__global__ __launch_bounds__(256) void cvt_x(const float* __restrict__ x) {
    int idx = blockIdx.x * 256 + threadIdx.x;           // 8 floats per thread
    const float4* p = (const float4*)x + (size_t)idx * 2;
    float4 a = p[0], b = p[1];
    *(uint4*)(g_Xh + (size_t)idx * 8) =
        make_uint4(f2h2(a.x, a.y), f2h2(a.z, a.w), f2h2(b.x, b.y), f2h2(b.z, b.w));
}

// ---------------- fused weight transpose (grid.z selects matrix) -------------
__global__ __launch_bounds__(256) void transpose_w(const float* __restrict__ s0,
                                                   const float* __restrict__ s1,
                                                   const float* __restrict__ s2,
                                                   const float* __restrict__ s3) {
    __shared__ float tile[32][33];
    const float* src;
    __half* dst;
    switch (blockIdx.z) {
        case 0: src = s0; dst = g_WqT;  break;
        case 1: src = s1; dst = g_WkvT; break;
        case 2: src = s2; dst = g_WocT; break;
        default: src = s3; dst = g_WolT; break;
    }
    int c0 = blockIdx.x * 32, r0 = blockIdx.y * 32;
    int tx = threadIdx.x & 31, ty = threadIdx.x >> 5;
    #pragma unroll
    for (int i = 0; i < 4; i++)
        tile[ty + i * 8][tx] = src[(size_t)(r0 + ty + i * 8) * DIM_ + c0 + tx];
    __syncthreads();
    #pragma unroll
    for (int i = 0; i < 4; i++)
        dst[(size_t)(c0 + ty + i * 8) * DIM_ + r0 + tx] = __float2half(tile[tx][ty + i * 8]);
}

// ---------------- fused Q+KV projection, cp.async double-buffered ------------
__global__ __launch_bounds__(256) void proj_kernel(const float* __restrict__ lng,
                                                   const float* __restrict__ lnb) {
    extern __shared__ uint32_t dsm[];
    const int m0 = blockIdx.x * 128;
    const int head = blockIdx.y;
    const int n0 = head * 64;
    const int tid = threadIdx.x;
    const int lane = tid & 31, wid = tid >> 5;
    const int g = lane >> 2, t = lane & 3;
    const uint32_t sbase = (uint32_t)__cvta_generic_to_shared(dsm);

    auto stage = [&](int bi, int k0) {
        uint32_t aoff = sbase + (uint32_t)(bi * 4608) * 4;
        #pragma unroll
        for (int i = 0; i < 4; i++) {
            int idx = tid + i * 256;
            int r = idx >> 3, c = idx & 7;
            cpa16(aoff + (uint32_t)(r * 36 + c * 4) * 4,
                  g_Xh + (size_t)(m0 + r) * DIM_ + k0 + c * 8);
        }
        uint32_t bqo = sbase + (uint32_t)(9216 + bi * 2304) * 4;
        uint32_t bko = sbase + (uint32_t)(13824 + bi * 2304) * 4;
        #pragma unroll
        for (int i = 0; i < 2; i++) {
            int idx = tid + i * 256;
            int r = idx >> 3, c = idx & 7;
            cpa16(bqo + (uint32_t)(r * 36 + c * 4) * 4,
                  g_WqT + (size_t)(n0 + r) * DIM_ + k0 + c * 8);
            cpa16(bko + (uint32_t)(r * 36 + c * 4) * 4,
                  g_WkvT + (size_t)(n0 + r) * DIM_ + k0 + c * 8);
        }
    };

    float4 accQ[8], accKV[8];
    #pragma unroll
    for (int j = 0; j < 8; j++) {
        accQ[j] = make_float4(0.f, 0.f, 0.f, 0.f);
        accKV[j] = make_float4(0.f, 0.f, 0.f, 0.f);
    }

    stage(0, 0);
    cp_commit();

    for (int kt = 0; kt < 12; kt++) {
        int bi = kt & 1;
        if (kt < 11) { stage(bi ^ 1, (kt + 1) * 64); cp_commit(); cp_wait<1>(); }
        else cp_wait<0>();
        __syncthreads();

        uint32_t lA = sbase + (uint32_t)(bi * 4608) * 4 + lane_off16(lane, 36);
        uint32_t lQ = sbase + (uint32_t)(9216 + bi * 2304) * 4 + lane_off16(lane, 36);
        uint32_t lK = sbase + (uint32_t)(13824 + bi * 2304) * 4 + lane_off16(lane, 36);
        #pragma unroll
        for (int kk = 0; kk < 4; kk++) {
            uint32_t a[4];
            ldsm4(a[0], a[1], a[2], a[3], lA + (uint32_t)((wid * 16) * 36 * 4 + kk * 32));
            #pragma unroll
            for (int jp = 0; jp < 4; jp++) {
                uint32_t b0, b1, b2, b3;
                ldsm4(b0, b1, b2, b3, lQ + (uint32_t)((jp * 16) * 36 * 4 + kk * 32));
                mma16(accQ[2 * jp],     a, b0, b2);
                mma16(accQ[2 * jp + 1], a, b1, b3);
                ldsm4(b0, b1, b2, b3, lK + (uint32_t)((jp * 16) * 36 * 4 + kk * 32));
                mma16(accKV[2 * jp],     a, b0, b2);
                mma16(accKV[2 * jp + 1], a, b1, b3);
            }
        }
        __syncthreads();
    }

    const int rA = m0 + wid * 16 + g;
    const int bb = rA >> 10;
    const int nA = rA & 1023;
    size_t oA = ((size_t)(bb * H_ + head) * N_ + nA) * DH_ + 2 * t;
    size_t oB = oA + 8 * DH_;
    // ---- Q epilogue ----
    {
        float lo[4][4], hi[4][4];
        #pragma unroll
        for (int jl = 0; jl < 4; jl++)
            #pragma unroll
            for (int c = 0; c < 4; c++) {
                float v1 = ((const float*)&accQ[jl])[c];
                float v2 = ((const float*)&accQ[jl + 4])[c];
                int d = jl * 8 + 2 * t + (c & 1);
                int n = nA + (c >> 1) * 8;
                float inv = exp2f(-(float)d * 0.41524101186092034f);
                float sn, cs;
                sincosf((float)n * inv, &sn, &cs);
                lo[jl][c] = v1 * cs - v2 * sn;
                hi[jl][c] = v2 * cs + v1 * sn;
            }
        #pragma unroll
        for (int jl = 0; jl < 4; jl++) {
            *(uint32_t*)(g_Qh + oA + jl * 8)      = f2h2(lo[jl][0] * 0.125f, lo[jl][1] * 0.125f);
            *(uint32_t*)(g_Qh + oA + jl * 8 + 32) = f2h2(hi[jl][0] * 0.125f, hi[jl][1] * 0.125f);
            *(uint32_t*)(g_Qh + oB + jl * 8)      = f2h2(lo[jl][2] * 0.125f, lo[jl][3] * 0.125f);
            *(uint32_t*)(g_Qh + oB + jl * 8 + 32) = f2h2(hi[jl][2] * 0.125f, hi[jl][3] * 0.125f);
        }
    }
    // ---- KV epilogue (RoPE + LN) ----
    {
        float lo[4][4], hi[4][4];
        #pragma unroll
        for (int jl = 0; jl < 4; jl++)
            #pragma unroll
            for (int c = 0; c < 4; c++) {
                float v1 = ((const float*)&accKV[jl])[c];
                float v2 = ((const float*)&accKV[jl + 4])[c];
                int d = jl * 8 + 2 * t + (c & 1);
                int n = nA + (c >> 1) * 8;
                float inv = exp2f(-(float)d * 0.41524101186092034f);
                float sn, cs;
                sincosf((float)n * inv, &sn, &cs);
                lo[jl][c] = v1 * cs - v2 * sn;
                hi[jl][c] = v2 * cs + v1 * sn;
            }
        #pragma unroll
        for (int jl = 0; jl < 4; jl++) {
            *(uint32_t*)(g_KVh + oA + jl * 8)      = f2h2(lo[jl][0], lo[jl][1]);
            *(uint32_t*)(g_KVh + oA + jl * 8 + 32) = f2h2(hi[jl][0], hi[jl][1]);
            *(uint32_t*)(g_KVh + oB + jl * 8)      = f2h2(lo[jl][2], lo[jl][3]);
            *(uint32_t*)(g_KVh + oB + jl * 8 + 32) = f2h2(hi[jl][2], hi[jl][3]);
        }
        float sumA = 0.f, sumB = 0.f;
        #pragma unroll
        for (int jl = 0; jl < 4; jl++) {
            sumA += lo[jl][0] + lo[jl][1] + hi[jl][0] + hi[jl][1];
            sumB += lo[jl][2] + lo[jl][3] + hi[jl][2] + hi[jl][3];
        }
        sumA += __shfl_xor_sync(0xffffffffu, sumA, 1);
        sumA += __shfl_xor_sync(0xffffffffu, sumA, 2);
        sumB += __shfl_xor_sync(0xffffffffu, sumB, 1);
        sumB += __shfl_xor_sync(0xffffffffu, sumB, 2);
        float mA = sumA * (1.f / 64.f), mB = sumB * (1.f / 64.f);
        float vA = 0.f, vB = 0.f;
        #pragma unroll
        for (int jl = 0; jl < 4; jl++)
            #pragma unroll
            for (int c = 0; c < 2; c++) {
                float d1 = lo[jl][c] - mA, d2 = hi[jl][c] - mA;
                vA += d1 * d1 + d2 * d2;
                float d3 = lo[jl][c + 2] - mB, d4 = hi[jl][c + 2] - mB;
                vB += d3 * d3 + d4 * d4;
            }
        vA += __shfl_xor_sync(0xffffffffu, vA, 1);
        vA += __shfl_xor_sync(0xffffffffu, vA, 2);
        vB += __shfl_xor_sync(0xffffffffu, vB, 1);
        vB += __shfl_xor_sync(0xffffffffu, vB, 2);
        float iA = rsqrtf(vA * (1.f / 64.f) + 1e-5f);
        float iB = rsqrtf(vB * (1.f / 64.f) + 1e-5f);
        #pragma unroll
        for (int jl = 0; jl < 4; jl++) {
            int d = jl * 8 + 2 * t;
            float g0 = lng[d], g1 = lng[d + 1], b0 = lnb[d], b1 = lnb[d + 1];
            float g2 = lng[d + 32], g3 = lng[d + 33], b2 = lnb[d + 32], b3 = lnb[d + 33];
            *(uint32_t*)(g_LKVh + oA + jl * 8) = f2h2(
                (lo[jl][0] - mA) * iA * g0 + b0, (lo[jl][1] - mA) * iA * g1 + b1);
            *(uint32_t*)(g_LKVh + oA + jl * 8 + 32) = f2h2(
                (hi[jl][0] - mA) * iA * g2 + b2, (hi[jl][1] - mA) * iA * g3 + b3);
            *(uint32_t*)(g_LKVh + oB + jl * 8) = f2h2(
                (lo[jl][2] - mB) * iB * g0 + b0, (lo[jl][3] - mB) * iB * g1 + b1);
            *(uint32_t*)(g_LKVh + oB + jl * 8 + 32) = f2h2(
                (hi[jl][2] - mB) * iB * g2 + b2, (hi[jl][3] - mB) * iB * g3 + b3);
        }
    }
}

// ---------------- fused attention, register-resident P -----------------------
// dyn smem u32: Q@0 (4608), K[2]@4608/6912, V[2]@9216/11520 = 13824 u32.
__global__ __launch_bounds__(256, 2) void attn_kernel() {
    extern __shared__ uint32_t dsm[];
    const int bh = blockIdx.x, qt = blockIdx.y;
    const int m0 = qt * 128;
    const int tid = threadIdx.x;
    const int lane = tid & 31, wid = tid >> 5;
    const int g = lane >> 2, t = lane & 3;
    const int wr = wid * 16;
    const uint32_t sbase = (uint32_t)__cvta_generic_to_shared(dsm);
    const uint32_t lbQ = sbase + lane_off16(lane, 36);

    auto stageKV = [&](int bi, int kt) {
        const __half* kb = g_KVh  + ((size_t)bh * N_ + kt * 64) * DH_;
        const __half* vb = g_LKVh + ((size_t)bh * N_ + kt * 64) * DH_;
        uint32_t ko = sbase + (uint32_t)(4608 + bi * 2304) * 4;
        uint32_t vo = sbase + (uint32_t)(9216 + bi * 2304) * 4;
        #pragma unroll
        for (int i = 0; i < 2; i++) {
            int idx = tid + i * 256;
            int r = idx >> 3, c = idx & 7;
            cpa16(ko + (uint32_t)(r * 36 + c * 4) * 4, kb + (size_t)r * DH_ + c * 8);
            cpa16(vo + (uint32_t)(r * 36 + c * 4) * 4, vb + (size_t)r * DH_ + c * 8);
        }
    };

    // stage Q + tile 0
    const __half* qsrc = g_Qh + ((size_t)bh * N_ + m0) * DH_;
    #pragma unroll
    for (int i = 0; i < 4; i++) {
        int idx = tid + i * 256;
        int r = idx >> 3, c = idx & 7;
        cpa16(sbase + (uint32_t)(r * 36 + c * 4) * 4, qsrc + (size_t)r * DH_ + c * 8);
    }
    stageKV(0, 0);
    cp_commit();
    cp_wait<0>();
    __syncthreads();

    uint32_t qa[4][4];
    #pragma unroll
    for (int kk = 0; kk < 4; kk++)
        ldsm4(qa[kk][0], qa[kk][1], qa[kk][2], qa[kk][3],
              lbQ + (uint32_t)(wr * 36 * 4 + kk * 32));

    float4 o[8];
    #pragma unroll
    for (int j = 0; j < 8; j++) o[j] = make_float4(0.f, 0.f, 0.f, 0.f);
    float l0 = 0.f, l1 = 0.f;
    const int r0g = m0 + wr + g;
    const bool lat0 = (r0g >= CTX_);
    const bool lat1 = (r0g + 8 >= CTX_);

    for (int kt = 0; kt < 16; kt++) {
        int bi = kt & 1;
        if (kt < 15) { stageKV(bi ^ 1, kt + 1); cp_commit(); cp_wait<1>(); }
        else cp_wait<0>();
        __syncthreads();

        uint32_t lbK = sbase + (uint32_t)(4608 + bi * 2304) * 4 + lane_off16(lane, 36);
        uint32_t lbV = sbase + (uint32_t)(9216 + bi * 2304) * 4 + lane_off16t(lane, 36);

        // S = Q K^T
        float4 s[8];
        #pragma unroll
        for (int j = 0; j < 8; j++) s[j] = make_float4(0.f, 0.f, 0.f, 0.f);
        #pragma unroll
        for (int kk = 0; kk < 4; kk++) {
            #pragma unroll
            for (int jp = 0; jp < 4; jp++) {
                uint32_t b0, b1, b2, b3;
                ldsm4(b0, b1, b2, b3, lbK + (uint32_t)((jp * 16) * 36 * 4 + kk * 32));
                mma16(s[2 * jp],     qa[kk], b0, b2);
                mma16(s[2 * jp + 1], qa[kk], b1, b3);
            }
        }
        // exp -> register-resident P fragments (S accum layout == A frag layout)
        uint32_t ph[16];
        #pragma unroll
        for (int j = 0; j < 8; j++) {
            float px = __expf(s[j].x), py = __expf(s[j].y);
            float pz = __expf(s[j].z), pw = __expf(s[j].w);
            if (kt == 15 && j >= 4) {
                if (!lat0) { px = 0.f; py = 0.f; }
                if (!lat1) { pz = 0.f; pw = 0.f; }
            }
            l0 += px + py; l1 += pz + pw;
            ph[2 * j]     = f2h2(px, py);   // row g
            ph[2 * j + 1] = f2h2(pz, pw);   // row g+8
        }
        // O += P V   (pa for k-chunk kk = keys kk*16..+15)
        #pragma unroll
        for (int kk = 0; kk < 4; kk++) {
            uint32_t pa[4];
            pa[0] = ph[4 * kk];     pa[1] = ph[4 * kk + 1];
            pa[2] = ph[4 * kk + 2]; pa[3] = ph[4 * kk + 3];
            #pragma unroll
            for (int jp = 0; jp < 4; jp++) {
                uint32_t b0, b1, b2, b3;
                ldsm4t(b0, b1, b2, b3,
                       lbV + (uint32_t)((kk * 16) * 36 * 4 + (jp * 16) * 2));
                mma16(o[2 * jp],     pa, b0, b2);
                mma16(o[2 * jp + 1], pa, b1, b3);
            }
        }
        __syncthreads();
    }

    l0 += __shfl_xor_sync(0xffffffffu, l0, 1);
    l0 += __shfl_xor_sync(0xffffffffu, l0, 2);
    l1 += __shfl_xor_sync(0xffffffffu, l1, 1);
    l1 += __shfl_xor_sync(0xffffffffu, l1, 2);
    float i0 = 1.0f / l0, i1 = 1.0f / l1;

    const int bb = bh / H_, h = bh % H_;
    int gr0 = (r0g < CTX_) ? bb * CTX_ + r0g : GCTX_ + bb * 32 + (r0g - CTX_);
    int r1g = r0g + 8;
    int gr1 = (r1g < CTX_) ? bb * CTX_ + r1g : GCTX_ + bb * 32 + (r1g - CTX_);
    #pragma unroll
    for (int j = 0; j < 8; j++) {
        int col = h * 64 + j * 8 + 2 * t;
        *(uint32_t*)(g_Attn + (size_t)gr0 * DIM_ + col) = f2h2(o[j].x * i0, o[j].y * i0);
        *(uint32_t*)(g_Attn + (size_t)gr1 * DIM_ + col) = f2h2(o[j].z * i1, o[j].w * i1);
    }
}

// ---------------- output projection, cp.async double-buffered ----------------
__global__ __launch_bounds__(256) void out_kernel(const float* __restrict__ bc,
                                                  const float* __restrict__ bl,
                                                  float* __restrict__ out) {
    extern __shared__ uint32_t dsm[];
    const int m0 = blockIdx.x * 128;
    const int n0 = blockIdx.y * 128;
    const bool ctx = (m0 < GCTX_);
    const __half* WT  = ctx ? g_WocT : g_WolT;
    const float* bias = ctx ? bc : bl;

    const int tid = threadIdx.x;
    const int lane = tid & 31, wid = tid >> 5;
    const int wm = (wid & 3) * 32;
    const int wn = (wid >> 2) * 64;
    const int g = lane >> 2, t = lane & 3;
    const uint32_t sbase = (uint32_t)__cvta_generic_to_shared(dsm);

    auto stage = [&](int bi, int k0) {
        uint32_t ao = sbase + (uint32_t)(bi * 4608) * 4;
        uint32_t bo = sbase + (uint32_t)(9216 + bi * 4608) * 4;
        #pragma unroll
        for (int i = 0; i < 4; i++) {
            int idx = tid + i * 256;
            int r = idx >> 3, c = idx & 7;
            cpa16(ao + (uint32_t)(r * 36 + c * 4) * 4,
                  g_Attn + (size_t)(m0 + r) * DIM_ + k0 + c * 8);
            cpa16(bo + (uint32_t)(r * 36 + c * 4) * 4,
                  WT + (size_t)(n0 + r) * DIM_ + k0 + c * 8);
        }
    };

    float4 acc[2][8];
    #pragma unroll
    for (int i = 0; i < 2; i++)
        #pragma unroll
        for (int j = 0; j < 8; j++) acc[i][j] = make_float4(0.f, 0.f, 0.f, 0.f);

    stage(0, 0);
    cp_commit();

    for (int kt = 0; kt < 12; kt++) {
        int bi = kt & 1;
        if (kt < 11) { stage(bi ^ 1, (kt + 1) * 64); cp_commit(); cp_wait<1>(); }
        else cp_wait<0>();
        __syncthreads();

        uint32_t sA = sbase + (uint32_t)(bi * 4608) * 4 + lane_off16(lane, 36);
        uint32_t sB = sbase + (uint32_t)(9216 + bi * 4608) * 4 + lane_off16(lane, 36);
        #pragma unroll
        for (int kk = 0; kk < 4; kk++) {
            uint32_t a0[4], a1[4];
            ldsm4(a0[0], a0[1], a0[2], a0[3], sA + (uint32_t)(wm * 36 * 4 + kk * 32));
            ldsm4(a1[0], a1[1], a1[2], a1[3], sA + (uint32_t)((wm + 16) * 36 * 4 + kk * 32));
            #pragma unroll
            for (int jp = 0; jp < 4; jp++) {
                uint32_t b0, b1, b2, b3;
                ldsm4(b0, b1, b2, b3, sB + (uint32_t)((wn + jp * 16) * 36 * 4 + kk * 32));
                mma16(acc[0][2 * jp],     a0, b0, b2);
                mma16(acc[0][2 * jp + 1], a0, b1, b3);
                mma16(acc[1][2 * jp],     a1, b0, b2);
                mma16(acc[1][2 * jp + 1], a1, b1, b3);
            }
        }
        __syncthreads();
    }

    #pragma unroll
    for (int mt = 0; mt < 2; mt++) {
        int rA = m0 + wm + mt * 16 + g;
        #pragma unroll
        for (int half = 0; half < 2; half++) {
            int r = rA + half * 8;
            int b, n;
            if (r < GCTX_) { b = r / CTX_; n = r - b * CTX_; }
            else { int q = r - GCTX_; b = q >> 5; n = CTX_ + (q & 31); }
            float* orow = out + (size_t)(b * N_ + n) * DIM_;
            #pragma unroll
            for (int jf = 0; jf < 8; jf++) {
                int col = n0 + wn + jf * 8 + 2 * t;
                float vx = half ? acc[mt][jf].z : acc[mt][jf].x;
                float vy = half ? acc[mt][jf].w : acc[mt][jf].y;
                *(float2*)(orow + col) = make_float2(vx + bias[col], vy + bias[col + 1]);
            }
        }
    }
}

// ---------------- launch -----------------------------------------------------
extern "C" void kernel_launch(void* const* d_in, const int* in_sizes, int n_in,
                              void* d_out, int out_size) {
    const float* x      = (const float*)d_in[0];
    const float* Wq     = (const float*)d_in[1];
    const float* Wkv    = (const float*)d_in[2];
    const float* Wo_ctx = (const float*)d_in[3];
    const float* bo_ctx = (const float*)d_in[4];
    const float* Wo_lat = (const float*)d_in[5];
    const float* bo_lat = (const float*)d_in[6];
    const float* ln_g   = (const float*)d_in[7];
    const float* ln_b   = (const float*)d_in[8];
    float* out = (float*)d_out;

    cudaFuncSetAttribute(proj_kernel, cudaFuncAttributeMaxDynamicSharedMemorySize, 73728);
    cudaFuncSetAttribute(attn_kernel, cudaFuncAttributeMaxDynamicSharedMemorySize, 55296);
    cudaFuncSetAttribute(out_kernel,  cudaFuncAttributeMaxDynamicSharedMemorySize, 73728);

    cvt_x<<<ROWS_ * DIM_ / (256 * 8), 256>>>(x);
    transpose_w<<<dim3(24, 24, 4), 256>>>(Wq, Wkv, Wo_ctx, Wo_lat);

    proj_kernel<<<dim3(64, 12), 256, 73728>>>(ln_g, ln_b);
    attn_kernel<<<dim3(96, 8), 256, 55296>>>();
    out_kernel<<<dim3(64, 6), 256, 73728>>>(bo_ctx, bo_lat, out);
}

// round 11
// speedup vs baseline: 5.5635x; 1.0236x over previous
#include <cuda_runtime.h>
#include <cuda_fp16.h>
#include <math.h>
#include <stdint.h>

#define B_    8
#define N_    1024
#define DIM_  768
#define H_    12
#define DH_   64
#define CTX_  992
#define BH_   96
#define ROWS_ 8192
#define GCTX_ 7936   // 8*992 grouped ctx rows

// ---------------- scratch (all fp16, 16B aligned) ----------------------------
__device__ __align__(16) __half g_Xh  [ROWS_ * DIM_];
__device__ __align__(16) __half g_Qh  [BH_ * N_ * DH_];
__device__ __align__(16) __half g_KVh [BH_ * N_ * DH_];
__device__ __align__(16) __half g_LKVh[BH_ * N_ * DH_];
__device__ __align__(16) __half g_Attn[ROWS_ * DIM_];   // grouped rows
__device__ __align__(16) __half g_WqT [DIM_ * DIM_];
__device__ __align__(16) __half g_WkvT[DIM_ * DIM_];
__device__ __align__(16) __half g_WocT[DIM_ * DIM_];
__device__ __align__(16) __half g_WolT[DIM_ * DIM_];

// ---------------- helpers ----------------------------------------------------
__device__ __forceinline__ uint32_t f2h2(float a, float b) {
    __half2 h = __floats2half2_rn(a, b);
    return *reinterpret_cast<uint32_t*>(&h);
}
__device__ __forceinline__ void mma16(float4& c, const uint32_t* a, uint32_t b0, uint32_t b1) {
    asm volatile(
        "mma.sync.aligned.m16n8k16.row.col.f32.f16.f16.f32 "
        "{%0,%1,%2,%3}, {%4,%5,%6,%7}, {%8,%9}, {%0,%1,%2,%3};\n"
        : "+f"(c.x), "+f"(c.y), "+f"(c.z), "+f"(c.w)
        : "r"(a[0]), "r"(a[1]), "r"(a[2]), "r"(a[3]), "r"(b0), "r"(b1));
}
__device__ __forceinline__ void ldsm4(uint32_t& r0, uint32_t& r1, uint32_t& r2,
                                      uint32_t& r3, uint32_t addr) {
    asm volatile("ldmatrix.sync.aligned.m8n8.x4.shared.b16 {%0,%1,%2,%3}, [%4];"
                 : "=r"(r0), "=r"(r1), "=r"(r2), "=r"(r3) : "r"(addr));
}
__device__ __forceinline__ void ldsm4t(uint32_t& r0, uint32_t& r1, uint32_t& r2,
                                       uint32_t& r3, uint32_t addr) {
    asm volatile("ldmatrix.sync.aligned.m8n8.x4.trans.shared.b16 {%0,%1,%2,%3}, [%4];"
                 : "=r"(r0), "=r"(r1), "=r"(r2), "=r"(r3) : "r"(addr));
}
__device__ __forceinline__ uint32_t lane_off16(int lane, int S) {
    int lr = (lane & 7) + ((lane >> 3) & 1) * 8;
    return (uint32_t)(lr * S * 4 + (lane >> 4) * 16);
}
__device__ __forceinline__ uint32_t lane_off16t(int lane, int S) {
    int lr = (lane & 7) + ((lane >> 4) & 1) * 8;
    return (uint32_t)(lr * S * 4 + ((lane >> 3) & 1) * 16);
}
__device__ __forceinline__ void cpa16(uint32_t dst, const void* src) {
    asm volatile("cp.async.ca.shared.global [%0], [%1], 16;" :: "r"(dst), "l"(src));
}
__device__ __forceinline__ void cp_commit() {
    asm volatile("cp.async.commit_group;");
}
template<int N>
__device__ __forceinline__ void cp_wait() {
    asm volatile("cp.async.wait_group %0;" :: "n"(N));
}

// ---------------- x -> fp16 ---------------------------------------------------
__global__ __launch_bounds__(256) void cvt_x(const float* __restrict__ x) {
    int idx = blockIdx.x * 256 + threadIdx.x;           // 8 floats per thread
    const float4* p = (const float4*)x + (size_t)idx * 2;
    float4 a = p[0], b = p[1];
    *(uint4*)(g_Xh + (size_t)idx * 8) =
        make_uint4(f2h2(a.x, a.y), f2h2(a.z, a.w), f2h2(b.x, b.y), f2h2(b.z, b.w));
}

// ---------------- fused weight transpose (grid.z selects matrix) -------------
__global__ __launch_bounds__(256) void transpose_w(const float* __restrict__ s0,
                                                   const float* __restrict__ s1,
                                                   const float* __restrict__ s2,
                                                   const float* __restrict__ s3) {
    __shared__ float tile[32][33];
    const float* src;
    __half* dst;
    switch (blockIdx.z) {
        case 0: src = s0; dst = g_WqT;  break;
        case 1: src = s1; dst = g_WkvT; break;
        case 2: src = s2; dst = g_WocT; break;
        default: src = s3; dst = g_WolT; break;
    }
    int c0 = blockIdx.x * 32, r0 = blockIdx.y * 32;
    int tx = threadIdx.x & 31, ty = threadIdx.x >> 5;
    #pragma unroll
    for (int i = 0; i < 4; i++)
        tile[ty + i * 8][tx] = src[(size_t)(r0 + ty + i * 8) * DIM_ + c0 + tx];
    __syncthreads();
    #pragma unroll
    for (int i = 0; i < 4; i++)
        dst[(size_t)(c0 + ty + i * 8) * DIM_ + r0 + tx] = __float2half(tile[tx][ty + i * 8]);
}

// ---------------- fused Q+KV projection, single-sync pipeline ----------------
__global__ __launch_bounds__(256) void proj_kernel(const float* __restrict__ lng,
                                                   const float* __restrict__ lnb) {
    extern __shared__ uint32_t dsm[];
    const int m0 = blockIdx.x * 128;
    const int head = blockIdx.y;
    const int n0 = head * 64;
    const int tid = threadIdx.x;
    const int lane = tid & 31, wid = tid >> 5;
    const int g = lane >> 2, t = lane & 3;
    const uint32_t sbase = (uint32_t)__cvta_generic_to_shared(dsm);

    auto stage = [&](int bi, int k0) {
        uint32_t aoff = sbase + (uint32_t)(bi * 4608) * 4;
        #pragma unroll
        for (int i = 0; i < 4; i++) {
            int idx = tid + i * 256;
            int r = idx >> 3, c = idx & 7;
            cpa16(aoff + (uint32_t)(r * 36 + c * 4) * 4,
                  g_Xh + (size_t)(m0 + r) * DIM_ + k0 + c * 8);
        }
        uint32_t bqo = sbase + (uint32_t)(9216 + bi * 2304) * 4;
        uint32_t bko = sbase + (uint32_t)(13824 + bi * 2304) * 4;
        #pragma unroll
        for (int i = 0; i < 2; i++) {
            int idx = tid + i * 256;
            int r = idx >> 3, c = idx & 7;
            cpa16(bqo + (uint32_t)(r * 36 + c * 4) * 4,
                  g_WqT + (size_t)(n0 + r) * DIM_ + k0 + c * 8);
            cpa16(bko + (uint32_t)(r * 36 + c * 4) * 4,
                  g_WkvT + (size_t)(n0 + r) * DIM_ + k0 + c * 8);
        }
    };

    float4 accQ[8], accKV[8];
    #pragma unroll
    for (int j = 0; j < 8; j++) {
        accQ[j] = make_float4(0.f, 0.f, 0.f, 0.f);
        accKV[j] = make_float4(0.f, 0.f, 0.f, 0.f);
    }

    stage(0, 0);
    cp_commit();

    for (int kt = 0; kt < 12; kt++) {
        int bi = kt & 1;
        cp_wait<0>();
        __syncthreads();           // tile kt visible; prev compute on bi^1 done
        if (kt < 11) { stage(bi ^ 1, (kt + 1) * 64); cp_commit(); }

        uint32_t lA = sbase + (uint32_t)(bi * 4608) * 4 + lane_off16(lane, 36);
        uint32_t lQ = sbase + (uint32_t)(9216 + bi * 2304) * 4 + lane_off16(lane, 36);
        uint32_t lK = sbase + (uint32_t)(13824 + bi * 2304) * 4 + lane_off16(lane, 36);
        #pragma unroll
        for (int kk = 0; kk < 4; kk++) {
            uint32_t a[4];
            ldsm4(a[0], a[1], a[2], a[3], lA + (uint32_t)((wid * 16) * 36 * 4 + kk * 32));
            #pragma unroll
            for (int jp = 0; jp < 4; jp++) {
                uint32_t b0, b1, b2, b3;
                ldsm4(b0, b1, b2, b3, lQ + (uint32_t)((jp * 16) * 36 * 4 + kk * 32));
                mma16(accQ[2 * jp],     a, b0, b2);
                mma16(accQ[2 * jp + 1], a, b1, b3);
                ldsm4(b0, b1, b2, b3, lK + (uint32_t)((jp * 16) * 36 * 4 + kk * 32));
                mma16(accKV[2 * jp],     a, b0, b2);
                mma16(accKV[2 * jp + 1], a, b1, b3);
            }
        }
    }

    const int rA = m0 + wid * 16 + g;
    const int bb = rA >> 10;
    const int nA = rA & 1023;
    size_t oA = ((size_t)(bb * H_ + head) * N_ + nA) * DH_ + 2 * t;
    size_t oB = oA + 8 * DH_;
    // ---- Q epilogue ----
    {
        float lo[4][4], hi[4][4];
        #pragma unroll
        for (int jl = 0; jl < 4; jl++)
            #pragma unroll
            for (int c = 0; c < 4; c++) {
                float v1 = ((const float*)&accQ[jl])[c];
                float v2 = ((const float*)&accQ[jl + 4])[c];
                int d = jl * 8 + 2 * t + (c & 1);
                int n = nA + (c >> 1) * 8;
                float inv = exp2f(-(float)d * 0.41524101186092034f);
                float sn, cs;
                sincosf((float)n * inv, &sn, &cs);
                lo[jl][c] = v1 * cs - v2 * sn;
                hi[jl][c] = v2 * cs + v1 * sn;
            }
        #pragma unroll
        for (int jl = 0; jl < 4; jl++) {
            *(uint32_t*)(g_Qh + oA + jl * 8)      = f2h2(lo[jl][0] * 0.125f, lo[jl][1] * 0.125f);
            *(uint32_t*)(g_Qh + oA + jl * 8 + 32) = f2h2(hi[jl][0] * 0.125f, hi[jl][1] * 0.125f);
            *(uint32_t*)(g_Qh + oB + jl * 8)      = f2h2(lo[jl][2] * 0.125f, lo[jl][3] * 0.125f);
            *(uint32_t*)(g_Qh + oB + jl * 8 + 32) = f2h2(hi[jl][2] * 0.125f, hi[jl][3] * 0.125f);
        }
    }
    // ---- KV epilogue (RoPE + LN) ----
    {
        float lo[4][4], hi[4][4];
        #pragma unroll
        for (int jl = 0; jl < 4; jl++)
            #pragma unroll
            for (int c = 0; c < 4; c++) {
                float v1 = ((const float*)&accKV[jl])[c];
                float v2 = ((const float*)&accKV[jl + 4])[c];
                int d = jl * 8 + 2 * t + (c & 1);
                int n = nA + (c >> 1) * 8;
                float inv = exp2f(-(float)d * 0.41524101186092034f);
                float sn, cs;
                sincosf((float)n * inv, &sn, &cs);
                lo[jl][c] = v1 * cs - v2 * sn;
                hi[jl][c] = v2 * cs + v1 * sn;
            }
        #pragma unroll
        for (int jl = 0; jl < 4; jl++) {
            *(uint32_t*)(g_KVh + oA + jl * 8)      = f2h2(lo[jl][0], lo[jl][1]);
            *(uint32_t*)(g_KVh + oA + jl * 8 + 32) = f2h2(hi[jl][0], hi[jl][1]);
            *(uint32_t*)(g_KVh + oB + jl * 8)      = f2h2(lo[jl][2], lo[jl][3]);
            *(uint32_t*)(g_KVh + oB + jl * 8 + 32) = f2h2(hi[jl][2], hi[jl][3]);
        }
        float sumA = 0.f, sumB = 0.f;
        #pragma unroll
        for (int jl = 0; jl < 4; jl++) {
            sumA += lo[jl][0] + lo[jl][1] + hi[jl][0] + hi[jl][1];
            sumB += lo[jl][2] + lo[jl][3] + hi[jl][2] + hi[jl][3];
        }
        sumA += __shfl_xor_sync(0xffffffffu, sumA, 1);
        sumA += __shfl_xor_sync(0xffffffffu, sumA, 2);
        sumB += __shfl_xor_sync(0xffffffffu, sumB, 1);
        sumB += __shfl_xor_sync(0xffffffffu, sumB, 2);
        float mA = sumA * (1.f / 64.f), mB = sumB * (1.f / 64.f);
        float vA = 0.f, vB = 0.f;
        #pragma unroll
        for (int jl = 0; jl < 4; jl++)
            #pragma unroll
            for (int c = 0; c < 2; c++) {
                float d1 = lo[jl][c] - mA, d2 = hi[jl][c] - mA;
                vA += d1 * d1 + d2 * d2;
                float d3 = lo[jl][c + 2] - mB, d4 = hi[jl][c + 2] - mB;
                vB += d3 * d3 + d4 * d4;
            }
        vA += __shfl_xor_sync(0xffffffffu, vA, 1);
        vA += __shfl_xor_sync(0xffffffffu, vA, 2);
        vB += __shfl_xor_sync(0xffffffffu, vB, 1);
        vB += __shfl_xor_sync(0xffffffffu, vB, 2);
        float iA = rsqrtf(vA * (1.f / 64.f) + 1e-5f);
        float iB = rsqrtf(vB * (1.f / 64.f) + 1e-5f);
        #pragma unroll
        for (int jl = 0; jl < 4; jl++) {
            int d = jl * 8 + 2 * t;
            float g0 = lng[d], g1 = lng[d + 1], b0 = lnb[d], b1 = lnb[d + 1];
            float g2 = lng[d + 32], g3 = lng[d + 33], b2 = lnb[d + 32], b3 = lnb[d + 33];
            *(uint32_t*)(g_LKVh + oA + jl * 8) = f2h2(
                (lo[jl][0] - mA) * iA * g0 + b0, (lo[jl][1] - mA) * iA * g1 + b1);
            *(uint32_t*)(g_LKVh + oA + jl * 8 + 32) = f2h2(
                (hi[jl][0] - mA) * iA * g2 + b2, (hi[jl][1] - mA) * iA * g3 + b3);
            *(uint32_t*)(g_LKVh + oB + jl * 8) = f2h2(
                (lo[jl][2] - mB) * iB * g0 + b0, (lo[jl][3] - mB) * iB * g1 + b1);
            *(uint32_t*)(g_LKVh + oB + jl * 8 + 32) = f2h2(
                (hi[jl][2] - mB) * iB * g2 + b2, (hi[jl][3] - mB) * iB * g3 + b3);
        }
    }
}

// ---------------- fused attention: 128-key tiles, single-sync, reg-P ---------
// dyn smem u32: Q@0 (4608), K[2]@4608/9216, V[2]@13824/18432 -> 23040 u32 = 92160 B
__global__ __launch_bounds__(256, 2) void attn_kernel() {
    extern __shared__ uint32_t dsm[];
    const int bh = blockIdx.x, qt = blockIdx.y;
    const int m0 = qt * 128;
    const int tid = threadIdx.x;
    const int lane = tid & 31, wid = tid >> 5;
    const int g = lane >> 2, t = lane & 3;
    const int wr = wid * 16;
    const uint32_t sbase = (uint32_t)__cvta_generic_to_shared(dsm);
    const uint32_t lbQ = sbase + lane_off16(lane, 36);

    auto stageKV = [&](int bi, int kt) {            // 128 keys
        const __half* kb = g_KVh  + ((size_t)bh * N_ + kt * 128) * DH_;
        const __half* vb = g_LKVh + ((size_t)bh * N_ + kt * 128) * DH_;
        uint32_t ko = sbase + (uint32_t)(4608 + bi * 4608) * 4;
        uint32_t vo = sbase + (uint32_t)(13824 + bi * 4608) * 4;
        #pragma unroll
        for (int i = 0; i < 4; i++) {
            int idx = tid + i * 256;
            int r = idx >> 3, c = idx & 7;
            cpa16(ko + (uint32_t)(r * 36 + c * 4) * 4, kb + (size_t)r * DH_ + c * 8);
            cpa16(vo + (uint32_t)(r * 36 + c * 4) * 4, vb + (size_t)r * DH_ + c * 8);
        }
    };

    // stage Q + tile 0
    const __half* qsrc = g_Qh + ((size_t)bh * N_ + m0) * DH_;
    #pragma unroll
    for (int i = 0; i < 4; i++) {
        int idx = tid + i * 256;
        int r = idx >> 3, c = idx & 7;
        cpa16(sbase + (uint32_t)(r * 36 + c * 4) * 4, qsrc + (size_t)r * DH_ + c * 8);
    }
    stageKV(0, 0);
    cp_commit();

    uint32_t qa[4][4];
    float4 o[8];
    #pragma unroll
    for (int j = 0; j < 8; j++) o[j] = make_float4(0.f, 0.f, 0.f, 0.f);
    float l0 = 0.f, l1 = 0.f;
    const int r0g = m0 + wr + g;
    const bool lat0 = (r0g >= CTX_);
    const bool lat1 = (r0g + 8 >= CTX_);

    for (int kt = 0; kt < 8; kt++) {
        int bi = kt & 1;
        cp_wait<0>();
        __syncthreads();              // tile kt visible; compute on bi^1 finished
        if (kt == 0) {
            #pragma unroll
            for (int kk = 0; kk < 4; kk++)
                ldsm4(qa[kk][0], qa[kk][1], qa[kk][2], qa[kk][3],
                      lbQ + (uint32_t)(wr * 36 * 4 + kk * 32));
        }
        if (kt < 7) { stageKV(bi ^ 1, kt + 1); cp_commit(); }

        #pragma unroll
        for (int half = 0; half < 2; half++) {
            uint32_t lbK = sbase + (uint32_t)(4608 + bi * 4608 + half * 2304) * 4
                           + lane_off16(lane, 36);
            uint32_t lbV = sbase + (uint32_t)(13824 + bi * 4608 + half * 2304) * 4
                           + lane_off16t(lane, 36);
            // S = Q K^T (64 keys)
            float4 s[8];
            #pragma unroll
            for (int j = 0; j < 8; j++) s[j] = make_float4(0.f, 0.f, 0.f, 0.f);
            #pragma unroll
            for (int kk = 0; kk < 4; kk++) {
                #pragma unroll
                for (int jp = 0; jp < 4; jp++) {
                    uint32_t b0, b1, b2, b3;
                    ldsm4(b0, b1, b2, b3, lbK + (uint32_t)((jp * 16) * 36 * 4 + kk * 32));
                    mma16(s[2 * jp],     qa[kk], b0, b2);
                    mma16(s[2 * jp + 1], qa[kk], b1, b3);
                }
            }
            // exp -> register-resident P fragments
            uint32_t ph[16];
            #pragma unroll
            for (int j = 0; j < 8; j++) {
                float px = __expf(s[j].x), py = __expf(s[j].y);
                float pz = __expf(s[j].z), pw = __expf(s[j].w);
                if (kt == 7 && half == 1 && j >= 4) {     // keys >= CTX_
                    if (!lat0) { px = 0.f; py = 0.f; }
                    if (!lat1) { pz = 0.f; pw = 0.f; }
                }
                l0 += px + py; l1 += pz + pw;
                ph[2 * j]     = f2h2(px, py);
                ph[2 * j + 1] = f2h2(pz, pw);
            }
            // O += P V
            #pragma unroll
            for (int kk = 0; kk < 4; kk++) {
                uint32_t pa[4];
                pa[0] = ph[4 * kk];     pa[1] = ph[4 * kk + 1];
                pa[2] = ph[4 * kk + 2]; pa[3] = ph[4 * kk + 3];
                #pragma unroll
                for (int jp = 0; jp < 4; jp++) {
                    uint32_t b0, b1, b2, b3;
                    ldsm4t(b0, b1, b2, b3,
                           lbV + (uint32_t)((kk * 16) * 36 * 4 + (jp * 16) * 2));
                    mma16(o[2 * jp],     pa, b0, b2);
                    mma16(o[2 * jp + 1], pa, b1, b3);
                }
            }
        }
    }

    l0 += __shfl_xor_sync(0xffffffffu, l0, 1);
    l0 += __shfl_xor_sync(0xffffffffu, l0, 2);
    l1 += __shfl_xor_sync(0xffffffffu, l1, 1);
    l1 += __shfl_xor_sync(0xffffffffu, l1, 2);
    float i0 = 1.0f / l0, i1 = 1.0f / l1;

    const int bb = bh / H_, h = bh % H_;
    int gr0 = (r0g < CTX_) ? bb * CTX_ + r0g : GCTX_ + bb * 32 + (r0g - CTX_);
    int r1g = r0g + 8;
    int gr1 = (r1g < CTX_) ? bb * CTX_ + r1g : GCTX_ + bb * 32 + (r1g - CTX_);
    #pragma unroll
    for (int j = 0; j < 8; j++) {
        int col = h * 64 + j * 8 + 2 * t;
        *(uint32_t*)(g_Attn + (size_t)gr0 * DIM_ + col) = f2h2(o[j].x * i0, o[j].y * i0);
        *(uint32_t*)(g_Attn + (size_t)gr1 * DIM_ + col) = f2h2(o[j].z * i1, o[j].w * i1);
    }
}

// ---------------- output projection, single-sync pipeline --------------------
__global__ __launch_bounds__(256) void out_kernel(const float* __restrict__ bc,
                                                  const float* __restrict__ bl,
                                                  float* __restrict__ out) {
    extern __shared__ uint32_t dsm[];
    const int m0 = blockIdx.x * 128;
    const int n0 = blockIdx.y * 128;
    const bool ctx = (m0 < GCTX_);
    const __half* WT  = ctx ? g_WocT : g_WolT;
    const float* bias = ctx ? bc : bl;

    const int tid = threadIdx.x;
    const int lane = tid & 31, wid = tid >> 5;
    const int wm = (wid & 3) * 32;
    const int wn = (wid >> 2) * 64;
    const int g = lane >> 2, t = lane & 3;
    const uint32_t sbase = (uint32_t)__cvta_generic_to_shared(dsm);

    auto stage = [&](int bi, int k0) {
        uint32_t ao = sbase + (uint32_t)(bi * 4608) * 4;
        uint32_t bo = sbase + (uint32_t)(9216 + bi * 4608) * 4;
        #pragma unroll
        for (int i = 0; i < 4; i++) {
            int idx = tid + i * 256;
            int r = idx >> 3, c = idx & 7;
            cpa16(ao + (uint32_t)(r * 36 + c * 4) * 4,
                  g_Attn + (size_t)(m0 + r) * DIM_ + k0 + c * 8);
            cpa16(bo + (uint32_t)(r * 36 + c * 4) * 4,
                  WT + (size_t)(n0 + r) * DIM_ + k0 + c * 8);
        }
    };

    float4 acc[2][8];
    #pragma unroll
    for (int i = 0; i < 2; i++)
        #pragma unroll
        for (int j = 0; j < 8; j++) acc[i][j] = make_float4(0.f, 0.f, 0.f, 0.f);

    stage(0, 0);
    cp_commit();

    for (int kt = 0; kt < 12; kt++) {
        int bi = kt & 1;
        cp_wait<0>();
        __syncthreads();
        if (kt < 11) { stage(bi ^ 1, (kt + 1) * 64); cp_commit(); }

        uint32_t sA = sbase + (uint32_t)(bi * 4608) * 4 + lane_off16(lane, 36);
        uint32_t sB = sbase + (uint32_t)(9216 + bi * 4608) * 4 + lane_off16(lane, 36);
        #pragma unroll
        for (int kk = 0; kk < 4; kk++) {
            uint32_t a0[4], a1[4];
            ldsm4(a0[0], a0[1], a0[2], a0[3], sA + (uint32_t)(wm * 36 * 4 + kk * 32));
            ldsm4(a1[0], a1[1], a1[2], a1[3], sA + (uint32_t)((wm + 16) * 36 * 4 + kk * 32));
            #pragma unroll
            for (int jp = 0; jp < 4; jp++) {
                uint32_t b0, b1, b2, b3;
                ldsm4(b0, b1, b2, b3, sB + (uint32_t)((wn + jp * 16) * 36 * 4 + kk * 32));
                mma16(acc[0][2 * jp],     a0, b0, b2);
                mma16(acc[0][2 * jp + 1], a0, b1, b3);
                mma16(acc[1][2 * jp],     a1, b0, b2);
                mma16(acc[1][2 * jp + 1], a1, b1, b3);
            }
        }
    }

    #pragma unroll
    for (int mt = 0; mt < 2; mt++) {
        int rA = m0 + wm + mt * 16 + g;
        #pragma unroll
        for (int half = 0; half < 2; half++) {
            int r = rA + half * 8;
            int b, n;
            if (r < GCTX_) { b = r / CTX_; n = r - b * CTX_; }
            else { int q = r - GCTX_; b = q >> 5; n = CTX_ + (q & 31); }
            float* orow = out + (size_t)(b * N_ + n) * DIM_;
            #pragma unroll
            for (int jf = 0; jf < 8; jf++) {
                int col = n0 + wn + jf * 8 + 2 * t;
                float vx = half ? acc[mt][jf].z : acc[mt][jf].x;
                float vy = half ? acc[mt][jf].w : acc[mt][jf].y;
                *(float2*)(orow + col) = make_float2(vx + bias[col], vy + bias[col + 1]);
            }
        }
    }
}

// ---------------- launch -----------------------------------------------------
extern "C" void kernel_launch(void* const* d_in, const int* in_sizes, int n_in,
                              void* d_out, int out_size) {
    const float* x      = (const float*)d_in[0];
    const float* Wq     = (const float*)d_in[1];
    const float* Wkv    = (const float*)d_in[2];
    const float* Wo_ctx = (const float*)d_in[3];
    const float* bo_ctx = (const float*)d_in[4];
    const float* Wo_lat = (const float*)d_in[5];
    const float* bo_lat = (const float*)d_in[6];
    const float* ln_g   = (const float*)d_in[7];
    const float* ln_b   = (const float*)d_in[8];
    float* out = (float*)d_out;

    cudaFuncSetAttribute(proj_kernel, cudaFuncAttributeMaxDynamicSharedMemorySize, 73728);
    cudaFuncSetAttribute(attn_kernel, cudaFuncAttributeMaxDynamicSharedMemorySize, 92160);
    cudaFuncSetAttribute(out_kernel,  cudaFuncAttributeMaxDynamicSharedMemorySize, 73728);

    cvt_x<<<ROWS_ * DIM_ / (256 * 8), 256>>>(x);
    transpose_w<<<dim3(24, 24, 4), 256>>>(Wq, Wkv, Wo_ctx, Wo_lat);

    proj_kernel<<<dim3(64, 12), 256, 73728>>>(ln_g, ln_b);
    attn_kernel<<<dim3(96, 8), 256, 92160>>>();
    out_kernel<<<dim3(64, 6), 256, 73728>>>(bo_ctx, bo_lat, out);
}

// round 12
// speedup vs baseline: 5.7373x; 1.0312x over previous
#include <cuda_runtime.h>
#include <cuda_fp16.h>
#include <math.h>
#include <stdint.h>

#define B_    8
#define N_    1024
#define DIM_  768
#define H_    12
#define DH_   64
#define CTX_  992
#define BH_   96
#define ROWS_ 8192
#define GCTX_ 7936   // 8*992 grouped ctx rows

// ---------------- scratch (all fp16, 16B aligned) ----------------------------
__device__ __align__(16) __half g_Xh  [ROWS_ * DIM_];
__device__ __align__(16) __half g_Qh  [BH_ * N_ * DH_];
__device__ __align__(16) __half g_KVh [BH_ * N_ * DH_];
__device__ __align__(16) __half g_LKVh[BH_ * N_ * DH_];
__device__ __align__(16) __half g_Attn[ROWS_ * DIM_];   // grouped rows
__device__ __align__(16) __half g_WqT [DIM_ * DIM_];
__device__ __align__(16) __half g_WkvT[DIM_ * DIM_];
__device__ __align__(16) __half g_WocT[DIM_ * DIM_];
__device__ __align__(16) __half g_WolT[DIM_ * DIM_];

// Q scale absorbs DH^-0.5 (=0.125) AND log2(e) so attention can use raw ex2.
#define QSCALE_ 0.18033688011112042f

// ---------------- helpers ----------------------------------------------------
__device__ __forceinline__ uint32_t f2h2(float a, float b) {
    __half2 h = __floats2half2_rn(a, b);
    return *reinterpret_cast<uint32_t*>(&h);
}
__device__ __forceinline__ float ex2f(float x) {
    float r; asm("ex2.approx.ftz.f32 %0, %1;" : "=f"(r) : "f"(x)); return r;
}
__device__ __forceinline__ void mma16(float4& c, const uint32_t* a, uint32_t b0, uint32_t b1) {
    asm volatile(
        "mma.sync.aligned.m16n8k16.row.col.f32.f16.f16.f32 "
        "{%0,%1,%2,%3}, {%4,%5,%6,%7}, {%8,%9}, {%0,%1,%2,%3};\n"
        : "+f"(c.x), "+f"(c.y), "+f"(c.z), "+f"(c.w)
        : "r"(a[0]), "r"(a[1]), "r"(a[2]), "r"(a[3]), "r"(b0), "r"(b1));
}
__device__ __forceinline__ void ldsm4(uint32_t& r0, uint32_t& r1, uint32_t& r2,
                                      uint32_t& r3, uint32_t addr) {
    asm volatile("ldmatrix.sync.aligned.m8n8.x4.shared.b16 {%0,%1,%2,%3}, [%4];"
                 : "=r"(r0), "=r"(r1), "=r"(r2), "=r"(r3) : "r"(addr));
}
__device__ __forceinline__ void ldsm4t(uint32_t& r0, uint32_t& r1, uint32_t& r2,
                                       uint32_t& r3, uint32_t addr) {
    asm volatile("ldmatrix.sync.aligned.m8n8.x4.trans.shared.b16 {%0,%1,%2,%3}, [%4];"
                 : "=r"(r0), "=r"(r1), "=r"(r2), "=r"(r3) : "r"(addr));
}
__device__ __forceinline__ uint32_t lane_off16(int lane, int S) {
    int lr = (lane & 7) + ((lane >> 3) & 1) * 8;
    return (uint32_t)(lr * S * 4 + (lane >> 4) * 16);
}
__device__ __forceinline__ uint32_t lane_off16t(int lane, int S) {
    int lr = (lane & 7) + ((lane >> 4) & 1) * 8;
    return (uint32_t)(lr * S * 4 + ((lane >> 3) & 1) * 16);
}
__device__ __forceinline__ void cpa16(uint32_t dst, const void* src) {
    asm volatile("cp.async.ca.shared.global [%0], [%1], 16;" :: "r"(dst), "l"(src));
}
__device__ __forceinline__ void cp_commit() {
    asm volatile("cp.async.commit_group;");
}
template<int N>
__device__ __forceinline__ void cp_wait() {
    asm volatile("cp.async.wait_group %0;" :: "n"(N));
}

// ---------------- x -> fp16 ---------------------------------------------------
__global__ __launch_bounds__(256) void cvt_x(const float* __restrict__ x) {
    int idx = blockIdx.x * 256 + threadIdx.x;           // 8 floats per thread
    const float4* p = (const float4*)x + (size_t)idx * 2;
    float4 a = p[0], b = p[1];
    *(uint4*)(g_Xh + (size_t)idx * 8) =
        make_uint4(f2h2(a.x, a.y), f2h2(a.z, a.w), f2h2(b.x, b.y), f2h2(b.z, b.w));
}

// ---------------- fused weight transpose (grid.z selects matrix) -------------
__global__ __launch_bounds__(256) void transpose_w(const float* __restrict__ s0,
                                                   const float* __restrict__ s1,
                                                   const float* __restrict__ s2,
                                                   const float* __restrict__ s3) {
    __shared__ float tile[32][33];
    const float* src;
    __half* dst;
    switch (blockIdx.z) {
        case 0: src = s0; dst = g_WqT;  break;
        case 1: src = s1; dst = g_WkvT; break;
        case 2: src = s2; dst = g_WocT; break;
        default: src = s3; dst = g_WolT; break;
    }
    int c0 = blockIdx.x * 32, r0 = blockIdx.y * 32;
    int tx = threadIdx.x & 31, ty = threadIdx.x >> 5;
    #pragma unroll
    for (int i = 0; i < 4; i++)
        tile[ty + i * 8][tx] = src[(size_t)(r0 + ty + i * 8) * DIM_ + c0 + tx];
    __syncthreads();
    #pragma unroll
    for (int i = 0; i < 4; i++)
        dst[(size_t)(c0 + ty + i * 8) * DIM_ + r0 + tx] = __float2half(tile[tx][ty + i * 8]);
}

// ---------------- fused Q+KV projection, single-sync pipeline ----------------
__global__ __launch_bounds__(256) void proj_kernel(const float* __restrict__ lng,
                                                   const float* __restrict__ lnb) {
    extern __shared__ uint32_t dsm[];
    const int m0 = blockIdx.x * 128;
    const int head = blockIdx.y;
    const int n0 = head * 64;
    const int tid = threadIdx.x;
    const int lane = tid & 31, wid = tid >> 5;
    const int g = lane >> 2, t = lane & 3;
    const uint32_t sbase = (uint32_t)__cvta_generic_to_shared(dsm);

    auto stage = [&](int bi, int k0) {
        uint32_t aoff = sbase + (uint32_t)(bi * 4608) * 4;
        #pragma unroll
        for (int i = 0; i < 4; i++) {
            int idx = tid + i * 256;
            int r = idx >> 3, c = idx & 7;
            cpa16(aoff + (uint32_t)(r * 36 + c * 4) * 4,
                  g_Xh + (size_t)(m0 + r) * DIM_ + k0 + c * 8);
        }
        uint32_t bqo = sbase + (uint32_t)(9216 + bi * 2304) * 4;
        uint32_t bko = sbase + (uint32_t)(13824 + bi * 2304) * 4;
        #pragma unroll
        for (int i = 0; i < 2; i++) {
            int idx = tid + i * 256;
            int r = idx >> 3, c = idx & 7;
            cpa16(bqo + (uint32_t)(r * 36 + c * 4) * 4,
                  g_WqT + (size_t)(n0 + r) * DIM_ + k0 + c * 8);
            cpa16(bko + (uint32_t)(r * 36 + c * 4) * 4,
                  g_WkvT + (size_t)(n0 + r) * DIM_ + k0 + c * 8);
        }
    };

    float4 accQ[8], accKV[8];
    #pragma unroll
    for (int j = 0; j < 8; j++) {
        accQ[j] = make_float4(0.f, 0.f, 0.f, 0.f);
        accKV[j] = make_float4(0.f, 0.f, 0.f, 0.f);
    }

    stage(0, 0);
    cp_commit();

    for (int kt = 0; kt < 12; kt++) {
        int bi = kt & 1;
        cp_wait<0>();
        __syncthreads();           // tile kt visible; prev compute on bi^1 done
        if (kt < 11) { stage(bi ^ 1, (kt + 1) * 64); cp_commit(); }

        uint32_t lA = sbase + (uint32_t)(bi * 4608) * 4 + lane_off16(lane, 36);
        uint32_t lQ = sbase + (uint32_t)(9216 + bi * 2304) * 4 + lane_off16(lane, 36);
        uint32_t lK = sbase + (uint32_t)(13824 + bi * 2304) * 4 + lane_off16(lane, 36);
        #pragma unroll
        for (int kk = 0; kk < 4; kk++) {
            uint32_t a[4];
            ldsm4(a[0], a[1], a[2], a[3], lA + (uint32_t)((wid * 16) * 36 * 4 + kk * 32));
            #pragma unroll
            for (int jp = 0; jp < 4; jp++) {
                uint32_t b0, b1, b2, b3;
                ldsm4(b0, b1, b2, b3, lQ + (uint32_t)((jp * 16) * 36 * 4 + kk * 32));
                mma16(accQ[2 * jp],     a, b0, b2);
                mma16(accQ[2 * jp + 1], a, b1, b3);
                ldsm4(b0, b1, b2, b3, lK + (uint32_t)((jp * 16) * 36 * 4 + kk * 32));
                mma16(accKV[2 * jp],     a, b0, b2);
                mma16(accKV[2 * jp + 1], a, b1, b3);
            }
        }
    }

    const int rA = m0 + wid * 16 + g;
    const int bb = rA >> 10;
    const int nA = rA & 1023;
    size_t oA = ((size_t)(bb * H_ + head) * N_ + nA) * DH_ + 2 * t;
    size_t oB = oA + 8 * DH_;
    // ---- Q epilogue (RoPE + combined 0.125*log2e scale) ----
    {
        float lo[4][4], hi[4][4];
        #pragma unroll
        for (int jl = 0; jl < 4; jl++)
            #pragma unroll
            for (int c = 0; c < 4; c++) {
                float v1 = ((const float*)&accQ[jl])[c];
                float v2 = ((const float*)&accQ[jl + 4])[c];
                int d = jl * 8 + 2 * t + (c & 1);
                int n = nA + (c >> 1) * 8;
                float inv = exp2f(-(float)d * 0.41524101186092034f);
                float sn, cs;
                sincosf((float)n * inv, &sn, &cs);
                lo[jl][c] = v1 * cs - v2 * sn;
                hi[jl][c] = v2 * cs + v1 * sn;
            }
        #pragma unroll
        for (int jl = 0; jl < 4; jl++) {
            *(uint32_t*)(g_Qh + oA + jl * 8)      = f2h2(lo[jl][0] * QSCALE_, lo[jl][1] * QSCALE_);
            *(uint32_t*)(g_Qh + oA + jl * 8 + 32) = f2h2(hi[jl][0] * QSCALE_, hi[jl][1] * QSCALE_);
            *(uint32_t*)(g_Qh + oB + jl * 8)      = f2h2(lo[jl][2] * QSCALE_, lo[jl][3] * QSCALE_);
            *(uint32_t*)(g_Qh + oB + jl * 8 + 32) = f2h2(hi[jl][2] * QSCALE_, hi[jl][3] * QSCALE_);
        }
    }
    // ---- KV epilogue (RoPE + LN) ----
    {
        float lo[4][4], hi[4][4];
        #pragma unroll
        for (int jl = 0; jl < 4; jl++)
            #pragma unroll
            for (int c = 0; c < 4; c++) {
                float v1 = ((const float*)&accKV[jl])[c];
                float v2 = ((const float*)&accKV[jl + 4])[c];
                int d = jl * 8 + 2 * t + (c & 1);
                int n = nA + (c >> 1) * 8;
                float inv = exp2f(-(float)d * 0.41524101186092034f);
                float sn, cs;
                sincosf((float)n * inv, &sn, &cs);
                lo[jl][c] = v1 * cs - v2 * sn;
                hi[jl][c] = v2 * cs + v1 * sn;
            }
        #pragma unroll
        for (int jl = 0; jl < 4; jl++) {
            *(uint32_t*)(g_KVh + oA + jl * 8)      = f2h2(lo[jl][0], lo[jl][1]);
            *(uint32_t*)(g_KVh + oA + jl * 8 + 32) = f2h2(hi[jl][0], hi[jl][1]);
            *(uint32_t*)(g_KVh + oB + jl * 8)      = f2h2(lo[jl][2], lo[jl][3]);
            *(uint32_t*)(g_KVh + oB + jl * 8 + 32) = f2h2(hi[jl][2], hi[jl][3]);
        }
        float sumA = 0.f, sumB = 0.f;
        #pragma unroll
        for (int jl = 0; jl < 4; jl++) {
            sumA += lo[jl][0] + lo[jl][1] + hi[jl][0] + hi[jl][1];
            sumB += lo[jl][2] + lo[jl][3] + hi[jl][2] + hi[jl][3];
        }
        sumA += __shfl_xor_sync(0xffffffffu, sumA, 1);
        sumA += __shfl_xor_sync(0xffffffffu, sumA, 2);
        sumB += __shfl_xor_sync(0xffffffffu, sumB, 1);
        sumB += __shfl_xor_sync(0xffffffffu, sumB, 2);
        float mA = sumA * (1.f / 64.f), mB = sumB * (1.f / 64.f);
        float vA = 0.f, vB = 0.f;
        #pragma unroll
        for (int jl = 0; jl < 4; jl++)
            #pragma unroll
            for (int c = 0; c < 2; c++) {
                float d1 = lo[jl][c] - mA, d2 = hi[jl][c] - mA;
                vA += d1 * d1 + d2 * d2;
                float d3 = lo[jl][c + 2] - mB, d4 = hi[jl][c + 2] - mB;
                vB += d3 * d3 + d4 * d4;
            }
        vA += __shfl_xor_sync(0xffffffffu, vA, 1);
        vA += __shfl_xor_sync(0xffffffffu, vA, 2);
        vB += __shfl_xor_sync(0xffffffffu, vB, 1);
        vB += __shfl_xor_sync(0xffffffffu, vB, 2);
        float iA = rsqrtf(vA * (1.f / 64.f) + 1e-5f);
        float iB = rsqrtf(vB * (1.f / 64.f) + 1e-5f);
        #pragma unroll
        for (int jl = 0; jl < 4; jl++) {
            int d = jl * 8 + 2 * t;
            float g0 = lng[d], g1 = lng[d + 1], b0 = lnb[d], b1 = lnb[d + 1];
            float g2 = lng[d + 32], g3 = lng[d + 33], b2 = lnb[d + 32], b3 = lnb[d + 33];
            *(uint32_t*)(g_LKVh + oA + jl * 8) = f2h2(
                (lo[jl][0] - mA) * iA * g0 + b0, (lo[jl][1] - mA) * iA * g1 + b1);
            *(uint32_t*)(g_LKVh + oA + jl * 8 + 32) = f2h2(
                (hi[jl][0] - mA) * iA * g2 + b2, (hi[jl][1] - mA) * iA * g3 + b3);
            *(uint32_t*)(g_LKVh + oB + jl * 8) = f2h2(
                (lo[jl][2] - mB) * iB * g0 + b0, (lo[jl][3] - mB) * iB * g1 + b1);
            *(uint32_t*)(g_LKVh + oB + jl * 8 + 32) = f2h2(
                (hi[jl][2] - mB) * iB * g2 + b2, (hi[jl][3] - mB) * iB * g3 + b3);
        }
    }
}

// ---------------- fused attention: ex2 exp + mma rowsum ----------------------
// dyn smem u32: Q@0 (4608), K[2]@4608/9216, V[2]@13824/18432 -> 23040 u32 = 92160 B
__global__ __launch_bounds__(256, 2) void attn_kernel() {
    extern __shared__ uint32_t dsm[];
    const int bh = blockIdx.x, qt = blockIdx.y;
    const int m0 = qt * 128;
    const int tid = threadIdx.x;
    const int lane = tid & 31, wid = tid >> 5;
    const int g = lane >> 2, t = lane & 3;
    const int wr = wid * 16;
    const uint32_t sbase = (uint32_t)__cvta_generic_to_shared(dsm);
    const uint32_t lbQ = sbase + lane_off16(lane, 36);
    const uint32_t onesb = (g == 0) ? 0x3C003C00u : 0u;   // B-frag of ones col 0

    auto stageKV = [&](int bi, int kt) {            // 128 keys
        const __half* kb = g_KVh  + ((size_t)bh * N_ + kt * 128) * DH_;
        const __half* vb = g_LKVh + ((size_t)bh * N_ + kt * 128) * DH_;
        uint32_t ko = sbase + (uint32_t)(4608 + bi * 4608) * 4;
        uint32_t vo = sbase + (uint32_t)(13824 + bi * 4608) * 4;
        #pragma unroll
        for (int i = 0; i < 4; i++) {
            int idx = tid + i * 256;
            int r = idx >> 3, c = idx & 7;
            cpa16(ko + (uint32_t)(r * 36 + c * 4) * 4, kb + (size_t)r * DH_ + c * 8);
            cpa16(vo + (uint32_t)(r * 36 + c * 4) * 4, vb + (size_t)r * DH_ + c * 8);
        }
    };

    // stage Q + tile 0
    const __half* qsrc = g_Qh + ((size_t)bh * N_ + m0) * DH_;
    #pragma unroll
    for (int i = 0; i < 4; i++) {
        int idx = tid + i * 256;
        int r = idx >> 3, c = idx & 7;
        cpa16(sbase + (uint32_t)(r * 36 + c * 4) * 4, qsrc + (size_t)r * DH_ + c * 8);
    }
    stageKV(0, 0);
    cp_commit();

    uint32_t qa[4][4];
    float4 o[8];
    #pragma unroll
    for (int j = 0; j < 8; j++) o[j] = make_float4(0.f, 0.f, 0.f, 0.f);
    float4 lsum = make_float4(0.f, 0.f, 0.f, 0.f);
    const int r0g = m0 + wr + g;
    const bool lat0 = (r0g >= CTX_);
    const bool lat1 = (r0g + 8 >= CTX_);

    for (int kt = 0; kt < 8; kt++) {
        int bi = kt & 1;
        cp_wait<0>();
        __syncthreads();              // tile kt visible; compute on bi^1 finished
        if (kt == 0) {
            #pragma unroll
            for (int kk = 0; kk < 4; kk++)
                ldsm4(qa[kk][0], qa[kk][1], qa[kk][2], qa[kk][3],
                      lbQ + (uint32_t)(wr * 36 * 4 + kk * 32));
        }
        if (kt < 7) { stageKV(bi ^ 1, kt + 1); cp_commit(); }

        #pragma unroll
        for (int half = 0; half < 2; half++) {
            uint32_t lbK = sbase + (uint32_t)(4608 + bi * 4608 + half * 2304) * 4
                           + lane_off16(lane, 36);
            uint32_t lbV = sbase + (uint32_t)(13824 + bi * 4608 + half * 2304) * 4
                           + lane_off16t(lane, 36);
            // S = Q K^T (64 keys); Q pre-scaled by 0.125*log2e
            float4 s[8];
            #pragma unroll
            for (int j = 0; j < 8; j++) s[j] = make_float4(0.f, 0.f, 0.f, 0.f);
            #pragma unroll
            for (int kk = 0; kk < 4; kk++) {
                #pragma unroll
                for (int jp = 0; jp < 4; jp++) {
                    uint32_t b0, b1, b2, b3;
                    ldsm4(b0, b1, b2, b3, lbK + (uint32_t)((jp * 16) * 36 * 4 + kk * 32));
                    mma16(s[2 * jp],     qa[kk], b0, b2);
                    mma16(s[2 * jp + 1], qa[kk], b1, b3);
                }
            }
            // exp2 -> register-resident P fragments (no FMUL, no scalar rowsum)
            uint32_t ph[16];
            #pragma unroll
            for (int j = 0; j < 8; j++) {
                float px = ex2f(s[j].x), py = ex2f(s[j].y);
                float pz = ex2f(s[j].z), pw = ex2f(s[j].w);
                if (kt == 7 && half == 1 && j >= 4) {     // keys >= CTX_
                    if (!lat0) { px = 0.f; py = 0.f; }
                    if (!lat1) { pz = 0.f; pw = 0.f; }
                }
                ph[2 * j]     = f2h2(px, py);
                ph[2 * j + 1] = f2h2(pz, pw);
            }
            // O += P V ; rowsum += P 1 (tensor-pipe rowsum via ones fragment)
            #pragma unroll
            for (int kk = 0; kk < 4; kk++) {
                uint32_t pa[4];
                pa[0] = ph[4 * kk];     pa[1] = ph[4 * kk + 1];
                pa[2] = ph[4 * kk + 2]; pa[3] = ph[4 * kk + 3];
                mma16(lsum, pa, onesb, onesb);
                #pragma unroll
                for (int jp = 0; jp < 4; jp++) {
                    uint32_t b0, b1, b2, b3;
                    ldsm4t(b0, b1, b2, b3,
                           lbV + (uint32_t)((kk * 16) * 36 * 4 + (jp * 16) * 2));
                    mma16(o[2 * jp],     pa, b0, b2);
                    mma16(o[2 * jp + 1], pa, b1, b3);
                }
            }
        }
    }

    float l0 = lsum.x, l1 = lsum.z;   // nonzero only at t==0; xor-sum broadcasts
    l0 += __shfl_xor_sync(0xffffffffu, l0, 1);
    l0 += __shfl_xor_sync(0xffffffffu, l0, 2);
    l1 += __shfl_xor_sync(0xffffffffu, l1, 1);
    l1 += __shfl_xor_sync(0xffffffffu, l1, 2);
    float i0 = 1.0f / l0, i1 = 1.0f / l1;

    const int bb = bh / H_, h = bh % H_;
    int gr0 = (r0g < CTX_) ? bb * CTX_ + r0g : GCTX_ + bb * 32 + (r0g - CTX_);
    int r1g = r0g + 8;
    int gr1 = (r1g < CTX_) ? bb * CTX_ + r1g : GCTX_ + bb * 32 + (r1g - CTX_);
    #pragma unroll
    for (int j = 0; j < 8; j++) {
        int col = h * 64 + j * 8 + 2 * t;
        *(uint32_t*)(g_Attn + (size_t)gr0 * DIM_ + col) = f2h2(o[j].x * i0, o[j].y * i0);
        *(uint32_t*)(g_Attn + (size_t)gr1 * DIM_ + col) = f2h2(o[j].z * i1, o[j].w * i1);
    }
}

// ---------------- output projection, single-sync pipeline --------------------
__global__ __launch_bounds__(256) void out_kernel(const float* __restrict__ bc,
                                                  const float* __restrict__ bl,
                                                  float* __restrict__ out) {
    extern __shared__ uint32_t dsm[];
    const int m0 = blockIdx.x * 128;
    const int n0 = blockIdx.y * 128;
    const bool ctx = (m0 < GCTX_);
    const __half* WT  = ctx ? g_WocT : g_WolT;
    const float* bias = ctx ? bc : bl;

    const int tid = threadIdx.x;
    const int lane = tid & 31, wid = tid >> 5;
    const int wm = (wid & 3) * 32;
    const int wn = (wid >> 2) * 64;
    const int g = lane >> 2, t = lane & 3;
    const uint32_t sbase = (uint32_t)__cvta_generic_to_shared(dsm);

    auto stage = [&](int bi, int k0) {
        uint32_t ao = sbase + (uint32_t)(bi * 4608) * 4;
        uint32_t bo = sbase + (uint32_t)(9216 + bi * 4608) * 4;
        #pragma unroll
        for (int i = 0; i < 4; i++) {
            int idx = tid + i * 256;
            int r = idx >> 3, c = idx & 7;
            cpa16(ao + (uint32_t)(r * 36 + c * 4) * 4,
                  g_Attn + (size_t)(m0 + r) * DIM_ + k0 + c * 8);
            cpa16(bo + (uint32_t)(r * 36 + c * 4) * 4,
                  WT + (size_t)(n0 + r) * DIM_ + k0 + c * 8);
        }
    };

    float4 acc[2][8];
    #pragma unroll
    for (int i = 0; i < 2; i++)
        #pragma unroll
        for (int j = 0; j < 8; j++) acc[i][j] = make_float4(0.f, 0.f, 0.f, 0.f);

    stage(0, 0);
    cp_commit();

    for (int kt = 0; kt < 12; kt++) {
        int bi = kt & 1;
        cp_wait<0>();
        __syncthreads();
        if (kt < 11) { stage(bi ^ 1, (kt + 1) * 64); cp_commit(); }

        uint32_t sA = sbase + (uint32_t)(bi * 4608) * 4 + lane_off16(lane, 36);
        uint32_t sB = sbase + (uint32_t)(9216 + bi * 4608) * 4 + lane_off16(lane, 36);
        #pragma unroll
        for (int kk = 0; kk < 4; kk++) {
            uint32_t a0[4], a1[4];
            ldsm4(a0[0], a0[1], a0[2], a0[3], sA + (uint32_t)(wm * 36 * 4 + kk * 32));
            ldsm4(a1[0], a1[1], a1[2], a1[3], sA + (uint32_t)((wm + 16) * 36 * 4 + kk * 32));
            #pragma unroll
            for (int jp = 0; jp < 4; jp++) {
                uint32_t b0, b1, b2, b3;
                ldsm4(b0, b1, b2, b3, sB + (uint32_t)((wn + jp * 16) * 36 * 4 + kk * 32));
                mma16(acc[0][2 * jp],     a0, b0, b2);
                mma16(acc[0][2 * jp + 1], a0, b1, b3);
                mma16(acc[1][2 * jp],     a1, b0, b2);
                mma16(acc[1][2 * jp + 1], a1, b1, b3);
            }
        }
    }

    #pragma unroll
    for (int mt = 0; mt < 2; mt++) {
        int rA = m0 + wm + mt * 16 + g;
        #pragma unroll
        for (int half = 0; half < 2; half++) {
            int r = rA + half * 8;
            int b, n;
            if (r < GCTX_) { b = r / CTX_; n = r - b * CTX_; }
            else { int q = r - GCTX_; b = q >> 5; n = CTX_ + (q & 31); }
            float* orow = out + (size_t)(b * N_ + n) * DIM_;
            #pragma unroll
            for (int jf = 0; jf < 8; jf++) {
                int col = n0 + wn + jf * 8 + 2 * t;
                float vx = half ? acc[mt][jf].z : acc[mt][jf].x;
                float vy = half ? acc[mt][jf].w : acc[mt][jf].y;
                *(float2*)(orow + col) = make_float2(vx + bias[col], vy + bias[col + 1]);
            }
        }
    }
}

// ---------------- launch -----------------------------------------------------
extern "C" void kernel_launch(void* const* d_in, const int* in_sizes, int n_in,
                              void* d_out, int out_size) {
    const float* x      = (const float*)d_in[0];
    const float* Wq     = (const float*)d_in[1];
    const float* Wkv    = (const float*)d_in[2];
    const float* Wo_ctx = (const float*)d_in[3];
    const float* bo_ctx = (const float*)d_in[4];
    const float* Wo_lat = (const float*)d_in[5];
    const float* bo_lat = (const float*)d_in[6];
    const float* ln_g   = (const float*)d_in[7];
    const float* ln_b   = (const float*)d_in[8];
    float* out = (float*)d_out;

    cudaFuncSetAttribute(proj_kernel, cudaFuncAttributeMaxDynamicSharedMemorySize, 73728);
    cudaFuncSetAttribute(attn_kernel, cudaFuncAttributeMaxDynamicSharedMemorySize, 92160);
    cudaFuncSetAttribute(out_kernel,  cudaFuncAttributeMaxDynamicSharedMemorySize, 73728);

    cvt_x<<<ROWS_ * DIM_ / (256 * 8), 256>>>(x);
    transpose_w<<<dim3(24, 24, 4), 256>>>(Wq, Wkv, Wo_ctx, Wo_lat);

    proj_kernel<<<dim3(64, 12), 256, 73728>>>(ln_g, ln_b);
    attn_kernel<<<dim3(96, 8), 256, 92160>>>();
    out_kernel<<<dim3(64, 6), 256, 73728>>>(bo_ctx, bo_lat, out);
}

// round 17
// speedup vs baseline: 5.7985x; 1.0107x over previous
#include <cuda_runtime.h>
#include <cuda_fp16.h>
#include <math.h>
#include <stdint.h>

#define B_    8
#define N_    1024
#define DIM_  768
#define H_    12
#define DH_   64
#define CTX_  992
#define BH_   96
#define ROWS_ 8192
#define GCTX_ 7936   // 8*992 grouped ctx rows

// ---------------- scratch (all fp16, 16B aligned) ----------------------------
__device__ __align__(16) __half g_Xh  [ROWS_ * DIM_];
__device__ __align__(16) __half g_Qh  [BH_ * N_ * DH_];
__device__ __align__(16) __half g_KVh [BH_ * N_ * DH_];
__device__ __align__(16) __half g_LKVh[BH_ * N_ * DH_];
__device__ __align__(16) __half g_Attn[ROWS_ * DIM_];   // grouped rows
__device__ __align__(16) __half g_WqT [DIM_ * DIM_];
__device__ __align__(16) __half g_WkvT[DIM_ * DIM_];
__device__ __align__(16) __half g_WocT[DIM_ * DIM_];
__device__ __align__(16) __half g_WolT[DIM_ * DIM_];

// Q scale absorbs DH^-0.5 (=0.125) AND log2(e) so attention can use raw ex2.
#define QSCALE_ 0.18033688011112042f

// ---------------- helpers ----------------------------------------------------
__device__ __forceinline__ uint32_t f2h2(float a, float b) {
    __half2 h = __floats2half2_rn(a, b);
    return *reinterpret_cast<uint32_t*>(&h);
}
__device__ __forceinline__ void mma16(float4& c, const uint32_t* a, uint32_t b0, uint32_t b1) {
    asm volatile(
        "mma.sync.aligned.m16n8k16.row.col.f32.f16.f16.f32 "
        "{%0,%1,%2,%3}, {%4,%5,%6,%7}, {%8,%9}, {%0,%1,%2,%3};\n"
        : "+f"(c.x), "+f"(c.y), "+f"(c.z), "+f"(c.w)
        : "r"(a[0]), "r"(a[1]), "r"(a[2]), "r"(a[3]), "r"(b0), "r"(b1));
}
__device__ __forceinline__ void ldsm4(uint32_t& r0, uint32_t& r1, uint32_t& r2,
                                      uint32_t& r3, uint32_t addr) {
    asm volatile("ldmatrix.sync.aligned.m8n8.x4.shared.b16 {%0,%1,%2,%3}, [%4];"
                 : "=r"(r0), "=r"(r1), "=r"(r2), "=r"(r3) : "r"(addr));
}
__device__ __forceinline__ void ldsm4t(uint32_t& r0, uint32_t& r1, uint32_t& r2,
                                       uint32_t& r3, uint32_t addr) {
    asm volatile("ldmatrix.sync.aligned.m8n8.x4.trans.shared.b16 {%0,%1,%2,%3}, [%4];"
                 : "=r"(r0), "=r"(r1), "=r"(r2), "=r"(r3) : "r"(addr));
}
__device__ __forceinline__ uint32_t lane_off16(int lane, int S) {
    int lr = (lane & 7) + ((lane >> 3) & 1) * 8;
    return (uint32_t)(lr * S * 4 + (lane >> 4) * 16);
}
__device__ __forceinline__ uint32_t lane_off16t(int lane, int S) {
    int lr = (lane & 7) + ((lane >> 4) & 1) * 8;
    return (uint32_t)(lr * S * 4 + ((lane >> 3) & 1) * 16);
}
__device__ __forceinline__ void cpa16(uint32_t dst, const void* src) {
    asm volatile("cp.async.ca.shared.global [%0], [%1], 16;" :: "r"(dst), "l"(src));
}
__device__ __forceinline__ void cp_commit() {
    asm volatile("cp.async.commit_group;");
}
template<int N>
__device__ __forceinline__ void cp_wait() {
    asm volatile("cp.async.wait_group %0;" :: "n"(N));
}

// ---------------- x -> fp16 ---------------------------------------------------
__global__ __launch_bounds__(256) void cvt_x(const float* __restrict__ x) {
    int idx = blockIdx.x * 256 + threadIdx.x;           // 8 floats per thread
    const float4* p = (const float4*)x + (size_t)idx * 2;
    float4 a = p[0], b = p[1];
    *(uint4*)(g_Xh + (size_t)idx * 8) =
        make_uint4(f2h2(a.x, a.y), f2h2(a.z, a.w), f2h2(b.x, b.y), f2h2(b.z, b.w));
}

// ---------------- fused weight transpose (grid.z selects matrix) -------------
__global__ __launch_bounds__(256) void transpose_w(const float* __restrict__ s0,
                                                   const float* __restrict__ s1,
                                                   const float* __restrict__ s2,
                                                   const float* __restrict__ s3) {
    __shared__ float tile[32][33];
    const float* src;
    __half* dst;
    switch (blockIdx.z) {
        case 0: src = s0; dst = g_WqT;  break;
        case 1: src = s1; dst = g_WkvT; break;
        case 2: src = s2; dst = g_WocT; break;
        default: src = s3; dst = g_WolT; break;
    }
    int c0 = blockIdx.x * 32, r0 = blockIdx.y * 32;
    int tx = threadIdx.x & 31, ty = threadIdx.x >> 5;
    #pragma unroll
    for (int i = 0; i < 4; i++)
        tile[ty + i * 8][tx] = src[(size_t)(r0 + ty + i * 8) * DIM_ + c0 + tx];
    __syncthreads();
    #pragma unroll
    for (int i = 0; i < 4; i++)
        dst[(size_t)(c0 + ty + i * 8) * DIM_ + r0 + tx] = __float2half(tile[tx][ty + i * 8]);
}

// ---------------- fused Q+KV projection, single-sync pipeline ----------------
__global__ __launch_bounds__(256) void proj_kernel(const float* __restrict__ lng,
                                                   const float* __restrict__ lnb) {
    extern __shared__ uint32_t dsm[];
    const int m0 = blockIdx.x * 128;
    const int head = blockIdx.y;
    const int n0 = head * 64;
    const int tid = threadIdx.x;
    const int lane = tid & 31, wid = tid >> 5;
    const int g = lane >> 2, t = lane & 3;
    const uint32_t sbase = (uint32_t)__cvta_generic_to_shared(dsm);

    auto stage = [&](int bi, int k0) {
        uint32_t aoff = sbase + (uint32_t)(bi * 4608) * 4;
        #pragma unroll
        for (int i = 0; i < 4; i++) {
            int idx = tid + i * 256;
            int r = idx >> 3, c = idx & 7;
            cpa16(aoff + (uint32_t)(r * 36 + c * 4) * 4,
                  g_Xh + (size_t)(m0 + r) * DIM_ + k0 + c * 8);
        }
        uint32_t bqo = sbase + (uint32_t)(9216 + bi * 2304) * 4;
        uint32_t bko = sbase + (uint32_t)(13824 + bi * 2304) * 4;
        #pragma unroll
        for (int i = 0; i < 2; i++) {
            int idx = tid + i * 256;
            int r = idx >> 3, c = idx & 7;
            cpa16(bqo + (uint32_t)(r * 36 + c * 4) * 4,
                  g_WqT + (size_t)(n0 + r) * DIM_ + k0 + c * 8);
            cpa16(bko + (uint32_t)(r * 36 + c * 4) * 4,
                  g_WkvT + (size_t)(n0 + r) * DIM_ + k0 + c * 8);
        }
    };

    float4 accQ[8], accKV[8];
    #pragma unroll
    for (int j = 0; j < 8; j++) {
        accQ[j] = make_float4(0.f, 0.f, 0.f, 0.f);
        accKV[j] = make_float4(0.f, 0.f, 0.f, 0.f);
    }

    stage(0, 0);
    cp_commit();

    for (int kt = 0; kt < 12; kt++) {
        int bi = kt & 1;
        cp_wait<0>();
        __syncthreads();           // tile kt visible; prev compute on bi^1 done
        if (kt < 11) { stage(bi ^ 1, (kt + 1) * 64); cp_commit(); }

        uint32_t lA = sbase + (uint32_t)(bi * 4608) * 4 + lane_off16(lane, 36);
        uint32_t lQ = sbase + (uint32_t)(9216 + bi * 2304) * 4 + lane_off16(lane, 36);
        uint32_t lK = sbase + (uint32_t)(13824 + bi * 2304) * 4 + lane_off16(lane, 36);
        #pragma unroll
        for (int kk = 0; kk < 4; kk++) {
            uint32_t a[4];
            ldsm4(a[0], a[1], a[2], a[3], lA + (uint32_t)((wid * 16) * 36 * 4 + kk * 32));
            #pragma unroll
            for (int jp = 0; jp < 4; jp++) {
                uint32_t b0, b1, b2, b3;
                ldsm4(b0, b1, b2, b3, lQ + (uint32_t)((jp * 16) * 36 * 4 + kk * 32));
                mma16(accQ[2 * jp],     a, b0, b2);
                mma16(accQ[2 * jp + 1], a, b1, b3);
                ldsm4(b0, b1, b2, b3, lK + (uint32_t)((jp * 16) * 36 * 4 + kk * 32));
                mma16(accKV[2 * jp],     a, b0, b2);
                mma16(accKV[2 * jp + 1], a, b1, b3);
            }
        }
    }

    const int rA = m0 + wid * 16 + g;
    const int bb = rA >> 10;
    const int nA = rA & 1023;
    size_t oA = ((size_t)(bb * H_ + head) * N_ + nA) * DH_ + 2 * t;
    size_t oB = oA + 8 * DH_;
    // ---- Q epilogue (RoPE + combined 0.125*log2e scale) ----
    {
        float lo[4][4], hi[4][4];
        #pragma unroll
        for (int jl = 0; jl < 4; jl++)
            #pragma unroll
            for (int c = 0; c < 4; c++) {
                float v1 = ((const float*)&accQ[jl])[c];
                float v2 = ((const float*)&accQ[jl + 4])[c];
                int d = jl * 8 + 2 * t + (c & 1);
                int n = nA + (c >> 1) * 8;
                float inv = exp2f(-(float)d * 0.41524101186092034f);
                float sn, cs;
                sincosf((float)n * inv, &sn, &cs);
                lo[jl][c] = v1 * cs - v2 * sn;
                hi[jl][c] = v2 * cs + v1 * sn;
            }
        #pragma unroll
        for (int jl = 0; jl < 4; jl++) {
            *(uint32_t*)(g_Qh + oA + jl * 8)      = f2h2(lo[jl][0] * QSCALE_, lo[jl][1] * QSCALE_);
            *(uint32_t*)(g_Qh + oA + jl * 8 + 32) = f2h2(hi[jl][0] * QSCALE_, hi[jl][1] * QSCALE_);
            *(uint32_t*)(g_Qh + oB + jl * 8)      = f2h2(lo[jl][2] * QSCALE_, lo[jl][3] * QSCALE_);
            *(uint32_t*)(g_Qh + oB + jl * 8 + 32) = f2h2(hi[jl][2] * QSCALE_, hi[jl][3] * QSCALE_);
        }
    }
    // ---- KV epilogue (RoPE + LN) ----
    {
        float lo[4][4], hi[4][4];
        #pragma unroll
        for (int jl = 0; jl < 4; jl++)
            #pragma unroll
            for (int c = 0; c < 4; c++) {
                float v1 = ((const float*)&accKV[jl])[c];
                float v2 = ((const float*)&accKV[jl + 4])[c];
                int d = jl * 8 + 2 * t + (c & 1);
                int n = nA + (c >> 1) * 8;
                float inv = exp2f(-(float)d * 0.41524101186092034f);
                float sn, cs;
                sincosf((float)n * inv, &sn, &cs);
                lo[jl][c] = v1 * cs - v2 * sn;
                hi[jl][c] = v2 * cs + v1 * sn;
            }
        #pragma unroll
        for (int jl = 0; jl < 4; jl++) {
            *(uint32_t*)(g_KVh + oA + jl * 8)      = f2h2(lo[jl][0], lo[jl][1]);
            *(uint32_t*)(g_KVh + oA + jl * 8 + 32) = f2h2(hi[jl][0], hi[jl][1]);
            *(uint32_t*)(g_KVh + oB + jl * 8)      = f2h2(lo[jl][2], lo[jl][3]);
            *(uint32_t*)(g_KVh + oB + jl * 8 + 32) = f2h2(hi[jl][2], hi[jl][3]);
        }
        float sumA = 0.f, sumB = 0.f;
        #pragma unroll
        for (int jl = 0; jl < 4; jl++) {
            sumA += lo[jl][0] + lo[jl][1] + hi[jl][0] + hi[jl][1];
            sumB += lo[jl][2] + lo[jl][3] + hi[jl][2] + hi[jl][3];
        }
        sumA += __shfl_xor_sync(0xffffffffu, sumA, 1);
        sumA += __shfl_xor_sync(0xffffffffu, sumA, 2);
        sumB += __shfl_xor_sync(0xffffffffu, sumB, 1);
        sumB += __shfl_xor_sync(0xffffffffu, sumB, 2);
        float mA = sumA * (1.f / 64.f), mB = sumB * (1.f / 64.f);
        float vA = 0.f, vB = 0.f;
        #pragma unroll
        for (int jl = 0; jl < 4; jl++)
            #pragma unroll
            for (int c = 0; c < 2; c++) {
                float d1 = lo[jl][c] - mA, d2 = hi[jl][c] - mA;
                vA += d1 * d1 + d2 * d2;
                float d3 = lo[jl][c + 2] - mB, d4 = hi[jl][c + 2] - mB;
                vB += d3 * d3 + d4 * d4;
            }
        vA += __shfl_xor_sync(0xffffffffu, vA, 1);
        vA += __shfl_xor_sync(0xffffffffu, vA, 2);
        vB += __shfl_xor_sync(0xffffffffu, vB, 1);
        vB += __shfl_xor_sync(0xffffffffu, vB, 2);
        float iA = rsqrtf(vA * (1.f / 64.f) + 1e-5f);
        float iB = rsqrtf(vB * (1.f / 64.f) + 1e-5f);
        #pragma unroll
        for (int jl = 0; jl < 4; jl++) {
            int d = jl * 8 + 2 * t;
            float g0 = lng[d], g1 = lng[d + 1], b0 = lnb[d], b1 = lnb[d + 1];
            float g2 = lng[d + 32], g3 = lng[d + 33], b2 = lnb[d + 32], b3 = lnb[d + 33];
            *(uint32_t*)(g_LKVh + oA + jl * 8) = f2h2(
                (lo[jl][0] - mA) * iA * g0 + b0, (lo[jl][1] - mA) * iA * g1 + b1);
            *(uint32_t*)(g_LKVh + oA + jl * 8 + 32) = f2h2(
                (hi[jl][0] - mA) * iA * g2 + b2, (hi[jl][1] - mA) * iA * g3 + b3);
            *(uint32_t*)(g_LKVh + oB + jl * 8) = f2h2(
                (lo[jl][2] - mB) * iB * g0 + b0, (lo[jl][3] - mB) * iB * g1 + b1);
            *(uint32_t*)(g_LKVh + oB + jl * 8 + 32) = f2h2(
                (hi[jl][2] - mB) * iB * g2 + b2, (hi[jl][3] - mB) * iB * g3 + b3);
        }
    }
}

// ---------------- fused attention: f16x2 ex2 + mma rowsum --------------------
// dyn smem u32: Q@0 (4608), K[2]@4608/9216, V[2]@13824/18432 -> 23040 u32 = 92160 B
__global__ __launch_bounds__(256, 2) void attn_kernel() {
    extern __shared__ uint32_t dsm[];
    const int bh = blockIdx.x, qt = blockIdx.y;
    const int m0 = qt * 128;
    const int tid = threadIdx.x;
    const int lane = tid & 31, wid = tid >> 5;
    const int g = lane >> 2, t = lane & 3;
    const int wr = wid * 16;
    const uint32_t sbase = (uint32_t)__cvta_generic_to_shared(dsm);
    const uint32_t lbQ = sbase + lane_off16(lane, 36);
    const uint32_t onesb = (g == 0) ? 0x3C003C00u : 0u;   // B-frag of ones col 0

    auto stageKV = [&](int bi, int kt) {            // 128 keys
        const __half* kb = g_KVh  + ((size_t)bh * N_ + kt * 128) * DH_;
        const __half* vb = g_LKVh + ((size_t)bh * N_ + kt * 128) * DH_;
        uint32_t ko = sbase + (uint32_t)(4608 + bi * 4608) * 4;
        uint32_t vo = sbase + (uint32_t)(13824 + bi * 4608) * 4;
        #pragma unroll
        for (int i = 0; i < 4; i++) {
            int idx = tid + i * 256;
            int r = idx >> 3, c = idx & 7;
            cpa16(ko + (uint32_t)(r * 36 + c * 4) * 4, kb + (size_t)r * DH_ + c * 8);
            cpa16(vo + (uint32_t)(r * 36 + c * 4) * 4, vb + (size_t)r * DH_ + c * 8);
        }
    };

    // stage Q + tile 0
    const __half* qsrc = g_Qh + ((size_t)bh * N_ + m0) * DH_;
    #pragma unroll
    for (int i = 0; i < 4; i++) {
        int idx = tid + i * 256;
        int r = idx >> 3, c = idx & 7;
        cpa16(sbase + (uint32_t)(r * 36 + c * 4) * 4, qsrc + (size_t)r * DH_ + c * 8);
    }
    stageKV(0, 0);
    cp_commit();

    uint32_t qa[4][4];
    float4 o[8];
    #pragma unroll
    for (int j = 0; j < 8; j++) o[j] = make_float4(0.f, 0.f, 0.f, 0.f);
    float4 lsum = make_float4(0.f, 0.f, 0.f, 0.f);
    const int r0g = m0 + wr + g;
    const bool lat0 = (r0g >= CTX_);
    const bool lat1 = (r0g + 8 >= CTX_);

    for (int kt = 0; kt < 8; kt++) {
        int bi = kt & 1;
        cp_wait<0>();
        __syncthreads();              // tile kt visible; compute on bi^1 finished
        if (kt == 0) {
            #pragma unroll
            for (int kk = 0; kk < 4; kk++)
                ldsm4(qa[kk][0], qa[kk][1], qa[kk][2], qa[kk][3],
                      lbQ + (uint32_t)(wr * 36 * 4 + kk * 32));
        }
        if (kt < 7) { stageKV(bi ^ 1, kt + 1); cp_commit(); }

        #pragma unroll
        for (int half = 0; half < 2; half++) {
            uint32_t lbK = sbase + (uint32_t)(4608 + bi * 4608 + half * 2304) * 4
                           + lane_off16(lane, 36);
            uint32_t lbV = sbase + (uint32_t)(13824 + bi * 4608 + half * 2304) * 4
                           + lane_off16t(lane, 36);
            // S = Q K^T (64 keys); Q pre-scaled by 0.125*log2e
            float4 s[8];
            #pragma unroll
            for (int j = 0; j < 8; j++) s[j] = make_float4(0.f, 0.f, 0.f, 0.f);
            #pragma unroll
            for (int kk = 0; kk < 4; kk++) {
                #pragma unroll
                for (int jp = 0; jp < 4; jp++) {
                    uint32_t b0, b1, b2, b3;
                    ldsm4(b0, b1, b2, b3, lbK + (uint32_t)((jp * 16) * 36 * 4 + kk * 32));
                    mma16(s[2 * jp],     qa[kk], b0, b2);
                    mma16(s[2 * jp + 1], qa[kk], b1, b3);
                }
            }
            // packed half2 ex2 -> register-resident P fragments (2 exps / MUFU op)
            uint32_t ph[16];
            #pragma unroll
            for (int j = 0; j < 8; j++) {
                uint32_t h0 = f2h2(s[j].x, s[j].y);
                uint32_t h1 = f2h2(s[j].z, s[j].w);
                asm("ex2.approx.f16x2 %0, %0;" : "+r"(h0));
                asm("ex2.approx.f16x2 %0, %0;" : "+r"(h1));
                if (kt == 7 && half == 1 && j >= 4) {     // keys >= CTX_
                    if (!lat0) h0 = 0u;
                    if (!lat1) h1 = 0u;
                }
                ph[2 * j]     = h0;
                ph[2 * j + 1] = h1;
            }
            // O += P V ; rowsum += P 1 (tensor-pipe rowsum via ones fragment)
            #pragma unroll
            for (int kk = 0; kk < 4; kk++) {
                uint32_t pa[4];
                pa[0] = ph[4 * kk];     pa[1] = ph[4 * kk + 1];
                pa[2] = ph[4 * kk + 2]; pa[3] = ph[4 * kk + 3];
                mma16(lsum, pa, onesb, onesb);
                #pragma unroll
                for (int jp = 0; jp < 4; jp++) {
                    uint32_t b0, b1, b2, b3;
                    ldsm4t(b0, b1, b2, b3,
                           lbV + (uint32_t)((kk * 16) * 36 * 4 + (jp * 16) * 2));
                    mma16(o[2 * jp],     pa, b0, b2);
                    mma16(o[2 * jp + 1], pa, b1, b3);
                }
            }
        }
    }

    float l0 = lsum.x, l1 = lsum.z;   // nonzero only at t==0; xor-sum broadcasts
    l0 += __shfl_xor_sync(0xffffffffu, l0, 1);
    l0 += __shfl_xor_sync(0xffffffffu, l0, 2);
    l1 += __shfl_xor_sync(0xffffffffu, l1, 1);
    l1 += __shfl_xor_sync(0xffffffffu, l1, 2);
    float i0 = 1.0f / l0, i1 = 1.0f / l1;

    const int bb = bh / H_, h = bh % H_;
    int gr0 = (r0g < CTX_) ? bb * CTX_ + r0g : GCTX_ + bb * 32 + (r0g - CTX_);
    int r1g = r0g + 8;
    int gr1 = (r1g < CTX_) ? bb * CTX_ + r1g : GCTX_ + bb * 32 + (r1g - CTX_);
    #pragma unroll
    for (int j = 0; j < 8; j++) {
        int col = h * 64 + j * 8 + 2 * t;
        *(uint32_t*)(g_Attn + (size_t)gr0 * DIM_ + col) = f2h2(o[j].x * i0, o[j].y * i0);
        *(uint32_t*)(g_Attn + (size_t)gr1 * DIM_ + col) = f2h2(o[j].z * i1, o[j].w * i1);
    }
}

// ---------------- output projection, single-sync pipeline (legacy mma) -------
__global__ __launch_bounds__(256) void out_kernel(const float* __restrict__ bc,
                                                  const float* __restrict__ bl,
                                                  float* __restrict__ out) {
    extern __shared__ uint32_t dsm[];
    const int m0 = blockIdx.x * 128;
    const int n0 = blockIdx.y * 128;
    const bool ctx = (m0 < GCTX_);
    const __half* WT  = ctx ? g_WocT : g_WolT;
    const float* bias = ctx ? bc : bl;

    const int tid = threadIdx.x;
    const int lane = tid & 31, wid = tid >> 5;
    const int wm = (wid & 3) * 32;
    const int wn = (wid >> 2) * 64;
    const int g = lane >> 2, t = lane & 3;
    const uint32_t sbase = (uint32_t)__cvta_generic_to_shared(dsm);

    auto stage = [&](int bi, int k0) {
        uint32_t ao = sbase + (uint32_t)(bi * 4608) * 4;
        uint32_t bo = sbase + (uint32_t)(9216 + bi * 4608) * 4;
        #pragma unroll
        for (int i = 0; i < 4; i++) {
            int idx = tid + i * 256;
            int r = idx >> 3, c = idx & 7;
            cpa16(ao + (uint32_t)(r * 36 + c * 4) * 4,
                  g_Attn + (size_t)(m0 + r) * DIM_ + k0 + c * 8);
            cpa16(bo + (uint32_t)(r * 36 + c * 4) * 4,
                  WT + (size_t)(n0 + r) * DIM_ + k0 + c * 8);
        }
    };

    float4 acc[2][8];
    #pragma unroll
    for (int i = 0; i < 2; i++)
        #pragma unroll
        for (int j = 0; j < 8; j++) acc[i][j] = make_float4(0.f, 0.f, 0.f, 0.f);

    stage(0, 0);
    cp_commit();

    for (int kt = 0; kt < 12; kt++) {
        int bi = kt & 1;
        cp_wait<0>();
        __syncthreads();
        if (kt < 11) { stage(bi ^ 1, (kt + 1) * 64); cp_commit(); }

        uint32_t sA = sbase + (uint32_t)(bi * 4608) * 4 + lane_off16(lane, 36);
        uint32_t sB = sbase + (uint32_t)(9216 + bi * 4608) * 4 + lane_off16(lane, 36);
        #pragma unroll
        for (int kk = 0; kk < 4; kk++) {
            uint32_t a0[4], a1[4];
            ldsm4(a0[0], a0[1], a0[2], a0[3], sA + (uint32_t)(wm * 36 * 4 + kk * 32));
            ldsm4(a1[0], a1[1], a1[2], a1[3], sA + (uint32_t)((wm + 16) * 36 * 4 + kk * 32));
            #pragma unroll
            for (int jp = 0; jp < 4; jp++) {
                uint32_t b0, b1, b2, b3;
                ldsm4(b0, b1, b2, b3, sB + (uint32_t)((wn + jp * 16) * 36 * 4 + kk * 32));
                mma16(acc[0][2 * jp],     a0, b0, b2);
                mma16(acc[0][2 * jp + 1], a0, b1, b3);
                mma16(acc[1][2 * jp],     a1, b0, b2);
                mma16(acc[1][2 * jp + 1], a1, b1, b3);
            }
        }
    }

    #pragma unroll
    for (int mt = 0; mt < 2; mt++) {
        int rA = m0 + wm + mt * 16 + g;
        #pragma unroll
        for (int half = 0; half < 2; half++) {
            int r = rA + half * 8;
            int b, n;
            if (r < GCTX_) { b = r / CTX_; n = r - b * CTX_; }
            else { int q = r - GCTX_; b = q >> 5; n = CTX_ + (q & 31); }
            float* orow = out + (size_t)(b * N_ + n) * DIM_;
            #pragma unroll
            for (int jf = 0; jf < 8; jf++) {
                int col = n0 + wn + jf * 8 + 2 * t;
                float vx = half ? acc[mt][jf].z : acc[mt][jf].x;
                float vy = half ? acc[mt][jf].w : acc[mt][jf].y;
                *(float2*)(orow + col) = make_float2(vx + bias[col], vy + bias[col + 1]);
            }
        }
    }
}

// ---------------- launch -----------------------------------------------------
extern "C" void kernel_launch(void* const* d_in, const int* in_sizes, int n_in,
                              void* d_out, int out_size) {
    const float* x      = (const float*)d_in[0];
    const float* Wq     = (const float*)d_in[1];
    const float* Wkv    = (const float*)d_in[2];
    const float* Wo_ctx = (const float*)d_in[3];
    const float* bo_ctx = (const float*)d_in[4];
    const float* Wo_lat = (const float*)d_in[5];
    const float* bo_lat = (const float*)d_in[6];
    const float* ln_g   = (const float*)d_in[7];
    const float* ln_b   = (const float*)d_in[8];
    float* out = (float*)d_out;

    cudaFuncSetAttribute(proj_kernel, cudaFuncAttributeMaxDynamicSharedMemorySize, 73728);
    cudaFuncSetAttribute(attn_kernel, cudaFuncAttributeMaxDynamicSharedMemorySize, 92160);
    cudaFuncSetAttribute(out_kernel,  cudaFuncAttributeMaxDynamicSharedMemorySize, 73728);

    cvt_x<<<ROWS_ * DIM_ / (256 * 8), 256>>>(x);
    transpose_w<<<dim3(24, 24, 4), 256>>>(Wq, Wkv, Wo_ctx, Wo_lat);

    proj_kernel<<<dim3(64, 12), 256, 73728>>>(ln_g, ln_b);
    attn_kernel<<<dim3(96, 8), 256, 92160>>>();
    out_kernel<<<dim3(64, 6), 256, 73728>>>(bo_ctx, bo_lat, out);
}